// round 7
// baseline (speedup 1.0000x reference)
#include <cuda_runtime.h>
#include <math.h>
#include <stdint.h>

#define NTOK  4096
#define DIM   768
#define DEPTH 6
#define HEADS 12
#define DH    64
#define FFD   3072
#define MFEAT 256
#define NOUT  102

// ---------------- scratch (static device globals; no allocations) ----------
__device__ float g_x  [NTOK*DIM];
__device__ float g_h  [NTOK*DIM];
__device__ float g_q  [NTOK*DIM];
__device__ float g_k  [NTOK*DIM];
__device__ float g_v  [NTOK*DIM];
__device__ float g_o  [NTOK*DIM];
__device__ float g_ff [NTOK*FFD];
__device__ float g_qf [HEADS*NTOK*MFEAT];
__device__ float g_kf [HEADS*NTOK*MFEAT];
__device__ unsigned g_hmax[HEADS];
__device__ float g_ksum[HEADS*MFEAT];
__device__ float g_ctx [HEADS*MFEAT*DH];
__device__ float g_dinv[HEADS*NTOK];
__device__ int   g_bidx[NTOK];
__device__ float g_projT[DH*MFEAT];

// ---------------- helpers ---------------------------------------------------
__device__ __forceinline__ unsigned f2o(float f) {
    unsigned u = __float_as_uint(f);
    return (u & 0x80000000u) ? ~u : (u | 0x80000000u);
}
__device__ __forceinline__ float o2f(unsigned u) {
    return __uint_as_float((u & 0x80000000u) ? (u & 0x7fffffffu) : ~u);
}
__device__ __forceinline__ float gelu_tanh(float x) {
    float x3 = x * x * x;
    return 0.5f * x * (1.0f + tanhf(0.7978845608028654f * (x + 0.044715f * x3)));
}

// ---------------- embedding -------------------------------------------------
__global__ void bucket_kernel(const float* __restrict__ methy, int* __restrict__ idx) {
    int n = blockIdx.x * 256 + threadIdx.x;
    if (n >= NTOK) return;
    float v = methy[n];
    int c = 0;
    c += (v > -2.0f);
    c += (v > -1.0f);
    #pragma unroll
    for (int k = 0; k < 100; k++) c += (v > (float)k * 0.01f);
    idx[n] = c;
}

__global__ void embed_kernel(const int* __restrict__ idx, const int* __restrict__ pos,
                             const int* __restrict__ chromo,
                             const float* __restrict__ mtab, const float* __restrict__ ptab,
                             const float* __restrict__ ctab, float* __restrict__ x) {
    int n = blockIdx.x;
    int t = threadIdx.x;
    int mi = idx[n], pi = pos[n], ci = chromo[n];
    #pragma unroll
    for (int i = 0; i < 3; i++) {
        int d = t + i * 256;
        x[(size_t)n * DIM + d] = mtab[(size_t)mi * DIM + d]
                               + ptab[(size_t)pi * DIM + d]
                               + ctab[(size_t)ci * DIM + d];
    }
}

// ---------------- layernorm (one block per row, 768 = 3*256) ----------------
__global__ void ln_kernel(const float* __restrict__ x, const float* __restrict__ g,
                          const float* __restrict__ b, float* __restrict__ out) {
    __shared__ float red[256];
    int n = blockIdx.x, t = threadIdx.x;
    const float* xr = x + (size_t)n * DIM;
    float v0 = xr[t], v1 = xr[t + 256], v2 = xr[t + 512];
    red[t] = v0 + v1 + v2;
    __syncthreads();
    for (int s = 128; s; s >>= 1) { if (t < s) red[t] += red[t + s]; __syncthreads(); }
    float mu = red[0] * (1.0f / 768.0f);
    __syncthreads();
    float d0 = v0 - mu, d1 = v1 - mu, d2 = v2 - mu;
    red[t] = d0 * d0 + d1 * d1 + d2 * d2;
    __syncthreads();
    for (int s = 128; s; s >>= 1) { if (t < s) red[t] += red[t + s]; __syncthreads(); }
    float rstd = rsqrtf(red[0] * (1.0f / 768.0f) + 1e-5f);
    float* o = out + (size_t)n * DIM;
    o[t]       = d0 * rstd * g[t]       + b[t];
    o[t + 256] = d1 * rstd * g[t + 256] + b[t + 256];
    o[t + 512] = d2 * rstd * g[t + 512] + b[t + 512];
}

// ---------------- core tiled SGEMM (128x128x16, 8x8 micro via float4) -------
// EPI: 0 = none, 1 = +bias, 2 = gelu(+bias), 3 = +bias +res
template<int EPI, bool GUARD_N>
__device__ __forceinline__ void gemm_core(
    const float* __restrict__ A, int lda,
    const float* __restrict__ B, int ldb,
    const float* __restrict__ bias, const float* __restrict__ res,
    float* __restrict__ C, int ldc,
    int N, int K, int row0, int col0)
{
    __shared__ float As[16][132];   // padded: 132 floats = 528 B (16B aligned rows)
    __shared__ float Bs[16][128];

    int tid = threadIdx.x;
    int tx = tid & 15, ty = tid >> 4;
    // A tile loader: 128 rows x 16 k; thread -> rows (tid>>2) and 64+(tid>>2), k-chunk (tid&3)*4
    int arow = tid >> 2;
    int akc  = (tid & 3) * 4;
    // B tile loader: 16 rows x 128 cols; thread -> rows (tid>>5) and 8+(tid>>5), cols (tid&31)*4
    int brow = tid >> 5;
    int bcol = (tid & 31) * 4;

    float acc[8][8];
    #pragma unroll
    for (int i = 0; i < 8; i++)
        #pragma unroll
        for (int j = 0; j < 8; j++) acc[i][j] = 0.0f;

    float4 ra0, ra1, rb0, rb1;

    // prefetch k0 = 0
    {
        const float* Ap = A + (size_t)(row0 + arow) * lda + akc;
        ra0 = *(const float4*)Ap;
        ra1 = *(const float4*)(Ap + (size_t)64 * lda);
        if (GUARD_N) {
            const float* Bp0 = B + (size_t)brow * ldb + col0 + bcol;
            const float* Bp1 = B + (size_t)(brow + 8) * ldb + col0 + bcol;
            #pragma unroll
            for (int j = 0; j < 4; j++) {
                int c = col0 + bcol + j;
                ((float*)&rb0)[j] = (c < N) ? Bp0[j] : 0.0f;
                ((float*)&rb1)[j] = (c < N) ? Bp1[j] : 0.0f;
            }
        } else {
            rb0 = *(const float4*)(B + (size_t)brow * ldb + col0 + bcol);
            rb1 = *(const float4*)(B + (size_t)(brow + 8) * ldb + col0 + bcol);
        }
    }

    for (int k0 = 0; k0 < K; k0 += 16) {
        // stage to shared
        #pragma unroll
        for (int j = 0; j < 4; j++) {
            As[akc + j][arow]      = ((float*)&ra0)[j];
            As[akc + j][arow + 64] = ((float*)&ra1)[j];
        }
        *(float4*)&Bs[brow][bcol]     = rb0;
        *(float4*)&Bs[brow + 8][bcol] = rb1;
        __syncthreads();

        // prefetch next
        if (k0 + 16 < K) {
            const float* Ap = A + (size_t)(row0 + arow) * lda + k0 + 16 + akc;
            ra0 = *(const float4*)Ap;
            ra1 = *(const float4*)(Ap + (size_t)64 * lda);
            if (GUARD_N) {
                const float* Bp0 = B + (size_t)(k0 + 16 + brow) * ldb + col0 + bcol;
                const float* Bp1 = B + (size_t)(k0 + 24 + brow) * ldb + col0 + bcol;
                #pragma unroll
                for (int j = 0; j < 4; j++) {
                    int c = col0 + bcol + j;
                    ((float*)&rb0)[j] = (c < N) ? Bp0[j] : 0.0f;
                    ((float*)&rb1)[j] = (c < N) ? Bp1[j] : 0.0f;
                }
            } else {
                rb0 = *(const float4*)(B + (size_t)(k0 + 16 + brow) * ldb + col0 + bcol);
                rb1 = *(const float4*)(B + (size_t)(k0 + 24 + brow) * ldb + col0 + bcol);
            }
        }

        #pragma unroll
        for (int kk = 0; kk < 16; kk++) {
            const float4* As4 = (const float4*)&As[kk][0];
            const float4* Bs4 = (const float4*)&Bs[kk][0];
            float4 a0 = As4[ty], a1 = As4[ty + 16];
            float4 b0 = Bs4[tx], b1 = Bs4[tx + 16];
            float av[8] = {a0.x, a0.y, a0.z, a0.w, a1.x, a1.y, a1.z, a1.w};
            float bv[8] = {b0.x, b0.y, b0.z, b0.w, b1.x, b1.y, b1.z, b1.w};
            #pragma unroll
            for (int i = 0; i < 8; i++)
                #pragma unroll
                for (int j = 0; j < 8; j++) acc[i][j] += av[i] * bv[j];
        }
        __syncthreads();
    }

    // epilogue
    #pragma unroll
    for (int i = 0; i < 8; i++) {
        int r = row0 + (i < 4 ? ty * 4 + i : 64 + ty * 4 + (i - 4));
        #pragma unroll
        for (int half = 0; half < 2; half++) {
            int c0 = col0 + (half ? 64 + tx * 4 : tx * 4);
            if (GUARD_N) {
                #pragma unroll
                for (int j = 0; j < 4; j++) {
                    int c = c0 + j;
                    if (c < N) {
                        float v = acc[i][half * 4 + j];
                        if (EPI >= 1) v += bias[c];
                        if (EPI == 2) v = gelu_tanh(v);
                        if (EPI == 3) v += res[(size_t)r * ldc + c];
                        C[(size_t)r * ldc + c] = v;
                    }
                }
            } else {
                float4 v;
                v.x = acc[i][half * 4 + 0]; v.y = acc[i][half * 4 + 1];
                v.z = acc[i][half * 4 + 2]; v.w = acc[i][half * 4 + 3];
                if (EPI >= 1) {
                    float4 bb = *(const float4*)(bias + c0);
                    v.x += bb.x; v.y += bb.y; v.z += bb.z; v.w += bb.w;
                }
                if (EPI == 2) {
                    v.x = gelu_tanh(v.x); v.y = gelu_tanh(v.y);
                    v.z = gelu_tanh(v.z); v.w = gelu_tanh(v.w);
                }
                if (EPI == 3) {
                    float4 rr = *(const float4*)(res + (size_t)r * ldc + c0);
                    v.x += rr.x; v.y += rr.y; v.z += rr.z; v.w += rr.w;
                }
                *(float4*)(C + (size_t)r * ldc + c0) = v;
            }
        }
    }
}

template<int EPI>
__global__ __launch_bounds__(256, 2)
void sgemm_k(const float* __restrict__ A, int lda, const float* __restrict__ B, int ldb,
             const float* __restrict__ bias, const float* __restrict__ res,
             float* __restrict__ C, int ldc, int N, int K) {
    gemm_core<EPI, false>(A, lda, B, ldb, bias, res, C, ldc, N, K,
                          blockIdx.y * 128, blockIdx.x * 128);
}

__global__ __launch_bounds__(256, 2)
void sgemm_guard_k(const float* __restrict__ A, int lda, const float* __restrict__ B, int ldb,
                   const float* __restrict__ bias, float* __restrict__ C, int ldc,
                   int N, int K) {
    gemm_core<1, true>(A, lda, B, ldb, bias, nullptr, C, ldc, N, K,
                       blockIdx.y * 128, blockIdx.x * 128);
}

// fused QKV: blockIdx.z selects the weight / output
__global__ __launch_bounds__(256, 2)
void sgemm_qkv_k(const float* __restrict__ A,
                 const float* __restrict__ Bq, const float* __restrict__ Bk,
                 const float* __restrict__ Bv,
                 float* __restrict__ Cq, float* __restrict__ Ck, float* __restrict__ Cv) {
    int z = blockIdx.z;
    const float* B = (z == 0) ? Bq : (z == 1) ? Bk : Bv;
    float* C = (z == 0) ? Cq : (z == 1) ? Ck : Cv;
    gemm_core<0, false>(A, DIM, B, DIM, nullptr, nullptr, C, DIM, DIM, DIM,
                        blockIdx.y * 128, blockIdx.x * 128);
}

// FAVOR projection GEMM: xd[h][n][m] = x[n][h*64+d] @ (dnorm * proj^T)[d][m]
// z in [0,24): z<12 -> q path, else k path (h = z or z-12)
__global__ __launch_bounds__(256, 2)
void favor_xd_k(const float* __restrict__ q, const float* __restrict__ k,
                const float* __restrict__ projT,
                float* __restrict__ xq, float* __restrict__ xk) {
    int z = blockIdx.z;
    int h = (z < 12) ? z : z - 12;
    const float* A = ((z < 12) ? q : k) + h * DH;
    float* C = ((z < 12) ? xq : xk) + (size_t)h * NTOK * MFEAT;
    gemm_core<0, false>(A, DIM, projT, MFEAT, nullptr, nullptr, C, MFEAT, MFEAT, DH,
                        blockIdx.y * 128, blockIdx.x * 128);
}

// projT[d][m] = dnorm * proj[m][d]
__global__ void projT_kernel(const float* __restrict__ proj, float* __restrict__ projT) {
    int i = blockIdx.x * 256 + threadIdx.x;     // 16384
    int m = i >> 6, d = i & 63;
    projT[d * MFEAT + m] = 0.35355339059327373f * proj[i];
}

// ---------------- FAVOR+ post-processing -------------------------------------
// warp per (h,n) row: rowmax + diag + exp, in-place on xd
__global__ void q_post_kernel(const float* __restrict__ q, float* __restrict__ qf) {
    int gw = (blockIdx.x * 256 + threadIdx.x) >> 5;
    int lane = threadIdx.x & 31;
    int h = gw >> 12, n = gw & 4095;
    float* row = qf + (size_t)gw * MFEAT;
    float v[8];
    float mx = -3e38f;
    #pragma unroll
    for (int i = 0; i < 8; i++) { v[i] = row[lane + 32 * i]; mx = fmaxf(mx, v[i]); }
    #pragma unroll
    for (int off = 16; off; off >>= 1) mx = fmaxf(mx, __shfl_xor_sync(0xffffffffu, mx, off));
    const float* qr = q + (size_t)n * DIM + h * DH;
    float a = qr[lane], b = qr[lane + 32];
    float ss = a * a + b * b;
    #pragma unroll
    for (int off = 16; off; off >>= 1) ss += __shfl_xor_sync(0xffffffffu, ss, off);
    float diag = ss * 0.0625f;   // 0.5 * dnorm^2 = 1/16
    #pragma unroll
    for (int i = 0; i < 8; i++)
        row[lane + 32 * i] = 0.0625f * (expf(v[i] - diag - mx) + 1e-4f);
}

// per-head global max of raw xd_k
__global__ void k_max_kernel(const float* __restrict__ kf, unsigned* __restrict__ hmax) {
    __shared__ float red[256];
    int h = blockIdx.y, t = threadIdx.x;
    int n0 = blockIdx.x * 128;
    float m = -3e38f;
    for (int n = n0; n < n0 + 128; n++)
        m = fmaxf(m, kf[((size_t)((h << 12) + n)) * MFEAT + t]);
    red[t] = m;
    __syncthreads();
    for (int s = 128; s; s >>= 1) { if (t < s) red[t] = fmaxf(red[t], red[t + s]); __syncthreads(); }
    if (t == 0) atomicMax(hmax + h, f2o(red[0]));
}

__global__ void k_post_kernel(const float* __restrict__ k, float* __restrict__ kf,
                              const unsigned* __restrict__ hmax,
                              const float* __restrict__ methy) {
    int gw = (blockIdx.x * 256 + threadIdx.x) >> 5;
    int lane = threadIdx.x & 31;
    int h = gw >> 12, n = gw & 4095;
    float* row = kf + (size_t)gw * MFEAT;
    float mx = o2f(hmax[h]);
    const float* kr = k + (size_t)n * DIM + h * DH;
    float a = kr[lane], b = kr[lane + 32];
    float ss = a * a + b * b;
    #pragma unroll
    for (int off = 16; off; off >>= 1) ss += __shfl_xor_sync(0xffffffffu, ss, off);
    float diag = ss * 0.0625f;
    float msk = (methy[n] != 0.0f) ? 1.0f : 0.0f;
    #pragma unroll
    for (int i = 0; i < 8; i++) {
        float v = row[lane + 32 * i];
        row[lane + 32 * i] = msk * 0.0625f * (expf(v - diag - mx) + 1e-4f);
    }
}

// k_sum[h,m] += sum over 256-row n-chunk
__global__ void ksum_kernel(const float* __restrict__ kf, float* __restrict__ ksum) {
    int h = blockIdx.y, m = threadIdx.x;
    int n0 = blockIdx.x * 256;
    float s = 0.0f;
    for (int n = n0; n < n0 + 256; n++)
        s += kf[((size_t)((h << 12) + n)) * MFEAT + m];
    atomicAdd(&ksum[h * MFEAT + m], s);
}

// ctx[h,m,d] += sum_n kf[h,n,m]*v[n,h,d]
__global__ void ctx_kernel(const float* __restrict__ kf, const float* __restrict__ v,
                           float* __restrict__ ctx) {
    int h = blockIdx.y;
    int n0 = blockIdx.x * 128;
    int t = threadIdx.x;
    __shared__ float sv[4][64];
    float4 acc4[16];
    #pragma unroll
    for (int i = 0; i < 16; i++) acc4[i] = make_float4(0.f, 0.f, 0.f, 0.f);
    int rr = t >> 6, cc = t & 63;
    for (int n = n0; n < n0 + 128; n += 4) {
        sv[rr][cc] = v[(size_t)(n + rr) * DIM + h * DH + cc];
        __syncthreads();
        #pragma unroll
        for (int r = 0; r < 4; r++) {
            float kv = kf[((size_t)((h << 12) + n + r)) * MFEAT + t];
            const float4* vp = (const float4*)sv[r];
            #pragma unroll
            for (int d4 = 0; d4 < 16; d4++) {
                float4 vv = vp[d4];
                acc4[d4].x += kv * vv.x; acc4[d4].y += kv * vv.y;
                acc4[d4].z += kv * vv.z; acc4[d4].w += kv * vv.w;
            }
        }
        __syncthreads();
    }
    float* cp = ctx + ((size_t)h * MFEAT + t) * DH;
    #pragma unroll
    for (int d4 = 0; d4 < 16; d4++) {
        atomicAdd(&cp[d4 * 4 + 0], acc4[d4].x);
        atomicAdd(&cp[d4 * 4 + 1], acc4[d4].y);
        atomicAdd(&cp[d4 * 4 + 2], acc4[d4].z);
        atomicAdd(&cp[d4 * 4 + 3], acc4[d4].w);
    }
}

// d_inv[h,n] = 1 / (qf[h,n,:] . ksum[h,:])
__global__ void dinv_kernel(const float* __restrict__ qf, const float* __restrict__ ksum,
                            float* __restrict__ dinv) {
    int w = (blockIdx.x * blockDim.x + threadIdx.x) >> 5;
    int lane = threadIdx.x & 31;
    if (w >= HEADS * NTOK) return;
    int h = w >> 12;
    const float* qr = qf + (size_t)w * MFEAT;
    const float* ks = ksum + h * MFEAT;
    float s = 0.0f;
    #pragma unroll
    for (int m = lane; m < MFEAT; m += 32) s += qr[m] * ks[m];
    #pragma unroll
    for (int off = 16; off; off >>= 1) s += __shfl_xor_sync(0xffffffffu, s, off);
    if (lane == 0) dinv[w] = 1.0f / s;
}

// o[n, h*64 + d] = d_inv[h,n] * (qf[h,n,:] @ ctx[h,:,:])
__global__ void o_kernel(const float* __restrict__ qf, const float* __restrict__ ctx,
                         const float* __restrict__ dinv, float* __restrict__ o) {
    int h = blockIdx.y;
    int n0 = blockIdx.x * 32;
    int t = threadIdx.x;
    __shared__ float sQ[32][64];
    __shared__ float sC[64][64];
    int r = t >> 3, dl = t & 7;     // thread covers cols [dl*8, dl*8+8)
    float4 acc0 = make_float4(0.f, 0.f, 0.f, 0.f);
    float4 acc1 = make_float4(0.f, 0.f, 0.f, 0.f);
    for (int mc = 0; mc < MFEAT; mc += 64) {
        #pragma unroll
        for (int i = 0; i < 8; i++) {
            int idx = t + i * 256, rr = idx >> 6, cc = idx & 63;
            sQ[rr][cc] = qf[((size_t)((h << 12) + n0 + rr)) * MFEAT + mc + cc];
        }
        #pragma unroll
        for (int i = 0; i < 16; i++) {
            int idx = t + i * 256, rr = idx >> 6, cc = idx & 63;
            sC[rr][cc] = ctx[((size_t)h * MFEAT + mc + rr) * DH + cc];
        }
        __syncthreads();
        #pragma unroll
        for (int m = 0; m < 64; m++) {
            float qv = sQ[r][m];
            const float4* cp = (const float4*)sC[m];
            float4 c0 = cp[dl * 2], c1 = cp[dl * 2 + 1];
            acc0.x += qv * c0.x; acc0.y += qv * c0.y;
            acc0.z += qv * c0.z; acc0.w += qv * c0.w;
            acc1.x += qv * c1.x; acc1.y += qv * c1.y;
            acc1.z += qv * c1.z; acc1.w += qv * c1.w;
        }
        __syncthreads();
    }
    float di = dinv[(h << 12) + n0 + r];
    float* op = o + (size_t)(n0 + r) * DIM + h * DH + dl * 8;
    op[0] = acc0.x * di; op[1] = acc0.y * di; op[2] = acc0.z * di; op[3] = acc0.w * di;
    op[4] = acc1.x * di; op[5] = acc1.y * di; op[6] = acc1.z * di; op[7] = acc1.w * di;
}

// ---------------- host ------------------------------------------------------
extern "C" void kernel_launch(void* const* d_in, const int* in_sizes, int n_in,
                              void* d_out, int out_size) {
    const float* methy  = (const float*)d_in[0];
    const int*   chromo = (const int*)  d_in[1];
    const int*   pos    = (const int*)  d_in[2];
    const float* mtab   = (const float*)d_in[3];
    const float* ctab   = (const float*)d_in[4];
    const float* ptab   = (const float*)d_in[5];
    const float* ln1g   = (const float*)d_in[6];
    const float* ln1b   = (const float*)d_in[7];
    const float* ln2g   = (const float*)d_in[8];
    const float* ln2b   = (const float*)d_in[9];
    const float* Wq     = (const float*)d_in[10];
    const float* Wk     = (const float*)d_in[11];
    const float* Wv     = (const float*)d_in[12];
    const float* Wo     = (const float*)d_in[13];
    const float* bo     = (const float*)d_in[14];
    const float* W1     = (const float*)d_in[15];
    const float* b1     = (const float*)d_in[16];
    const float* W2     = (const float*)d_in[17];
    const float* b2     = (const float*)d_in[18];
    const float* proj   = (const float*)d_in[19];
    const float* nfg    = (const float*)d_in[20];
    const float* nfb    = (const float*)d_in[21];
    const float* Wout   = (const float*)d_in[22];
    const float* bout   = (const float*)d_in[23];
    float* out = (float*)d_out;

    float *px, *ph, *pq, *pk, *pv, *po, *pff, *pqf, *pkf, *pksum, *pctx, *pdinv, *pprojT;
    unsigned* phmax; int* pbidx;
    cudaGetSymbolAddress((void**)&px,     g_x);
    cudaGetSymbolAddress((void**)&ph,     g_h);
    cudaGetSymbolAddress((void**)&pq,     g_q);
    cudaGetSymbolAddress((void**)&pk,     g_k);
    cudaGetSymbolAddress((void**)&pv,     g_v);
    cudaGetSymbolAddress((void**)&po,     g_o);
    cudaGetSymbolAddress((void**)&pff,    g_ff);
    cudaGetSymbolAddress((void**)&pqf,    g_qf);
    cudaGetSymbolAddress((void**)&pkf,    g_kf);
    cudaGetSymbolAddress((void**)&pksum,  g_ksum);
    cudaGetSymbolAddress((void**)&pctx,   g_ctx);
    cudaGetSymbolAddress((void**)&pdinv,  g_dinv);
    cudaGetSymbolAddress((void**)&phmax,  g_hmax);
    cudaGetSymbolAddress((void**)&pbidx,  g_bidx);
    cudaGetSymbolAddress((void**)&pprojT, g_projT);

    bucket_kernel<<<16, 256>>>(methy, pbidx);
    embed_kernel<<<NTOK, 256>>>(pbidx, pos, chromo, mtab, ptab, ctab, px);

    for (int l = 0; l < DEPTH; l++) {
        const float* prl = proj + (size_t)l * MFEAT * DH;

        ln_kernel<<<NTOK, 256>>>(px, ln1g + l * DIM, ln1b + l * DIM, ph);
        sgemm_qkv_k<<<dim3(6, 32, 3), 256>>>(ph,
            Wq + (size_t)l * DIM * DIM, Wk + (size_t)l * DIM * DIM, Wv + (size_t)l * DIM * DIM,
            pq, pk, pv);

        cudaMemsetAsync(phmax, 0, HEADS * sizeof(unsigned));
        cudaMemsetAsync(pksum, 0, HEADS * MFEAT * sizeof(float));
        cudaMemsetAsync(pctx,  0, HEADS * MFEAT * DH * sizeof(float));

        projT_kernel<<<64, 256>>>(prl, pprojT);
        favor_xd_k<<<dim3(2, 32, 24), 256>>>(pq, pk, pprojT, pqf, pkf);
        q_post_kernel<<<HEADS * NTOK / 8, 256>>>(pq, pqf);
        k_max_kernel<<<dim3(32, HEADS), 256>>>(pkf, phmax);
        k_post_kernel<<<HEADS * NTOK / 8, 256>>>(pk, pkf, phmax, methy);
        ksum_kernel<<<dim3(16, HEADS), 256>>>(pkf, pksum);
        ctx_kernel<<<dim3(32, HEADS), 256>>>(pkf, pv, pctx);
        dinv_kernel<<<HEADS * NTOK / 8, 256>>>(pqf, pksum, pdinv);
        o_kernel<<<dim3(NTOK / 32, HEADS), 256>>>(pqf, pctx, pdinv, po);

        sgemm_k<3><<<dim3(6, 32), 256>>>(po, DIM, Wo + (size_t)l * DIM * DIM, DIM,
                                         bo + l * DIM, px, px, DIM, DIM, DIM);
        ln_kernel<<<NTOK, 256>>>(px, ln2g + l * DIM, ln2b + l * DIM, ph);
        sgemm_k<2><<<dim3(24, 32), 256>>>(ph, DIM, W1 + (size_t)l * DIM * FFD, FFD,
                                          b1 + l * FFD, nullptr, pff, FFD, FFD, DIM);
        sgemm_k<3><<<dim3(6, 32), 256>>>(pff, FFD, W2 + (size_t)l * FFD * DIM, DIM,
                                         b2 + l * DIM, px, px, DIM, DIM, FFD);
    }

    ln_kernel<<<NTOK, 256>>>(px, nfg, nfb, ph);
    sgemm_guard_k<<<dim3(1, 32), 256>>>(ph, DIM, Wout, NOUT, bout, out, NOUT, NOUT, DIM);
}

// round 9
// speedup vs baseline: 1.7220x; 1.7220x over previous
#include <cuda_runtime.h>
#include <cuda_bf16.h>
#include <math.h>
#include <stdint.h>

#define NTOK  4096
#define DIM   768
#define DEPTH 6
#define HEADS 12
#define DH    64
#define FFD   3072
#define MFEAT 256
#define NOUT  102

// ---------------- fp32 scratch ----------------------------------------------
__device__ float g_x  [NTOK*DIM];
__device__ float g_h  [NTOK*DIM];
__device__ float g_q  [NTOK*DIM];
__device__ float g_k  [NTOK*DIM];
__device__ float g_v  [NTOK*DIM];
__device__ float g_qf [HEADS*NTOK*MFEAT];
__device__ float g_kf [HEADS*NTOK*MFEAT];
__device__ unsigned g_hmax[HEADS];
__device__ float g_ksum[HEADS*MFEAT];
__device__ float g_ctx [HEADS*MFEAT*DH];
__device__ float g_dinv[HEADS*NTOK];
__device__ int   g_bidx[NTOK];

// ---------------- bf16 hi/lo scratch -----------------------------------------
__device__ __nv_bfloat16 g_hh [NTOK*DIM],  g_hl [NTOK*DIM];
__device__ __nv_bfloat16 g_qh [NTOK*DIM],  g_ql [NTOK*DIM];
__device__ __nv_bfloat16 g_kh [NTOK*DIM],  g_kl [NTOK*DIM];
__device__ __nv_bfloat16 g_vh [NTOK*DIM],  g_vl [NTOK*DIM];
__device__ __nv_bfloat16 g_oh [NTOK*DIM],  g_ol [NTOK*DIM];
__device__ __nv_bfloat16 g_ffh[NTOK*FFD],  g_ffl[NTOK*FFD];
__device__ __nv_bfloat16 g_qfh[HEADS*NTOK*MFEAT], g_qfl[HEADS*NTOK*MFEAT];
__device__ __nv_bfloat16 g_ctTh[HEADS*DH*MFEAT],  g_ctTl[HEADS*DH*MFEAT];
__device__ __nv_bfloat16 g_pch[DEPTH*MFEAT*DH],   g_pcl[DEPTH*MFEAT*DH];
__device__ __nv_bfloat16 g_wqh[DEPTH*DIM*DIM], g_wql[DEPTH*DIM*DIM];
__device__ __nv_bfloat16 g_wkh[DEPTH*DIM*DIM], g_wkl[DEPTH*DIM*DIM];
__device__ __nv_bfloat16 g_wvh[DEPTH*DIM*DIM], g_wvl[DEPTH*DIM*DIM];
__device__ __nv_bfloat16 g_woh[DEPTH*DIM*DIM], g_wol[DEPTH*DIM*DIM];
__device__ __nv_bfloat16 g_w1h[DEPTH*FFD*DIM], g_w1l[DEPTH*FFD*DIM];
__device__ __nv_bfloat16 g_w2h[DEPTH*DIM*FFD], g_w2l[DEPTH*DIM*FFD];

// ---------------- helpers ----------------------------------------------------
__device__ __forceinline__ unsigned f2o(float f) {
    unsigned u = __float_as_uint(f);
    return (u & 0x80000000u) ? ~u : (u | 0x80000000u);
}
__device__ __forceinline__ float o2f(unsigned u) {
    return __uint_as_float((u & 0x80000000u) ? (u & 0x7fffffffu) : ~u);
}
__device__ __forceinline__ float gelu_tanh(float x) {
    float x3 = x * x * x;
    return 0.5f * x * (1.0f + tanhf(0.7978845608028654f * (x + 0.044715f * x3)));
}
__device__ __forceinline__ uint32_t smem_u32(const void* p) {
    uint32_t a;
    asm("{ .reg .u64 t; cvta.to.shared.u64 t, %1; cvt.u32.u64 %0, t; }" : "=r"(a) : "l"(p));
    return a;
}
__device__ __forceinline__ void split_store(float v, __nv_bfloat16* oh,
                                            __nv_bfloat16* ol, size_t i) {
    __nv_bfloat16 h = __float2bfloat16(v);
    oh[i] = h;
    ol[i] = __float2bfloat16(v - __bfloat162float(h));
}

// ldmatrix x4 for A tile (m16 x k16) from padded smem (row stride 40 bf16)
__device__ __forceinline__ void ldmA(uint32_t f[4], const __nv_bfloat16* base, int lane) {
    const __nv_bfloat16* p = base + (lane & 15) * 40 + ((lane >> 4) << 3);
    uint32_t a = smem_u32(p);
    asm volatile("ldmatrix.sync.aligned.m8n8.x4.shared.b16 {%0,%1,%2,%3}, [%4];"
                 : "=r"(f[0]), "=r"(f[1]), "=r"(f[2]), "=r"(f[3]) : "r"(a));
}
// ldmatrix x4 for two B tiles (n 0..15 of a 16 x k16 region), B smem is [n][k]
__device__ __forceinline__ void ldmB(uint32_t f0[2], uint32_t f1[2],
                                     const __nv_bfloat16* base, int lane) {
    int r = (lane & 7) + ((lane >> 4) << 3);
    int c = ((lane >> 3) & 1) << 3;
    const __nv_bfloat16* p = base + r * 40 + c;
    uint32_t a = smem_u32(p);
    asm volatile("ldmatrix.sync.aligned.m8n8.x4.shared.b16 {%0,%1,%2,%3}, [%4];"
                 : "=r"(f0[0]), "=r"(f0[1]), "=r"(f1[0]), "=r"(f1[1]) : "r"(a));
}
__device__ __forceinline__ void mma16816(float c[4], const uint32_t a[4], const uint32_t b[2]) {
    asm volatile(
        "mma.sync.aligned.m16n8k16.row.col.f32.bf16.bf16.f32 "
        "{%0,%1,%2,%3}, {%4,%5,%6,%7}, {%8,%9}, {%0,%1,%2,%3};"
        : "+f"(c[0]), "+f"(c[1]), "+f"(c[2]), "+f"(c[3])
        : "r"(a[0]), "r"(a[1]), "r"(a[2]), "r"(a[3]), "r"(b[0]), "r"(b[1]));
}

// ---------------- small SIMT kernels -----------------------------------------
__global__ void bucket_kernel(const float* __restrict__ methy, int* __restrict__ idx) {
    int n = blockIdx.x * 256 + threadIdx.x;
    if (n >= NTOK) return;
    float v = methy[n];
    int c = 0;
    c += (v > -2.0f);
    c += (v > -1.0f);
    #pragma unroll
    for (int k = 0; k < 100; k++) c += (v > (float)k * 0.01f);
    idx[n] = c;
}

__global__ void embed_kernel(const int* __restrict__ idx, const int* __restrict__ pos,
                             const int* __restrict__ chromo,
                             const float* __restrict__ mtab, const float* __restrict__ ptab,
                             const float* __restrict__ ctab, float* __restrict__ x) {
    int n = blockIdx.x, t = threadIdx.x;
    int mi = idx[n], pi = pos[n], ci = chromo[n];
    #pragma unroll
    for (int i = 0; i < 3; i++) {
        int d = t + i * 256;
        x[(size_t)n * DIM + d] = mtab[(size_t)mi * DIM + d]
                               + ptab[(size_t)pi * DIM + d]
                               + ctab[(size_t)ci * DIM + d];
    }
}

__global__ void ln_kernel(const float* __restrict__ x, const float* __restrict__ g,
                          const float* __restrict__ b, float* __restrict__ out,
                          __nv_bfloat16* __restrict__ oh, __nv_bfloat16* __restrict__ ol) {
    __shared__ float red[256];
    int n = blockIdx.x, t = threadIdx.x;
    const float* xr = x + (size_t)n * DIM;
    float v0 = xr[t], v1 = xr[t + 256], v2 = xr[t + 512];
    red[t] = v0 + v1 + v2;
    __syncthreads();
    for (int s = 128; s; s >>= 1) { if (t < s) red[t] += red[t + s]; __syncthreads(); }
    float mu = red[0] * (1.0f / 768.0f);
    __syncthreads();
    float d0 = v0 - mu, d1 = v1 - mu, d2 = v2 - mu;
    red[t] = d0 * d0 + d1 * d1 + d2 * d2;
    __syncthreads();
    for (int s = 128; s; s >>= 1) { if (t < s) red[t] += red[t + s]; __syncthreads(); }
    float rstd = rsqrtf(red[0] * (1.0f / 768.0f) + 1e-5f);
    size_t base = (size_t)n * DIM;
    float r0 = d0 * rstd * g[t]       + b[t];
    float r1 = d1 * rstd * g[t + 256] + b[t + 256];
    float r2 = d2 * rstd * g[t + 512] + b[t + 512];
    out[base + t] = r0; out[base + t + 256] = r1; out[base + t + 512] = r2;
    split_store(r0, oh, ol, base + t);
    split_store(r1, oh, ol, base + t + 256);
    split_store(r2, oh, ol, base + t + 512);
}

__global__ void q_post_kernel(const float* __restrict__ q, float* __restrict__ qf,
                              __nv_bfloat16* __restrict__ qh, __nv_bfloat16* __restrict__ ql) {
    int gw = (blockIdx.x * 256 + threadIdx.x) >> 5;
    int lane = threadIdx.x & 31;
    int h = gw >> 12, n = gw & 4095;
    float* row = qf + (size_t)gw * MFEAT;
    float v[8];
    float mx = -3e38f;
    #pragma unroll
    for (int i = 0; i < 8; i++) { v[i] = row[lane + 32 * i]; mx = fmaxf(mx, v[i]); }
    #pragma unroll
    for (int off = 16; off; off >>= 1) mx = fmaxf(mx, __shfl_xor_sync(0xffffffffu, mx, off));
    const float* qr = q + (size_t)n * DIM + h * DH;
    float a = qr[lane], b = qr[lane + 32];
    float ss = a * a + b * b;
    #pragma unroll
    for (int off = 16; off; off >>= 1) ss += __shfl_xor_sync(0xffffffffu, ss, off);
    float diag = ss * 0.0625f;
    #pragma unroll
    for (int i = 0; i < 8; i++) {
        float r = 0.0625f * (expf(v[i] - diag - mx) + 1e-4f);
        row[lane + 32 * i] = r;
        split_store(r, qh, ql, (size_t)gw * MFEAT + lane + 32 * i);
    }
}

__global__ void k_max_kernel(const float* __restrict__ kf, unsigned* __restrict__ hmax) {
    __shared__ float red[256];
    int h = blockIdx.y, t = threadIdx.x;
    int n0 = blockIdx.x * 128;
    float m = -3e38f;
    for (int n = n0; n < n0 + 128; n++)
        m = fmaxf(m, kf[((size_t)((h << 12) + n)) * MFEAT + t]);
    red[t] = m;
    __syncthreads();
    for (int s = 128; s; s >>= 1) { if (t < s) red[t] = fmaxf(red[t], red[t + s]); __syncthreads(); }
    if (t == 0) atomicMax(hmax + h, f2o(red[0]));
}

__global__ void k_post_kernel(const float* __restrict__ k, float* __restrict__ kf,
                              const unsigned* __restrict__ hmax,
                              const float* __restrict__ methy) {
    int gw = (blockIdx.x * 256 + threadIdx.x) >> 5;
    int lane = threadIdx.x & 31;
    int h = gw >> 12, n = gw & 4095;
    float* row = kf + (size_t)gw * MFEAT;
    float mx = o2f(hmax[h]);
    const float* kr = k + (size_t)n * DIM + h * DH;
    float a = kr[lane], b = kr[lane + 32];
    float ss = a * a + b * b;
    #pragma unroll
    for (int off = 16; off; off >>= 1) ss += __shfl_xor_sync(0xffffffffu, ss, off);
    float diag = ss * 0.0625f;
    float msk = (methy[n] != 0.0f) ? 1.0f : 0.0f;
    #pragma unroll
    for (int i = 0; i < 8; i++) {
        float v = row[lane + 32 * i];
        row[lane + 32 * i] = msk * 0.0625f * (expf(v - diag - mx) + 1e-4f);
    }
}

__global__ void ksum_kernel(const float* __restrict__ kf, float* __restrict__ ksum) {
    int h = blockIdx.y, m = threadIdx.x;
    int n0 = blockIdx.x * 256;
    float s = 0.0f;
    for (int n = n0; n < n0 + 256; n++)
        s += kf[((size_t)((h << 12) + n)) * MFEAT + m];
    atomicAdd(&ksum[h * MFEAT + m], s);
}

__global__ void ctx_kernel(const float* __restrict__ kf, const float* __restrict__ v,
                           float* __restrict__ ctx) {
    int h = blockIdx.y;
    int n0 = blockIdx.x * 128;
    int t = threadIdx.x;
    __shared__ float sv[4][64];
    float4 acc4[16];
    #pragma unroll
    for (int i = 0; i < 16; i++) acc4[i] = make_float4(0.f, 0.f, 0.f, 0.f);
    int rr = t >> 6, cc = t & 63;
    for (int n = n0; n < n0 + 128; n += 4) {
        sv[rr][cc] = v[(size_t)(n + rr) * DIM + h * DH + cc];
        __syncthreads();
        #pragma unroll
        for (int r = 0; r < 4; r++) {
            float kv = kf[((size_t)((h << 12) + n + r)) * MFEAT + t];
            const float4* vp = (const float4*)sv[r];
            #pragma unroll
            for (int d4 = 0; d4 < 16; d4++) {
                float4 vv = vp[d4];
                acc4[d4].x += kv * vv.x; acc4[d4].y += kv * vv.y;
                acc4[d4].z += kv * vv.z; acc4[d4].w += kv * vv.w;
            }
        }
        __syncthreads();
    }
    float* cp = ctx + ((size_t)h * MFEAT + t) * DH;
    #pragma unroll
    for (int d4 = 0; d4 < 16; d4++) {
        atomicAdd(&cp[d4 * 4 + 0], acc4[d4].x);
        atomicAdd(&cp[d4 * 4 + 1], acc4[d4].y);
        atomicAdd(&cp[d4 * 4 + 2], acc4[d4].z);
        atomicAdd(&cp[d4 * 4 + 3], acc4[d4].w);
    }
}

__global__ void dinv_kernel(const float* __restrict__ qf, const float* __restrict__ ksum,
                            float* __restrict__ dinv) {
    int w = (blockIdx.x * blockDim.x + threadIdx.x) >> 5;
    int lane = threadIdx.x & 31;
    if (w >= HEADS * NTOK) return;
    int h = w >> 12;
    const float* qr = qf + (size_t)w * MFEAT;
    const float* ks = ksum + h * MFEAT;
    float s = 0.0f;
    #pragma unroll
    for (int m = lane; m < MFEAT; m += 32) s += qr[m] * ks[m];
    #pragma unroll
    for (int off = 16; off; off >>= 1) s += __shfl_xor_sync(0xffffffffu, s, off);
    if (lane == 0) dinv[w] = 1.0f / s;
}

__global__ void ctxT_kernel(const float* __restrict__ ctx,
                            __nv_bfloat16* __restrict__ oh, __nv_bfloat16* __restrict__ ol) {
    int h = blockIdx.x;
    for (int i = threadIdx.x; i < MFEAT * DH; i += 256) {
        int m = i >> 6, d = i & 63;
        float v = ctx[(size_t)h * MFEAT * DH + i];
        split_store(v, oh, ol, ((size_t)h * DH + d) * MFEAT + m);
    }
}

__global__ void tconv_kernel(const float* __restrict__ in, int ldi, size_t inz,
                             __nv_bfloat16* __restrict__ oh, __nv_bfloat16* __restrict__ ol,
                             int ldo, size_t outz) {
    __shared__ float ts[32][33];
    const float* ip = in + (size_t)blockIdx.z * inz;
    int r0 = blockIdx.y * 32, c0 = blockIdx.x * 32;
    int tx = threadIdx.x, ty = threadIdx.y;
    #pragma unroll
    for (int j = 0; j < 4; j++)
        ts[ty + j * 8][tx] = ip[(size_t)(r0 + ty + j * 8) * ldi + c0 + tx];
    __syncthreads();
    size_t ob = (size_t)blockIdx.z * outz;
    #pragma unroll
    for (int j = 0; j < 4; j++)
        split_store(ts[tx][ty + j * 8], oh, ol, ob + (size_t)(c0 + ty + j * 8) * ldo + r0 + tx);
}

__global__ void projc_kernel(const float* __restrict__ in,
                             __nv_bfloat16* __restrict__ oh, __nv_bfloat16* __restrict__ ol) {
    size_t i = (size_t)blockIdx.x * 256 + threadIdx.x;
    split_store(0.35355339059327373f * in[i], oh, ol, i);
}

// ---------------- HMMA GEMM core (mma.sync bf16, 3-term split) ---------------
// D(128 x TN) = A(128 x K) @ B(TN x K)^T
// EPI: 0=fp32 C | 2=bias+gelu->splits | 3=bias+res->fp32 | 4=fp32+splits | 6=scale[r]->splits
template<int EPI>
__device__ __forceinline__ void epi2(int r, int c, float v0, float v1,
                                     const float* __restrict__ bias, const float* __restrict__ res,
                                     float* __restrict__ C, __nv_bfloat16* __restrict__ Ch,
                                     __nv_bfloat16* __restrict__ Cl, int ldc,
                                     const float* __restrict__ scale) {
    if (EPI == 2 || EPI == 3) { v0 += bias[c]; v1 += bias[c + 1]; }
    if (EPI == 2) { v0 = gelu_tanh(v0); v1 = gelu_tanh(v1); }
    if (EPI == 3) {
        float2 rr = *(const float2*)(res + (size_t)r * ldc + c);
        v0 += rr.x; v1 += rr.y;
    }
    if (EPI == 6) { float s = scale[r]; v0 *= s; v1 *= s; }
    if (EPI == 0 || EPI == 3 || EPI == 4)
        *(float2*)(C + (size_t)r * ldc + c) = make_float2(v0, v1);
    if (EPI == 2 || EPI == 4 || EPI == 6) {
        __nv_bfloat16 h0 = __float2bfloat16(v0), h1 = __float2bfloat16(v1);
        __nv_bfloat16 l0 = __float2bfloat16(v0 - __bfloat162float(h0));
        __nv_bfloat16 l1 = __float2bfloat16(v1 - __bfloat162float(h1));
        __nv_bfloat162 hh = __halves2bfloat162(h0, h1);
        __nv_bfloat162 ll = __halves2bfloat162(l0, l1);
        *(__nv_bfloat162*)(Ch + (size_t)r * ldc + c) = hh;
        *(__nv_bfloat162*)(Cl + (size_t)r * ldc + c) = ll;
    }
}

template<int EPI, int TN>
__device__ void hmma_core(const __nv_bfloat16* __restrict__ Ah, const __nv_bfloat16* __restrict__ Al,
                          int lda,
                          const __nv_bfloat16* __restrict__ Bh, const __nv_bfloat16* __restrict__ Bl,
                          int ldb,
                          const float* __restrict__ bias, const float* __restrict__ res,
                          float* __restrict__ C, __nv_bfloat16* __restrict__ Ch,
                          __nv_bfloat16* __restrict__ Cl, int ldc,
                          const float* __restrict__ scale,
                          int K, int row0, int col0)
{
    __shared__ __align__(16) __nv_bfloat16 As[2][128][40];
    __shared__ __align__(16) __nv_bfloat16 Bs[2][TN][40];

    const int MT = (TN == 128) ? 4 : 2;     // warp m-tiles of 16
    int tid = threadIdx.x, w = tid >> 5, lane = tid & 31;
    int wm0, wn0;
    if (TN == 128) { wm0 = (w >> 2) * 64; wn0 = (w & 3) * 32; }
    else           { wm0 = (w >> 1) * 32; wn0 = (w & 1) * 32; }

    float acc[4][4][4];
    #pragma unroll
    for (int i = 0; i < 4; i++)
        #pragma unroll
        for (int j = 0; j < 4; j++)
            #pragma unroll
            for (int e = 0; e < 4; e++) acc[i][j][e] = 0.0f;

    int nch = K >> 5;
    for (int c = 0; c < nch; c++) {
        int k0 = c << 5;
        if (c) __syncthreads();
        for (int i = tid; i < 128 * 4; i += 256) {
            int r = i >> 2, kp = (i & 3) << 3;
            size_t gi = (size_t)(row0 + r) * lda + k0 + kp;
            *(uint4*)&As[0][r][kp] = *(const uint4*)(Ah + gi);
            *(uint4*)&As[1][r][kp] = *(const uint4*)(Al + gi);
        }
        for (int i = tid; i < TN * 4; i += 256) {
            int r = i >> 2, kp = (i & 3) << 3;
            size_t gi = (size_t)(col0 + r) * ldb + k0 + kp;
            *(uint4*)&Bs[0][r][kp] = *(const uint4*)(Bh + gi);
            *(uint4*)&Bs[1][r][kp] = *(const uint4*)(Bl + gi);
        }
        __syncthreads();
        #pragma unroll
        for (int kk = 0; kk < 32; kk += 16) {
            uint32_t bh[4][2], bl[4][2];
            ldmB(bh[0], bh[1], &Bs[0][wn0][kk], lane);
            ldmB(bh[2], bh[3], &Bs[0][wn0 + 16][kk], lane);
            ldmB(bl[0], bl[1], &Bs[1][wn0][kk], lane);
            ldmB(bl[2], bl[3], &Bs[1][wn0 + 16][kk], lane);
            #pragma unroll
            for (int mt = 0; mt < MT; mt++) {
                uint32_t ah[4], al[4];
                ldmA(ah, &As[0][wm0 + mt * 16][kk], lane);
                ldmA(al, &As[1][wm0 + mt * 16][kk], lane);
                #pragma unroll
                for (int nt = 0; nt < 4; nt++) {
                    mma16816(acc[mt][nt], ah, bh[nt]);
                    mma16816(acc[mt][nt], ah, bl[nt]);
                    mma16816(acc[mt][nt], al, bh[nt]);
                }
            }
        }
    }

    #pragma unroll
    for (int mt = 0; mt < MT; mt++) {
        #pragma unroll
        for (int nt = 0; nt < 4; nt++) {
            int r = row0 + wm0 + mt * 16 + (lane >> 2);
            int cc = col0 + wn0 + nt * 8 + ((lane & 3) << 1);
            epi2<EPI>(r,     cc, acc[mt][nt][0], acc[mt][nt][1], bias, res, C, Ch, Cl, ldc, scale);
            epi2<EPI>(r + 8, cc, acc[mt][nt][2], acc[mt][nt][3], bias, res, C, Ch, Cl, ldc, scale);
        }
    }
}

// ---------------- HMMA wrappers ----------------------------------------------
template<int EPI>
__global__ __launch_bounds__(256) void hm_plain_k(
    const __nv_bfloat16* Ah, const __nv_bfloat16* Al, int lda,
    const __nv_bfloat16* Bh, const __nv_bfloat16* Bl, int ldb,
    const float* bias, const float* res,
    float* C, __nv_bfloat16* Ch, __nv_bfloat16* Cl, int ldc, int K)
{
    hmma_core<EPI, 128>(Ah, Al, lda, Bh, Bl, ldb, bias, res, C, Ch, Cl, ldc,
                        nullptr, K, blockIdx.y * 128, blockIdx.x * 128);
}

__global__ __launch_bounds__(256) void hm_qkv_k(
    const __nv_bfloat16* Ah, const __nv_bfloat16* Al,
    const __nv_bfloat16* Wqh, const __nv_bfloat16* Wql,
    const __nv_bfloat16* Wkh, const __nv_bfloat16* Wkl,
    const __nv_bfloat16* Wvh, const __nv_bfloat16* Wvl,
    float* q, float* k, float* v,
    __nv_bfloat16* qh, __nv_bfloat16* ql, __nv_bfloat16* kh, __nv_bfloat16* kl,
    __nv_bfloat16* vh, __nv_bfloat16* vl)
{
    int z = blockIdx.z;
    const __nv_bfloat16* Bh = (z == 0) ? Wqh : (z == 1) ? Wkh : Wvh;
    const __nv_bfloat16* Bl = (z == 0) ? Wql : (z == 1) ? Wkl : Wvl;
    float* C = (z == 0) ? q : (z == 1) ? k : v;
    __nv_bfloat16* Ch = (z == 0) ? qh : (z == 1) ? kh : vh;
    __nv_bfloat16* Cl = (z == 0) ? ql : (z == 1) ? kl : vl;
    hmma_core<4, 128>(Ah, Al, DIM, Bh, Bl, DIM, nullptr, nullptr, C, Ch, Cl, DIM,
                      nullptr, DIM, blockIdx.y * 128, blockIdx.x * 128);
}

__global__ __launch_bounds__(256) void hm_xd_k(
    const __nv_bfloat16* qh, const __nv_bfloat16* ql,
    const __nv_bfloat16* kh, const __nv_bfloat16* kl,
    const __nv_bfloat16* prh, const __nv_bfloat16* prl,
    float* xq, float* xk)
{
    int z = blockIdx.z;
    int h = (z < 12) ? z : z - 12;
    const __nv_bfloat16* Ah = ((z < 12) ? qh : kh) + h * DH;
    const __nv_bfloat16* Al = ((z < 12) ? ql : kl) + h * DH;
    float* C = ((z < 12) ? xq : xk) + (size_t)h * NTOK * MFEAT;
    hmma_core<0, 128>(Ah, Al, DIM, prh, prl, DH, nullptr, nullptr, C, nullptr, nullptr, MFEAT,
                      nullptr, DH, blockIdx.y * 128, blockIdx.x * 128);
}

__global__ __launch_bounds__(256) void hm_o_k(
    const __nv_bfloat16* qfh, const __nv_bfloat16* qfl,
    const __nv_bfloat16* cth, const __nv_bfloat16* ctl,
    const float* dinv, __nv_bfloat16* oh, __nv_bfloat16* ol)
{
    int h = blockIdx.z;
    hmma_core<6, 64>(qfh + (size_t)h * NTOK * MFEAT, qfl + (size_t)h * NTOK * MFEAT, MFEAT,
                     cth + (size_t)h * DH * MFEAT, ctl + (size_t)h * DH * MFEAT, MFEAT,
                     nullptr, nullptr, nullptr, oh + h * DH, ol + h * DH, DIM,
                     dinv + (size_t)h * NTOK, MFEAT, blockIdx.y * 128, 0);
}

// ---------------- SIMT guard GEMM for tiny Wout -------------------------------
__global__ __launch_bounds__(256)
void sgemm_guard_k(const float* __restrict__ A, int lda, const float* __restrict__ B, int ldb,
                   const float* __restrict__ bias, float* __restrict__ C, int ldc,
                   int N, int K) {
    __shared__ float As[8][128];
    __shared__ float Bs[8][128];
    int tid = threadIdx.x;
    int row0 = blockIdx.y * 128, col0 = blockIdx.x * 128;
    int tx = tid & 15, ty = tid >> 4;
    int arow = tid >> 1, acol = (tid & 1) * 4;
    int brow = tid >> 5, bcol = (tid & 31) * 4;
    float acc[8][8];
    #pragma unroll
    for (int i = 0; i < 8; i++)
        #pragma unroll
        for (int j = 0; j < 8; j++) acc[i][j] = 0.0f;
    for (int k0 = 0; k0 < K; k0 += 8) {
        float4 av = *(const float4*)(A + (size_t)(row0 + arow) * lda + k0 + acol);
        As[acol + 0][arow] = av.x; As[acol + 1][arow] = av.y;
        As[acol + 2][arow] = av.z; As[acol + 3][arow] = av.w;
        #pragma unroll
        for (int j = 0; j < 4; j++) {
            int c = col0 + bcol + j;
            Bs[brow][bcol + j] = (c < N) ? B[(size_t)(k0 + brow) * ldb + c] : 0.0f;
        }
        __syncthreads();
        #pragma unroll
        for (int kk = 0; kk < 8; kk++) {
            float a[8], bb[8];
            #pragma unroll
            for (int i = 0; i < 8; i++) a[i] = As[kk][ty + 16 * i];
            #pragma unroll
            for (int j = 0; j < 8; j++) bb[j] = Bs[kk][tx + 16 * j];
            #pragma unroll
            for (int i = 0; i < 8; i++)
                #pragma unroll
                for (int j = 0; j < 8; j++) acc[i][j] += a[i] * bb[j];
        }
        __syncthreads();
    }
    #pragma unroll
    for (int i = 0; i < 8; i++) {
        int r = row0 + ty + 16 * i;
        #pragma unroll
        for (int j = 0; j < 8; j++) {
            int c = col0 + tx + 16 * j;
            if (c < N) C[(size_t)r * ldc + c] = acc[i][j] + bias[c];
        }
    }
}

// ---------------- host --------------------------------------------------------
extern "C" void kernel_launch(void* const* d_in, const int* in_sizes, int n_in,
                              void* d_out, int out_size) {
    const float* methy  = (const float*)d_in[0];
    const int*   chromo = (const int*)  d_in[1];
    const int*   pos    = (const int*)  d_in[2];
    const float* mtab   = (const float*)d_in[3];
    const float* ctab   = (const float*)d_in[4];
    const float* ptab   = (const float*)d_in[5];
    const float* ln1g   = (const float*)d_in[6];
    const float* ln1b   = (const float*)d_in[7];
    const float* ln2g   = (const float*)d_in[8];
    const float* ln2b   = (const float*)d_in[9];
    const float* Wq     = (const float*)d_in[10];
    const float* Wk     = (const float*)d_in[11];
    const float* Wv     = (const float*)d_in[12];
    const float* Wo     = (const float*)d_in[13];
    const float* bo     = (const float*)d_in[14];
    const float* W1     = (const float*)d_in[15];
    const float* b1     = (const float*)d_in[16];
    const float* W2     = (const float*)d_in[17];
    const float* b2     = (const float*)d_in[18];
    const float* proj   = (const float*)d_in[19];
    const float* nfg    = (const float*)d_in[20];
    const float* nfb    = (const float*)d_in[21];
    const float* Wout   = (const float*)d_in[22];
    const float* bout   = (const float*)d_in[23];
    float* out = (float*)d_out;

    float *px, *ph, *pq, *pk, *pv, *pqf, *pkf, *pksum, *pctx, *pdinv;
    unsigned* phmax; int* pbidx;
    cudaGetSymbolAddress((void**)&px,    g_x);
    cudaGetSymbolAddress((void**)&ph,    g_h);
    cudaGetSymbolAddress((void**)&pq,    g_q);
    cudaGetSymbolAddress((void**)&pk,    g_k);
    cudaGetSymbolAddress((void**)&pv,    g_v);
    cudaGetSymbolAddress((void**)&pqf,   g_qf);
    cudaGetSymbolAddress((void**)&pkf,   g_kf);
    cudaGetSymbolAddress((void**)&pksum, g_ksum);
    cudaGetSymbolAddress((void**)&pctx,  g_ctx);
    cudaGetSymbolAddress((void**)&pdinv, g_dinv);
    cudaGetSymbolAddress((void**)&phmax, g_hmax);
    cudaGetSymbolAddress((void**)&pbidx, g_bidx);

    __nv_bfloat16 *hh, *hl, *qh, *ql, *kh, *kl, *vh, *vl, *oh, *ol, *ffh, *ffl;
    __nv_bfloat16 *qfh, *qfl, *ctTh, *ctTl, *pch, *pcl;
    __nv_bfloat16 *wqh, *wql, *wkh, *wkl, *wvh, *wvl, *woh, *wol, *w1h, *w1l, *w2h, *w2l;
    cudaGetSymbolAddress((void**)&hh,  g_hh);  cudaGetSymbolAddress((void**)&hl,  g_hl);
    cudaGetSymbolAddress((void**)&qh,  g_qh);  cudaGetSymbolAddress((void**)&ql,  g_ql);
    cudaGetSymbolAddress((void**)&kh,  g_kh);  cudaGetSymbolAddress((void**)&kl,  g_kl);
    cudaGetSymbolAddress((void**)&vh,  g_vh);  cudaGetSymbolAddress((void**)&vl,  g_vl);
    cudaGetSymbolAddress((void**)&oh,  g_oh);  cudaGetSymbolAddress((void**)&ol,  g_ol);
    cudaGetSymbolAddress((void**)&ffh, g_ffh); cudaGetSymbolAddress((void**)&ffl, g_ffl);
    cudaGetSymbolAddress((void**)&qfh, g_qfh); cudaGetSymbolAddress((void**)&qfl, g_qfl);
    cudaGetSymbolAddress((void**)&ctTh, g_ctTh); cudaGetSymbolAddress((void**)&ctTl, g_ctTl);
    cudaGetSymbolAddress((void**)&pch, g_pch); cudaGetSymbolAddress((void**)&pcl, g_pcl);
    cudaGetSymbolAddress((void**)&wqh, g_wqh); cudaGetSymbolAddress((void**)&wql, g_wql);
    cudaGetSymbolAddress((void**)&wkh, g_wkh); cudaGetSymbolAddress((void**)&wkl, g_wkl);
    cudaGetSymbolAddress((void**)&wvh, g_wvh); cudaGetSymbolAddress((void**)&wvl, g_wvl);
    cudaGetSymbolAddress((void**)&woh, g_woh); cudaGetSymbolAddress((void**)&wol, g_wol);
    cudaGetSymbolAddress((void**)&w1h, g_w1h); cudaGetSymbolAddress((void**)&w1l, g_w1l);
    cudaGetSymbolAddress((void**)&w2h, g_w2h); cudaGetSymbolAddress((void**)&w2l, g_w2l);

    // one-time-per-launch weight transposes + splits
    dim3 tb(32, 8);
    tconv_kernel<<<dim3(24, 24, 6), tb>>>(Wq, DIM, (size_t)DIM * DIM, wqh, wql, DIM, (size_t)DIM * DIM);
    tconv_kernel<<<dim3(24, 24, 6), tb>>>(Wk, DIM, (size_t)DIM * DIM, wkh, wkl, DIM, (size_t)DIM * DIM);
    tconv_kernel<<<dim3(24, 24, 6), tb>>>(Wv, DIM, (size_t)DIM * DIM, wvh, wvl, DIM, (size_t)DIM * DIM);
    tconv_kernel<<<dim3(24, 24, 6), tb>>>(Wo, DIM, (size_t)DIM * DIM, woh, wol, DIM, (size_t)DIM * DIM);
    tconv_kernel<<<dim3(96, 24, 6), tb>>>(W1, FFD, (size_t)DIM * FFD, w1h, w1l, DIM, (size_t)DIM * FFD);
    tconv_kernel<<<dim3(24, 96, 6), tb>>>(W2, DIM, (size_t)DIM * FFD, w2h, w2l, FFD, (size_t)DIM * FFD);
    projc_kernel<<<DEPTH * MFEAT * DH / 256, 256>>>(proj, pch, pcl);

    bucket_kernel<<<16, 256>>>(methy, pbidx);
    embed_kernel<<<NTOK, 256>>>(pbidx, pos, chromo, mtab, ptab, ctab, px);

    for (int l = 0; l < DEPTH; l++) {
        size_t wo = (size_t)l * DIM * DIM;
        size_t w12 = (size_t)l * DIM * FFD;

        ln_kernel<<<NTOK, 256>>>(px, ln1g + l * DIM, ln1b + l * DIM, ph, hh, hl);
        hm_qkv_k<<<dim3(6, 32, 3), 256>>>(hh, hl,
            wqh + wo, wql + wo, wkh + wo, wkl + wo, wvh + wo, wvl + wo,
            pq, pk, pv, qh, ql, kh, kl, vh, vl);

        cudaMemsetAsync(phmax, 0, HEADS * sizeof(unsigned));
        cudaMemsetAsync(pksum, 0, HEADS * MFEAT * sizeof(float));
        cudaMemsetAsync(pctx,  0, HEADS * MFEAT * DH * sizeof(float));

        hm_xd_k<<<dim3(2, 32, 24), 256>>>(qh, ql, kh, kl,
            pch + (size_t)l * MFEAT * DH, pcl + (size_t)l * MFEAT * DH, pqf, pkf);
        q_post_kernel<<<HEADS * NTOK / 8, 256>>>(pq, pqf, qfh, qfl);
        k_max_kernel<<<dim3(32, HEADS), 256>>>(pkf, phmax);
        k_post_kernel<<<HEADS * NTOK / 8, 256>>>(pk, pkf, phmax, methy);
        ksum_kernel<<<dim3(16, HEADS), 256>>>(pkf, pksum);
        ctx_kernel<<<dim3(32, HEADS), 256>>>(pkf, pv, pctx);
        dinv_kernel<<<HEADS * NTOK / 8, 256>>>(pqf, pksum, pdinv);
        ctxT_kernel<<<HEADS, 256>>>(pctx, ctTh, ctTl);
        hm_o_k<<<dim3(1, 32, HEADS), 256>>>(qfh, qfl, ctTh, ctTl, pdinv, oh, ol);

        hm_plain_k<3><<<dim3(6, 32), 256>>>(oh, ol, DIM, woh + wo, wol + wo, DIM,
            bo + l * DIM, px, px, nullptr, nullptr, DIM, DIM);
        ln_kernel<<<NTOK, 256>>>(px, ln2g + l * DIM, ln2b + l * DIM, ph, hh, hl);
        hm_plain_k<2><<<dim3(24, 32), 256>>>(hh, hl, DIM, w1h + w12, w1l + w12, DIM,
            b1 + l * FFD, nullptr, nullptr, ffh, ffl, FFD, DIM);
        hm_plain_k<3><<<dim3(6, 32), 256>>>(ffh, ffl, FFD, w2h + w12, w2l + w12, FFD,
            b2 + l * DIM, px, px, nullptr, nullptr, DIM, FFD);
    }

    ln_kernel<<<NTOK, 256>>>(px, nfg, nfb, ph, hh, hl);
    sgemm_guard_k<<<dim3(1, 32), 256>>>(ph, DIM, Wout, NOUT, bout, out, NOUT, NOUT, DIM);
}

// round 11
// speedup vs baseline: 1.7721x; 1.0291x over previous
#include <cuda_runtime.h>
#include <cuda_bf16.h>
#include <math.h>
#include <stdint.h>

#define NTOK  4096
#define DIM   768
#define DEPTH 6
#define HEADS 12
#define DH    64
#define FFD   3072
#define MFEAT 256
#define NOUT  102

// ---------------- fp32 scratch ----------------------------------------------
__device__ float g_x  [NTOK*DIM];
__device__ float g_h  [NTOK*DIM];
__device__ float g_q  [NTOK*DIM];
__device__ float g_k  [NTOK*DIM];
__device__ float g_v  [NTOK*DIM];
__device__ float g_qf [HEADS*NTOK*MFEAT];
__device__ float g_kf [HEADS*NTOK*MFEAT];
__device__ unsigned g_hmax[HEADS];
__device__ float g_ksum[HEADS*MFEAT];
__device__ float g_ctx [HEADS*MFEAT*DH];
__device__ float g_dinv[HEADS*NTOK];
__device__ int   g_bidx[NTOK];

// ---------------- bf16 hi/lo scratch -----------------------------------------
__device__ __nv_bfloat16 g_hh [NTOK*DIM],  g_hl [NTOK*DIM];
__device__ __nv_bfloat16 g_qh [NTOK*DIM],  g_ql [NTOK*DIM];
__device__ __nv_bfloat16 g_kh [NTOK*DIM],  g_kl [NTOK*DIM];
__device__ __nv_bfloat16 g_vh [NTOK*DIM],  g_vl [NTOK*DIM];
__device__ __nv_bfloat16 g_oh [NTOK*DIM],  g_ol [NTOK*DIM];
__device__ __nv_bfloat16 g_ffh[NTOK*FFD],  g_ffl[NTOK*FFD];
__device__ __nv_bfloat16 g_qfh[HEADS*NTOK*MFEAT], g_qfl[HEADS*NTOK*MFEAT];
__device__ __nv_bfloat16 g_ctTh[HEADS*DH*MFEAT],  g_ctTl[HEADS*DH*MFEAT];
__device__ __nv_bfloat16 g_pch[DEPTH*MFEAT*DH],   g_pcl[DEPTH*MFEAT*DH];
__device__ __nv_bfloat16 g_wqh[DEPTH*DIM*DIM], g_wql[DEPTH*DIM*DIM];
__device__ __nv_bfloat16 g_wkh[DEPTH*DIM*DIM], g_wkl[DEPTH*DIM*DIM];
__device__ __nv_bfloat16 g_wvh[DEPTH*DIM*DIM], g_wvl[DEPTH*DIM*DIM];
__device__ __nv_bfloat16 g_woh[DEPTH*DIM*DIM], g_wol[DEPTH*DIM*DIM];
__device__ __nv_bfloat16 g_w1h[DEPTH*FFD*DIM], g_w1l[DEPTH*FFD*DIM];
__device__ __nv_bfloat16 g_w2h[DEPTH*DIM*FFD], g_w2l[DEPTH*DIM*FFD];

// ---------------- helpers ----------------------------------------------------
__device__ __forceinline__ unsigned f2o(float f) {
    unsigned u = __float_as_uint(f);
    return (u & 0x80000000u) ? ~u : (u | 0x80000000u);
}
__device__ __forceinline__ float o2f(unsigned u) {
    return __uint_as_float((u & 0x80000000u) ? (u & 0x7fffffffu) : ~u);
}
__device__ __forceinline__ float gelu_tanh(float x) {
    float x3 = x * x * x;
    return 0.5f * x * (1.0f + tanhf(0.7978845608028654f * (x + 0.044715f * x3)));
}
__device__ __forceinline__ uint32_t smem_u32(const void* p) {
    uint32_t a;
    asm("{ .reg .u64 t; cvta.to.shared.u64 t, %1; cvt.u32.u64 %0, t; }" : "=r"(a) : "l"(p));
    return a;
}
__device__ __forceinline__ void split_store(float v, __nv_bfloat16* oh,
                                            __nv_bfloat16* ol, size_t i) {
    __nv_bfloat16 h = __float2bfloat16(v);
    oh[i] = h;
    ol[i] = __float2bfloat16(v - __bfloat162float(h));
}
__device__ __forceinline__ void cp16(void* dst_smem, const void* src) {
    uint32_t d = smem_u32(dst_smem);
    asm volatile("cp.async.cg.shared.global [%0], [%1], 16;" :: "r"(d), "l"(src));
}
__device__ __forceinline__ void cp_commit() {
    asm volatile("cp.async.commit_group;" ::: "memory");
}

// ldmatrix x4 for A tile (m16 x k16) from padded smem (row stride 40 bf16)
__device__ __forceinline__ void ldmA(uint32_t f[4], const __nv_bfloat16* base, int lane) {
    const __nv_bfloat16* p = base + (lane & 15) * 40 + ((lane >> 4) << 3);
    uint32_t a = smem_u32(p);
    asm volatile("ldmatrix.sync.aligned.m8n8.x4.shared.b16 {%0,%1,%2,%3}, [%4];"
                 : "=r"(f[0]), "=r"(f[1]), "=r"(f[2]), "=r"(f[3]) : "r"(a));
}
// ldmatrix x4 for two B tiles (n 0..15 of a 16 x k16 region), B smem is [n][k]
__device__ __forceinline__ void ldmB(uint32_t f0[2], uint32_t f1[2],
                                     const __nv_bfloat16* base, int lane) {
    int r = (lane & 7) + ((lane >> 4) << 3);
    int c = ((lane >> 3) & 1) << 3;
    const __nv_bfloat16* p = base + r * 40 + c;
    uint32_t a = smem_u32(p);
    asm volatile("ldmatrix.sync.aligned.m8n8.x4.shared.b16 {%0,%1,%2,%3}, [%4];"
                 : "=r"(f0[0]), "=r"(f0[1]), "=r"(f1[0]), "=r"(f1[1]) : "r"(a));
}
__device__ __forceinline__ void mma16816(float c[4], const uint32_t a[4], const uint32_t b[2]) {
    asm volatile(
        "mma.sync.aligned.m16n8k16.row.col.f32.bf16.bf16.f32 "
        "{%0,%1,%2,%3}, {%4,%5,%6,%7}, {%8,%9}, {%0,%1,%2,%3};"
        : "+f"(c[0]), "+f"(c[1]), "+f"(c[2]), "+f"(c[3])
        : "r"(a[0]), "r"(a[1]), "r"(a[2]), "r"(a[3]), "r"(b[0]), "r"(b[1]));
}

// ---------------- small SIMT kernels -----------------------------------------
__global__ void bucket_kernel(const float* __restrict__ methy, int* __restrict__ idx) {
    int n = blockIdx.x * 256 + threadIdx.x;
    if (n >= NTOK) return;
    float v = methy[n];
    int c = 0;
    c += (v > -2.0f);
    c += (v > -1.0f);
    #pragma unroll
    for (int k = 0; k < 100; k++) c += (v > (float)k * 0.01f);
    idx[n] = c;
}

__global__ void embed_kernel(const int* __restrict__ idx, const int* __restrict__ pos,
                             const int* __restrict__ chromo,
                             const float* __restrict__ mtab, const float* __restrict__ ptab,
                             const float* __restrict__ ctab, float* __restrict__ x) {
    int n = blockIdx.x, t = threadIdx.x;
    int mi = idx[n], pi = pos[n], ci = chromo[n];
    #pragma unroll
    for (int i = 0; i < 3; i++) {
        int d = t + i * 256;
        x[(size_t)n * DIM + d] = mtab[(size_t)mi * DIM + d]
                               + ptab[(size_t)pi * DIM + d]
                               + ctab[(size_t)ci * DIM + d];
    }
}

__global__ void ln_kernel(const float* __restrict__ x, const float* __restrict__ g,
                          const float* __restrict__ b, float* __restrict__ out,
                          __nv_bfloat16* __restrict__ oh, __nv_bfloat16* __restrict__ ol) {
    __shared__ float red[256];
    int n = blockIdx.x, t = threadIdx.x;
    const float* xr = x + (size_t)n * DIM;
    float v0 = xr[t], v1 = xr[t + 256], v2 = xr[t + 512];
    red[t] = v0 + v1 + v2;
    __syncthreads();
    for (int s = 128; s; s >>= 1) { if (t < s) red[t] += red[t + s]; __syncthreads(); }
    float mu = red[0] * (1.0f / 768.0f);
    __syncthreads();
    float d0 = v0 - mu, d1 = v1 - mu, d2 = v2 - mu;
    red[t] = d0 * d0 + d1 * d1 + d2 * d2;
    __syncthreads();
    for (int s = 128; s; s >>= 1) { if (t < s) red[t] += red[t + s]; __syncthreads(); }
    float rstd = rsqrtf(red[0] * (1.0f / 768.0f) + 1e-5f);
    size_t base = (size_t)n * DIM;
    float r0 = d0 * rstd * g[t]       + b[t];
    float r1 = d1 * rstd * g[t + 256] + b[t + 256];
    float r2 = d2 * rstd * g[t + 512] + b[t + 512];
    out[base + t] = r0; out[base + t + 256] = r1; out[base + t + 512] = r2;
    split_store(r0, oh, ol, base + t);
    split_store(r1, oh, ol, base + t + 256);
    split_store(r2, oh, ol, base + t + 512);
}

__global__ void q_post_kernel(const float* __restrict__ q, float* __restrict__ qf,
                              __nv_bfloat16* __restrict__ qh, __nv_bfloat16* __restrict__ ql) {
    int gw = (blockIdx.x * 256 + threadIdx.x) >> 5;
    int lane = threadIdx.x & 31;
    int h = gw >> 12, n = gw & 4095;
    float* row = qf + (size_t)gw * MFEAT;
    float v[8];
    float mx = -3e38f;
    #pragma unroll
    for (int i = 0; i < 8; i++) { v[i] = row[lane + 32 * i]; mx = fmaxf(mx, v[i]); }
    #pragma unroll
    for (int off = 16; off; off >>= 1) mx = fmaxf(mx, __shfl_xor_sync(0xffffffffu, mx, off));
    const float* qr = q + (size_t)n * DIM + h * DH;
    float a = qr[lane], b = qr[lane + 32];
    float ss = a * a + b * b;
    #pragma unroll
    for (int off = 16; off; off >>= 1) ss += __shfl_xor_sync(0xffffffffu, ss, off);
    float diag = ss * 0.0625f;
    #pragma unroll
    for (int i = 0; i < 8; i++) {
        float r = 0.0625f * (expf(v[i] - diag - mx) + 1e-4f);
        row[lane + 32 * i] = r;
        split_store(r, qh, ql, (size_t)gw * MFEAT + lane + 32 * i);
    }
}

__global__ void k_max_kernel(const float* __restrict__ kf, unsigned* __restrict__ hmax) {
    __shared__ float red[256];
    int h = blockIdx.y, t = threadIdx.x;
    int n0 = blockIdx.x * 128;
    float m = -3e38f;
    for (int n = n0; n < n0 + 128; n++)
        m = fmaxf(m, kf[((size_t)((h << 12) + n)) * MFEAT + t]);
    red[t] = m;
    __syncthreads();
    for (int s = 128; s; s >>= 1) { if (t < s) red[t] = fmaxf(red[t], red[t + s]); __syncthreads(); }
    if (t == 0) atomicMax(hmax + h, f2o(red[0]));
}

__global__ void k_post_kernel(const float* __restrict__ k, float* __restrict__ kf,
                              const unsigned* __restrict__ hmax,
                              const float* __restrict__ methy) {
    int gw = (blockIdx.x * 256 + threadIdx.x) >> 5;
    int lane = threadIdx.x & 31;
    int h = gw >> 12, n = gw & 4095;
    float* row = kf + (size_t)gw * MFEAT;
    float mx = o2f(hmax[h]);
    const float* kr = k + (size_t)n * DIM + h * DH;
    float a = kr[lane], b = kr[lane + 32];
    float ss = a * a + b * b;
    #pragma unroll
    for (int off = 16; off; off >>= 1) ss += __shfl_xor_sync(0xffffffffu, ss, off);
    float diag = ss * 0.0625f;
    float msk = (methy[n] != 0.0f) ? 1.0f : 0.0f;
    #pragma unroll
    for (int i = 0; i < 8; i++) {
        float v = row[lane + 32 * i];
        row[lane + 32 * i] = msk * 0.0625f * (expf(v - diag - mx) + 1e-4f);
    }
}

__global__ void ksum_kernel(const float* __restrict__ kf, float* __restrict__ ksum) {
    int h = blockIdx.y, m = threadIdx.x;
    int n0 = blockIdx.x * 256;
    float s = 0.0f;
    for (int n = n0; n < n0 + 256; n++)
        s += kf[((size_t)((h << 12) + n)) * MFEAT + m];
    atomicAdd(&ksum[h * MFEAT + m], s);
}

__global__ void ctx_kernel(const float* __restrict__ kf, const float* __restrict__ v,
                           float* __restrict__ ctx) {
    int h = blockIdx.y;
    int n0 = blockIdx.x * 128;
    int t = threadIdx.x;
    __shared__ float sv[4][64];
    float4 acc4[16];
    #pragma unroll
    for (int i = 0; i < 16; i++) acc4[i] = make_float4(0.f, 0.f, 0.f, 0.f);
    int rr = t >> 6, cc = t & 63;
    for (int n = n0; n < n0 + 128; n += 4) {
        sv[rr][cc] = v[(size_t)(n + rr) * DIM + h * DH + cc];
        __syncthreads();
        #pragma unroll
        for (int r = 0; r < 4; r++) {
            float kv = kf[((size_t)((h << 12) + n + r)) * MFEAT + t];
            const float4* vp = (const float4*)sv[r];
            #pragma unroll
            for (int d4 = 0; d4 < 16; d4++) {
                float4 vv = vp[d4];
                acc4[d4].x += kv * vv.x; acc4[d4].y += kv * vv.y;
                acc4[d4].z += kv * vv.z; acc4[d4].w += kv * vv.w;
            }
        }
        __syncthreads();
    }
    float* cp = ctx + ((size_t)h * MFEAT + t) * DH;
    #pragma unroll
    for (int d4 = 0; d4 < 16; d4++) {
        atomicAdd(&cp[d4 * 4 + 0], acc4[d4].x);
        atomicAdd(&cp[d4 * 4 + 1], acc4[d4].y);
        atomicAdd(&cp[d4 * 4 + 2], acc4[d4].z);
        atomicAdd(&cp[d4 * 4 + 3], acc4[d4].w);
    }
}

__global__ void dinv_kernel(const float* __restrict__ qf, const float* __restrict__ ksum,
                            float* __restrict__ dinv) {
    int w = (blockIdx.x * blockDim.x + threadIdx.x) >> 5;
    int lane = threadIdx.x & 31;
    if (w >= HEADS * NTOK) return;
    int h = w >> 12;
    const float* qr = qf + (size_t)w * MFEAT;
    const float* ks = ksum + h * MFEAT;
    float s = 0.0f;
    #pragma unroll
    for (int m = lane; m < MFEAT; m += 32) s += qr[m] * ks[m];
    #pragma unroll
    for (int off = 16; off; off >>= 1) s += __shfl_xor_sync(0xffffffffu, s, off);
    if (lane == 0) dinv[w] = 1.0f / s;
}

__global__ void ctxT_kernel(const float* __restrict__ ctx,
                            __nv_bfloat16* __restrict__ oh, __nv_bfloat16* __restrict__ ol) {
    int h = blockIdx.x;
    for (int i = threadIdx.x; i < MFEAT * DH; i += 256) {
        int m = i >> 6, d = i & 63;
        float v = ctx[(size_t)h * MFEAT * DH + i];
        split_store(v, oh, ol, ((size_t)h * DH + d) * MFEAT + m);
    }
}

__global__ void tconv_kernel(const float* __restrict__ in, int ldi, size_t inz,
                             __nv_bfloat16* __restrict__ oh, __nv_bfloat16* __restrict__ ol,
                             int ldo, size_t outz) {
    __shared__ float ts[32][33];
    const float* ip = in + (size_t)blockIdx.z * inz;
    int r0 = blockIdx.y * 32, c0 = blockIdx.x * 32;
    int tx = threadIdx.x, ty = threadIdx.y;
    #pragma unroll
    for (int j = 0; j < 4; j++)
        ts[ty + j * 8][tx] = ip[(size_t)(r0 + ty + j * 8) * ldi + c0 + tx];
    __syncthreads();
    size_t ob = (size_t)blockIdx.z * outz;
    #pragma unroll
    for (int j = 0; j < 4; j++)
        split_store(ts[tx][ty + j * 8], oh, ol, ob + (size_t)(c0 + ty + j * 8) * ldo + r0 + tx);
}

__global__ void projc_kernel(const float* __restrict__ in,
                             __nv_bfloat16* __restrict__ oh, __nv_bfloat16* __restrict__ ol) {
    size_t i = (size_t)blockIdx.x * 256 + threadIdx.x;
    split_store(0.35355339059327373f * in[i], oh, ol, i);
}

// ---------------- HMMA GEMM core (mma.sync bf16, 3-term split) ---------------
// D(128 x TN) = A(128 x K) @ B(TN x K)^T, cp.async 2-stage pipeline
// EPI: 0=fp32 C | 2=bias+gelu->splits | 3=bias+res->fp32 | 4=fp32+splits | 6=scale[r]->splits
template<int EPI>
__device__ __forceinline__ void epi2(int r, int c, float v0, float v1,
                                     const float* __restrict__ bias, const float* __restrict__ res,
                                     float* __restrict__ C, __nv_bfloat16* __restrict__ Ch,
                                     __nv_bfloat16* __restrict__ Cl, int ldc,
                                     const float* __restrict__ scale) {
    if (EPI == 2 || EPI == 3) { v0 += bias[c]; v1 += bias[c + 1]; }
    if (EPI == 2) { v0 = gelu_tanh(v0); v1 = gelu_tanh(v1); }
    if (EPI == 3) {
        float2 rr = *(const float2*)(res + (size_t)r * ldc + c);
        v0 += rr.x; v1 += rr.y;
    }
    if (EPI == 6) { float s = scale[r]; v0 *= s; v1 *= s; }
    if (EPI == 0 || EPI == 3 || EPI == 4)
        *(float2*)(C + (size_t)r * ldc + c) = make_float2(v0, v1);
    if (EPI == 2 || EPI == 4 || EPI == 6) {
        __nv_bfloat16 h0 = __float2bfloat16(v0), h1 = __float2bfloat16(v1);
        __nv_bfloat16 l0 = __float2bfloat16(v0 - __bfloat162float(h0));
        __nv_bfloat16 l1 = __float2bfloat16(v1 - __bfloat162float(h1));
        __nv_bfloat162 hh = __halves2bfloat162(h0, h1);
        __nv_bfloat162 ll = __halves2bfloat162(l0, l1);
        *(__nv_bfloat162*)(Ch + (size_t)r * ldc + c) = hh;
        *(__nv_bfloat162*)(Cl + (size_t)r * ldc + c) = ll;
    }
}

template<int EPI, int TN>
__device__ void hmma_core(const __nv_bfloat16* __restrict__ Ah, const __nv_bfloat16* __restrict__ Al,
                          int lda,
                          const __nv_bfloat16* __restrict__ Bh, const __nv_bfloat16* __restrict__ Bl,
                          int ldb,
                          const float* __restrict__ bias, const float* __restrict__ res,
                          float* __restrict__ C, __nv_bfloat16* __restrict__ Ch,
                          __nv_bfloat16* __restrict__ Cl, int ldc,
                          const float* __restrict__ scale,
                          int K, int row0, int col0)
{
    extern __shared__ __nv_bfloat16 smem[];
    const int AS = 128 * 40;            // elems per A matrix (padded rows)
    const int BS = TN * 40;
    const int STG = 2 * AS + 2 * BS;    // per stage: Ahi, Alo, Bhi, Blo

    const int MT = (TN == 128) ? 4 : 2;
    int tid = threadIdx.x, w = tid >> 5, lane = tid & 31;
    int wm0, wn0;
    if (TN == 128) { wm0 = (w >> 2) * 64; wn0 = (w & 3) * 32; }
    else           { wm0 = (w >> 1) * 32; wn0 = (w & 1) * 32; }

    float acc[4][4][4];
    #pragma unroll
    for (int i = 0; i < 4; i++)
        #pragma unroll
        for (int j = 0; j < 4; j++)
            #pragma unroll
            for (int e = 0; e < 4; e++) acc[i][j][e] = 0.0f;

    int nch = K >> 5;

    // prefetch chunk c into stage s
    auto prefetch = [&](int c, int s) {
        int k0 = c << 5;
        __nv_bfloat16* sAh = smem + s * STG;
        __nv_bfloat16* sAl = sAh + AS;
        __nv_bfloat16* sBh = sAh + 2 * AS;
        __nv_bfloat16* sBl = sBh + BS;
        for (int i = tid; i < 128 * 4; i += 256) {
            int r = i >> 2, kp = (i & 3) << 3;
            size_t gi = (size_t)(row0 + r) * lda + k0 + kp;
            cp16(sAh + r * 40 + kp, Ah + gi);
            cp16(sAl + r * 40 + kp, Al + gi);
        }
        for (int i = tid; i < TN * 4; i += 256) {
            int r = i >> 2, kp = (i & 3) << 3;
            size_t gi = (size_t)(col0 + r) * ldb + k0 + kp;
            cp16(sBh + r * 40 + kp, Bh + gi);
            cp16(sBl + r * 40 + kp, Bl + gi);
        }
        cp_commit();
    };

    prefetch(0, 0);
    for (int c = 0; c < nch; c++) {
        if (c + 1 < nch) {
            prefetch(c + 1, (c + 1) & 1);
            asm volatile("cp.async.wait_group 1;" ::: "memory");
        } else {
            asm volatile("cp.async.wait_group 0;" ::: "memory");
        }
        __syncthreads();

        __nv_bfloat16* cAh = smem + (c & 1) * STG;
        __nv_bfloat16* cAl = cAh + AS;
        __nv_bfloat16* cBh = cAh + 2 * AS;
        __nv_bfloat16* cBl = cBh + BS;

        #pragma unroll
        for (int kk = 0; kk < 32; kk += 16) {
            uint32_t bh[4][2], bl[4][2];
            ldmB(bh[0], bh[1], cBh + wn0 * 40 + kk, lane);
            ldmB(bh[2], bh[3], cBh + (wn0 + 16) * 40 + kk, lane);
            ldmB(bl[0], bl[1], cBl + wn0 * 40 + kk, lane);
            ldmB(bl[2], bl[3], cBl + (wn0 + 16) * 40 + kk, lane);
            #pragma unroll
            for (int mt = 0; mt < MT; mt++) {
                uint32_t ah[4], al[4];
                ldmA(ah, cAh + (wm0 + mt * 16) * 40 + kk, lane);
                ldmA(al, cAl + (wm0 + mt * 16) * 40 + kk, lane);
                #pragma unroll
                for (int nt = 0; nt < 4; nt++) {
                    mma16816(acc[mt][nt], ah, bh[nt]);
                    mma16816(acc[mt][nt], ah, bl[nt]);
                    mma16816(acc[mt][nt], al, bh[nt]);
                }
            }
        }
        __syncthreads();
    }

    #pragma unroll
    for (int mt = 0; mt < MT; mt++) {
        #pragma unroll
        for (int nt = 0; nt < 4; nt++) {
            int r = row0 + wm0 + mt * 16 + (lane >> 2);
            int cc = col0 + wn0 + nt * 8 + ((lane & 3) << 1);
            epi2<EPI>(r,     cc, acc[mt][nt][0], acc[mt][nt][1], bias, res, C, Ch, Cl, ldc, scale);
            epi2<EPI>(r + 8, cc, acc[mt][nt][2], acc[mt][nt][3], bias, res, C, Ch, Cl, ldc, scale);
        }
    }
}

#define SMEM_128 (2 * (2 * 128 * 40 + 2 * 128 * 40) * 2)   // 81920 B
#define SMEM_64  (2 * (2 * 128 * 40 + 2 * 64 * 40) * 2)    // 61440 B

// ---------------- HMMA wrappers ----------------------------------------------
template<int EPI>
__global__ __launch_bounds__(256) void hm_plain_k(
    const __nv_bfloat16* Ah, const __nv_bfloat16* Al, int lda,
    const __nv_bfloat16* Bh, const __nv_bfloat16* Bl, int ldb,
    const float* bias, const float* res,
    float* C, __nv_bfloat16* Ch, __nv_bfloat16* Cl, int ldc, int K)
{
    hmma_core<EPI, 128>(Ah, Al, lda, Bh, Bl, ldb, bias, res, C, Ch, Cl, ldc,
                        nullptr, K, blockIdx.y * 128, blockIdx.x * 128);
}

__global__ __launch_bounds__(256) void hm_qkv_k(
    const __nv_bfloat16* Ah, const __nv_bfloat16* Al,
    const __nv_bfloat16* Wqh, const __nv_bfloat16* Wql,
    const __nv_bfloat16* Wkh, const __nv_bfloat16* Wkl,
    const __nv_bfloat16* Wvh, const __nv_bfloat16* Wvl,
    float* q, float* k, float* v,
    __nv_bfloat16* qh, __nv_bfloat16* ql, __nv_bfloat16* kh, __nv_bfloat16* kl,
    __nv_bfloat16* vh, __nv_bfloat16* vl)
{
    int z = blockIdx.z;
    const __nv_bfloat16* Bh = (z == 0) ? Wqh : (z == 1) ? Wkh : Wvh;
    const __nv_bfloat16* Bl = (z == 0) ? Wql : (z == 1) ? Wkl : Wvl;
    float* C = (z == 0) ? q : (z == 1) ? k : v;
    __nv_bfloat16* Ch = (z == 0) ? qh : (z == 1) ? kh : vh;
    __nv_bfloat16* Cl = (z == 0) ? ql : (z == 1) ? kl : vl;
    hmma_core<4, 128>(Ah, Al, DIM, Bh, Bl, DIM, nullptr, nullptr, C, Ch, Cl, DIM,
                      nullptr, DIM, blockIdx.y * 128, blockIdx.x * 128);
}

__global__ __launch_bounds__(256) void hm_xd_k(
    const __nv_bfloat16* qh, const __nv_bfloat16* ql,
    const __nv_bfloat16* kh, const __nv_bfloat16* kl,
    const __nv_bfloat16* prh, const __nv_bfloat16* prl,
    float* xq, float* xk)
{
    int z = blockIdx.z;
    int h = (z < 12) ? z : z - 12;
    const __nv_bfloat16* Ah = ((z < 12) ? qh : kh) + h * DH;
    const __nv_bfloat16* Al = ((z < 12) ? ql : kl) + h * DH;
    float* C = ((z < 12) ? xq : xk) + (size_t)h * NTOK * MFEAT;
    hmma_core<0, 128>(Ah, Al, DIM, prh, prl, DH, nullptr, nullptr, C, nullptr, nullptr, MFEAT,
                      nullptr, DH, blockIdx.y * 128, blockIdx.x * 128);
}

__global__ __launch_bounds__(256) void hm_o_k(
    const __nv_bfloat16* qfh, const __nv_bfloat16* qfl,
    const __nv_bfloat16* cth, const __nv_bfloat16* ctl,
    const float* dinv, __nv_bfloat16* oh, __nv_bfloat16* ol)
{
    int h = blockIdx.z;
    hmma_core<6, 64>(qfh + (size_t)h * NTOK * MFEAT, qfl + (size_t)h * NTOK * MFEAT, MFEAT,
                     cth + (size_t)h * DH * MFEAT, ctl + (size_t)h * DH * MFEAT, MFEAT,
                     nullptr, nullptr, nullptr, oh + h * DH, ol + h * DH, DIM,
                     dinv + (size_t)h * NTOK, MFEAT, blockIdx.y * 128, 0);
}

// ---------------- SIMT guard GEMM for tiny Wout -------------------------------
__global__ __launch_bounds__(256)
void sgemm_guard_k(const float* __restrict__ A, int lda, const float* __restrict__ B, int ldb,
                   const float* __restrict__ bias, float* __restrict__ C, int ldc,
                   int N, int K) {
    __shared__ float As[8][128];
    __shared__ float Bs[8][128];
    int tid = threadIdx.x;
    int row0 = blockIdx.y * 128, col0 = blockIdx.x * 128;
    int tx = tid & 15, ty = tid >> 4;
    int arow = tid >> 1, acol = (tid & 1) * 4;
    int brow = tid >> 5, bcol = (tid & 31) * 4;
    float acc[8][8];
    #pragma unroll
    for (int i = 0; i < 8; i++)
        #pragma unroll
        for (int j = 0; j < 8; j++) acc[i][j] = 0.0f;
    for (int k0 = 0; k0 < K; k0 += 8) {
        float4 av = *(const float4*)(A + (size_t)(row0 + arow) * lda + k0 + acol);
        As[acol + 0][arow] = av.x; As[acol + 1][arow] = av.y;
        As[acol + 2][arow] = av.z; As[acol + 3][arow] = av.w;
        #pragma unroll
        for (int j = 0; j < 4; j++) {
            int c = col0 + bcol + j;
            Bs[brow][bcol + j] = (c < N) ? B[(size_t)(k0 + brow) * ldb + c] : 0.0f;
        }
        __syncthreads();
        #pragma unroll
        for (int kk = 0; kk < 8; kk++) {
            float a[8], bb[8];
            #pragma unroll
            for (int i = 0; i < 8; i++) a[i] = As[kk][ty + 16 * i];
            #pragma unroll
            for (int j = 0; j < 8; j++) bb[j] = Bs[kk][tx + 16 * j];
            #pragma unroll
            for (int i = 0; i < 8; i++)
                #pragma unroll
                for (int j = 0; j < 8; j++) acc[i][j] += a[i] * bb[j];
        }
        __syncthreads();
    }
    #pragma unroll
    for (int i = 0; i < 8; i++) {
        int r = row0 + ty + 16 * i;
        #pragma unroll
        for (int j = 0; j < 8; j++) {
            int c = col0 + tx + 16 * j;
            if (c < N) C[(size_t)r * ldc + c] = acc[i][j] + bias[c];
        }
    }
}

// ---------------- host --------------------------------------------------------
extern "C" void kernel_launch(void* const* d_in, const int* in_sizes, int n_in,
                              void* d_out, int out_size) {
    const float* methy  = (const float*)d_in[0];
    const int*   chromo = (const int*)  d_in[1];
    const int*   pos    = (const int*)  d_in[2];
    const float* mtab   = (const float*)d_in[3];
    const float* ctab   = (const float*)d_in[4];
    const float* ptab   = (const float*)d_in[5];
    const float* ln1g   = (const float*)d_in[6];
    const float* ln1b   = (const float*)d_in[7];
    const float* ln2g   = (const float*)d_in[8];
    const float* ln2b   = (const float*)d_in[9];
    const float* Wq     = (const float*)d_in[10];
    const float* Wk     = (const float*)d_in[11];
    const float* Wv     = (const float*)d_in[12];
    const float* Wo     = (const float*)d_in[13];
    const float* bo     = (const float*)d_in[14];
    const float* W1     = (const float*)d_in[15];
    const float* b1     = (const float*)d_in[16];
    const float* W2     = (const float*)d_in[17];
    const float* b2     = (const float*)d_in[18];
    const float* proj   = (const float*)d_in[19];
    const float* nfg    = (const float*)d_in[20];
    const float* nfb    = (const float*)d_in[21];
    const float* Wout   = (const float*)d_in[22];
    const float* bout   = (const float*)d_in[23];
    float* out = (float*)d_out;

    static int smem_set = 0;
    if (!smem_set) {
        cudaFuncSetAttribute(hm_qkv_k,      cudaFuncAttributeMaxDynamicSharedMemorySize, SMEM_128);
        cudaFuncSetAttribute(hm_xd_k,       cudaFuncAttributeMaxDynamicSharedMemorySize, SMEM_128);
        cudaFuncSetAttribute(hm_o_k,        cudaFuncAttributeMaxDynamicSharedMemorySize, SMEM_64);
        cudaFuncSetAttribute(hm_plain_k<2>, cudaFuncAttributeMaxDynamicSharedMemorySize, SMEM_128);
        cudaFuncSetAttribute(hm_plain_k<3>, cudaFuncAttributeMaxDynamicSharedMemorySize, SMEM_128);
        smem_set = 1;
    }

    float *px, *ph, *pq, *pk, *pv, *pqf, *pkf, *pksum, *pctx, *pdinv;
    unsigned* phmax; int* pbidx;
    cudaGetSymbolAddress((void**)&px,    g_x);
    cudaGetSymbolAddress((void**)&ph,    g_h);
    cudaGetSymbolAddress((void**)&pq,    g_q);
    cudaGetSymbolAddress((void**)&pk,    g_k);
    cudaGetSymbolAddress((void**)&pv,    g_v);
    cudaGetSymbolAddress((void**)&pqf,   g_qf);
    cudaGetSymbolAddress((void**)&pkf,   g_kf);
    cudaGetSymbolAddress((void**)&pksum, g_ksum);
    cudaGetSymbolAddress((void**)&pctx,  g_ctx);
    cudaGetSymbolAddress((void**)&pdinv, g_dinv);
    cudaGetSymbolAddress((void**)&phmax, g_hmax);
    cudaGetSymbolAddress((void**)&pbidx, g_bidx);

    __nv_bfloat16 *hh, *hl, *qh, *ql, *kh, *kl, *vh, *vl, *oh, *ol, *ffh, *ffl;
    __nv_bfloat16 *qfh, *qfl, *ctTh, *ctTl, *pch, *pcl;
    __nv_bfloat16 *wqh, *wql, *wkh, *wkl, *wvh, *wvl, *woh, *wol, *w1h, *w1l, *w2h, *w2l;
    cudaGetSymbolAddress((void**)&hh,  g_hh);  cudaGetSymbolAddress((void**)&hl,  g_hl);
    cudaGetSymbolAddress((void**)&qh,  g_qh);  cudaGetSymbolAddress((void**)&ql,  g_ql);
    cudaGetSymbolAddress((void**)&kh,  g_kh);  cudaGetSymbolAddress((void**)&kl,  g_kl);
    cudaGetSymbolAddress((void**)&vh,  g_vh);  cudaGetSymbolAddress((void**)&vl,  g_vl);
    cudaGetSymbolAddress((void**)&oh,  g_oh);  cudaGetSymbolAddress((void**)&ol,  g_ol);
    cudaGetSymbolAddress((void**)&ffh, g_ffh); cudaGetSymbolAddress((void**)&ffl, g_ffl);
    cudaGetSymbolAddress((void**)&qfh, g_qfh); cudaGetSymbolAddress((void**)&qfl, g_qfl);
    cudaGetSymbolAddress((void**)&ctTh, g_ctTh); cudaGetSymbolAddress((void**)&ctTl, g_ctTl);
    cudaGetSymbolAddress((void**)&pch, g_pch); cudaGetSymbolAddress((void**)&pcl, g_pcl);
    cudaGetSymbolAddress((void**)&wqh, g_wqh); cudaGetSymbolAddress((void**)&wql, g_wql);
    cudaGetSymbolAddress((void**)&wkh, g_wkh); cudaGetSymbolAddress((void**)&wkl, g_wkl);
    cudaGetSymbolAddress((void**)&wvh, g_wvh); cudaGetSymbolAddress((void**)&wvl, g_wvl);
    cudaGetSymbolAddress((void**)&woh, g_woh); cudaGetSymbolAddress((void**)&wol, g_wol);
    cudaGetSymbolAddress((void**)&w1h, g_w1h); cudaGetSymbolAddress((void**)&w1l, g_w1l);
    cudaGetSymbolAddress((void**)&w2h, g_w2h); cudaGetSymbolAddress((void**)&w2l, g_w2l);

    // one-time-per-launch weight transposes + splits
    dim3 tb(32, 8);
    tconv_kernel<<<dim3(24, 24, 6), tb>>>(Wq, DIM, (size_t)DIM * DIM, wqh, wql, DIM, (size_t)DIM * DIM);
    tconv_kernel<<<dim3(24, 24, 6), tb>>>(Wk, DIM, (size_t)DIM * DIM, wkh, wkl, DIM, (size_t)DIM * DIM);
    tconv_kernel<<<dim3(24, 24, 6), tb>>>(Wv, DIM, (size_t)DIM * DIM, wvh, wvl, DIM, (size_t)DIM * DIM);
    tconv_kernel<<<dim3(24, 24, 6), tb>>>(Wo, DIM, (size_t)DIM * DIM, woh, wol, DIM, (size_t)DIM * DIM);
    tconv_kernel<<<dim3(96, 24, 6), tb>>>(W1, FFD, (size_t)DIM * FFD, w1h, w1l, DIM, (size_t)DIM * FFD);
    tconv_kernel<<<dim3(24, 96, 6), tb>>>(W2, DIM, (size_t)DIM * FFD, w2h, w2l, FFD, (size_t)DIM * FFD);
    projc_kernel<<<DEPTH * MFEAT * DH / 256, 256>>>(proj, pch, pcl);

    bucket_kernel<<<16, 256>>>(methy, pbidx);
    embed_kernel<<<NTOK, 256>>>(pbidx, pos, chromo, mtab, ptab, ctab, px);

    for (int l = 0; l < DEPTH; l++) {
        size_t wo = (size_t)l * DIM * DIM;
        size_t w12 = (size_t)l * DIM * FFD;

        ln_kernel<<<NTOK, 256>>>(px, ln1g + l * DIM, ln1b + l * DIM, ph, hh, hl);
        hm_qkv_k<<<dim3(6, 32, 3), 256, SMEM_128>>>(hh, hl,
            wqh + wo, wql + wo, wkh + wo, wkl + wo, wvh + wo, wvl + wo,
            pq, pk, pv, qh, ql, kh, kl, vh, vl);

        cudaMemsetAsync(phmax, 0, HEADS * sizeof(unsigned));
        cudaMemsetAsync(pksum, 0, HEADS * MFEAT * sizeof(float));
        cudaMemsetAsync(pctx,  0, HEADS * MFEAT * DH * sizeof(float));

        hm_xd_k<<<dim3(2, 32, 24), 256, SMEM_128>>>(qh, ql, kh, kl,
            pch + (size_t)l * MFEAT * DH, pcl + (size_t)l * MFEAT * DH, pqf, pkf);
        q_post_kernel<<<HEADS * NTOK / 8, 256>>>(pq, pqf, qfh, qfl);
        k_max_kernel<<<dim3(32, HEADS), 256>>>(pkf, phmax);
        k_post_kernel<<<HEADS * NTOK / 8, 256>>>(pk, pkf, phmax, methy);
        ksum_kernel<<<dim3(16, HEADS), 256>>>(pkf, pksum);
        ctx_kernel<<<dim3(32, HEADS), 256>>>(pkf, pv, pctx);
        dinv_kernel<<<HEADS * NTOK / 8, 256>>>(pqf, pksum, pdinv);
        ctxT_kernel<<<HEADS, 256>>>(pctx, ctTh, ctTl);
        hm_o_k<<<dim3(1, 32, HEADS), 256, SMEM_64>>>(qfh, qfl, ctTh, ctTl, pdinv, oh, ol);

        hm_plain_k<3><<<dim3(6, 32), 256, SMEM_128>>>(oh, ol, DIM, woh + wo, wol + wo, DIM,
            bo + l * DIM, px, px, nullptr, nullptr, DIM, DIM);
        ln_kernel<<<NTOK, 256>>>(px, ln2g + l * DIM, ln2b + l * DIM, ph, hh, hl);
        hm_plain_k<2><<<dim3(24, 32), 256, SMEM_128>>>(hh, hl, DIM, w1h + w12, w1l + w12, DIM,
            b1 + l * FFD, nullptr, nullptr, ffh, ffl, FFD, DIM);
        hm_plain_k<3><<<dim3(6, 32), 256, SMEM_128>>>(ffh, ffl, FFD, w2h + w12, w2l + w12, FFD,
            b2 + l * DIM, px, px, nullptr, nullptr, DIM, FFD);
    }

    ln_kernel<<<NTOK, 256>>>(px, nfg, nfb, ph, hh, hl);
    sgemm_guard_k<<<dim3(1, 32), 256>>>(ph, DIM, Wout, NOUT, bout, out, NOUT, NOUT, DIM);
}

// round 13
// speedup vs baseline: 1.8413x; 1.0391x over previous
#include <cuda_runtime.h>
#include <cuda_bf16.h>
#include <math.h>
#include <stdint.h>

#define NTOK  4096
#define DIM   768
#define DEPTH 6
#define HEADS 12
#define DH    64
#define FFD   3072
#define MFEAT 256
#define NOUT  102

// ---------------- fp32 scratch ----------------------------------------------
__device__ float g_x  [NTOK*DIM];
__device__ float g_h  [NTOK*DIM];
__device__ float g_q  [NTOK*DIM];
__device__ float g_k  [NTOK*DIM];
__device__ float g_qf [HEADS*NTOK*MFEAT];
__device__ float g_kf [HEADS*NTOK*MFEAT];
__device__ unsigned g_hmax[HEADS];
__device__ float g_ksum[HEADS*MFEAT];
__device__ float g_ctx [HEADS*MFEAT*DH];
__device__ float g_dinv[HEADS*NTOK];
__device__ float g_v  [NTOK*DIM];

// ---------------- bf16 hi/lo scratch -----------------------------------------
__device__ __nv_bfloat16 g_hh [NTOK*DIM],  g_hl [NTOK*DIM];
__device__ __nv_bfloat16 g_qh [NTOK*DIM],  g_ql [NTOK*DIM];
__device__ __nv_bfloat16 g_kh [NTOK*DIM],  g_kl [NTOK*DIM];
__device__ __nv_bfloat16 g_vh [NTOK*DIM],  g_vl [NTOK*DIM];
__device__ __nv_bfloat16 g_oh [NTOK*DIM],  g_ol [NTOK*DIM];
__device__ __nv_bfloat16 g_ffh[NTOK*FFD],  g_ffl[NTOK*FFD];
__device__ __nv_bfloat16 g_qfh[HEADS*NTOK*MFEAT], g_qfl[HEADS*NTOK*MFEAT];
__device__ __nv_bfloat16 g_ctTh[HEADS*DH*MFEAT],  g_ctTl[HEADS*DH*MFEAT];
__device__ __nv_bfloat16 g_pch[DEPTH*MFEAT*DH],   g_pcl[DEPTH*MFEAT*DH];
__device__ __nv_bfloat16 g_wqh[DEPTH*DIM*DIM], g_wql[DEPTH*DIM*DIM];
__device__ __nv_bfloat16 g_wkh[DEPTH*DIM*DIM], g_wkl[DEPTH*DIM*DIM];
__device__ __nv_bfloat16 g_wvh[DEPTH*DIM*DIM], g_wvl[DEPTH*DIM*DIM];
__device__ __nv_bfloat16 g_woh[DEPTH*DIM*DIM], g_wol[DEPTH*DIM*DIM];
__device__ __nv_bfloat16 g_w1h[DEPTH*FFD*DIM], g_w1l[DEPTH*FFD*DIM];
__device__ __nv_bfloat16 g_w2h[DEPTH*DIM*FFD], g_w2l[DEPTH*DIM*FFD];

// ---------------- helpers ----------------------------------------------------
__device__ __forceinline__ unsigned f2o(float f) {
    unsigned u = __float_as_uint(f);
    return (u & 0x80000000u) ? ~u : (u | 0x80000000u);
}
__device__ __forceinline__ float o2f(unsigned u) {
    return __uint_as_float((u & 0x80000000u) ? (u & 0x7fffffffu) : ~u);
}
__device__ __forceinline__ float gelu_tanh(float x) {
    float x3 = x * x * x;
    return 0.5f * x * (1.0f + tanhf(0.7978845608028654f * (x + 0.044715f * x3)));
}
__device__ __forceinline__ uint32_t smem_u32(const void* p) {
    uint32_t a;
    asm("{ .reg .u64 t; cvta.to.shared.u64 t, %1; cvt.u32.u64 %0, t; }" : "=r"(a) : "l"(p));
    return a;
}
__device__ __forceinline__ void split_store(float v, __nv_bfloat16* oh,
                                            __nv_bfloat16* ol, size_t i) {
    __nv_bfloat16 h = __float2bfloat16(v);
    oh[i] = h;
    ol[i] = __float2bfloat16(v - __bfloat162float(h));
}
__device__ __forceinline__ void cp16(void* dst_smem, const void* src) {
    uint32_t d = smem_u32(dst_smem);
    asm volatile("cp.async.cg.shared.global [%0], [%1], 16;" :: "r"(d), "l"(src));
}
__device__ __forceinline__ void cp_commit() {
    asm volatile("cp.async.commit_group;" ::: "memory");
}

__device__ __forceinline__ void ldmA(uint32_t f[4], const __nv_bfloat16* base, int lane) {
    const __nv_bfloat16* p = base + (lane & 15) * 40 + ((lane >> 4) << 3);
    uint32_t a = smem_u32(p);
    asm volatile("ldmatrix.sync.aligned.m8n8.x4.shared.b16 {%0,%1,%2,%3}, [%4];"
                 : "=r"(f[0]), "=r"(f[1]), "=r"(f[2]), "=r"(f[3]) : "r"(a));
}
__device__ __forceinline__ void ldmB(uint32_t f0[2], uint32_t f1[2],
                                     const __nv_bfloat16* base, int lane) {
    int r = (lane & 7) + ((lane >> 4) << 3);
    int c = ((lane >> 3) & 1) << 3;
    const __nv_bfloat16* p = base + r * 40 + c;
    uint32_t a = smem_u32(p);
    asm volatile("ldmatrix.sync.aligned.m8n8.x4.shared.b16 {%0,%1,%2,%3}, [%4];"
                 : "=r"(f0[0]), "=r"(f0[1]), "=r"(f1[0]), "=r"(f1[1]) : "r"(a));
}
__device__ __forceinline__ void mma16816(float c[4], const uint32_t a[4], const uint32_t b[2]) {
    asm volatile(
        "mma.sync.aligned.m16n8k16.row.col.f32.bf16.bf16.f32 "
        "{%0,%1,%2,%3}, {%4,%5,%6,%7}, {%8,%9}, {%0,%1,%2,%3};"
        : "+f"(c[0]), "+f"(c[1]), "+f"(c[2]), "+f"(c[3])
        : "r"(a[0]), "r"(a[1]), "r"(a[2]), "r"(a[3]), "r"(b[0]), "r"(b[1]));
}

// ---------------- small SIMT kernels -----------------------------------------
// embedding with inlined bucketize
__global__ void embed_kernel(const float* __restrict__ methy, const int* __restrict__ pos,
                             const int* __restrict__ chromo,
                             const float* __restrict__ mtab, const float* __restrict__ ptab,
                             const float* __restrict__ ctab, float* __restrict__ x) {
    int n = blockIdx.x, t = threadIdx.x;
    float mv = methy[n];
    int mi = 0;
    mi += (mv > -2.0f);
    mi += (mv > -1.0f);
    #pragma unroll
    for (int k = 0; k < 100; k++) mi += (mv > (float)k * 0.01f);
    int pi = pos[n], ci = chromo[n];
    #pragma unroll
    for (int i = 0; i < 3; i++) {
        int d = t + i * 256;
        x[(size_t)n * DIM + d] = mtab[(size_t)mi * DIM + d]
                               + ptab[(size_t)pi * DIM + d]
                               + ctab[(size_t)ci * DIM + d];
    }
}

// LN: warp per row (24 elems/lane), 8 rows/block
__global__ void ln_kernel(const float* __restrict__ x, const float* __restrict__ g,
                          const float* __restrict__ b, float* __restrict__ out,
                          __nv_bfloat16* __restrict__ oh, __nv_bfloat16* __restrict__ ol) {
    int w = threadIdx.x >> 5, lane = threadIdx.x & 31;
    int n = blockIdx.x * 8 + w;
    const float* xr = x + (size_t)n * DIM;
    float v[24];
    float s = 0.0f;
    #pragma unroll
    for (int j = 0; j < 24; j++) { v[j] = xr[lane + 32 * j]; s += v[j]; }
    #pragma unroll
    for (int off = 16; off; off >>= 1) s += __shfl_xor_sync(0xffffffffu, s, off);
    float mu = s * (1.0f / 768.0f);
    float sq = 0.0f;
    #pragma unroll
    for (int j = 0; j < 24; j++) { float d = v[j] - mu; sq += d * d; }
    #pragma unroll
    for (int off = 16; off; off >>= 1) sq += __shfl_xor_sync(0xffffffffu, sq, off);
    float rstd = rsqrtf(sq * (1.0f / 768.0f) + 1e-5f);
    size_t base = (size_t)n * DIM;
    #pragma unroll
    for (int j = 0; j < 24; j++) {
        int d = lane + 32 * j;
        float r = (v[j] - mu) * rstd * g[d] + b[d];
        out[base + d] = r;
        split_store(r, oh, ol, base + d);
    }
}

// zero hmax + ksum + ctx in one launch
__global__ void zero_kernel(unsigned* __restrict__ hmax, float* __restrict__ ksum,
                            float* __restrict__ ctx) {
    int i = blockIdx.x * 256 + threadIdx.x;
    if (i < HEADS) hmax[i] = 0u;
    if (i < HEADS * MFEAT) ksum[i] = 0.0f;
    if (i < HEADS * MFEAT * DH) ctx[i] = 0.0f;
}

// k post: exp + mask, fused column-sum into ksum. warp = 16 rows. grid (32, HEADS)
__global__ void k_post_kernel(const float* __restrict__ k, float* __restrict__ kf,
                              const unsigned* __restrict__ hmax,
                              const float* __restrict__ methy, float* __restrict__ ksum) {
    __shared__ float sks[256];
    int h = blockIdx.y;
    int n0 = blockIdx.x * 128;
    int tid = threadIdx.x, w = tid >> 5, lane = tid & 31;
    sks[tid] = 0.0f;
    __syncthreads();
    float mx = o2f(hmax[h]);
    float csum[8];
    #pragma unroll
    for (int i = 0; i < 8; i++) csum[i] = 0.0f;
    for (int rr = 0; rr < 16; rr++) {
        int n = n0 + w * 16 + rr;
        float* row = kf + ((size_t)((h << 12) + n)) * MFEAT;
        const float* kr = k + (size_t)n * DIM + h * DH;
        float a = kr[lane], b = kr[lane + 32];
        float ss = a * a + b * b;
        #pragma unroll
        for (int off = 16; off; off >>= 1) ss += __shfl_xor_sync(0xffffffffu, ss, off);
        float diag = ss * 0.0625f;
        float msk = (methy[n] != 0.0f) ? 1.0f : 0.0f;
        #pragma unroll
        for (int i = 0; i < 8; i++) {
            float vv = row[lane + 32 * i];
            float r = msk * 0.0625f * (expf(vv - diag - mx) + 1e-4f);
            row[lane + 32 * i] = r;
            csum[i] += r;
        }
    }
    #pragma unroll
    for (int i = 0; i < 8; i++) atomicAdd(&sks[lane + 32 * i], csum[i]);
    __syncthreads();
    atomicAdd(&ksum[h * MFEAT + tid], sks[tid]);
}

// q post: rowmax+diag+exp -> splits, fused dinv (needs ksum ready). warp per row.
__global__ void q_post_kernel(const float* __restrict__ q, const float* __restrict__ qf,
                              __nv_bfloat16* __restrict__ qh, __nv_bfloat16* __restrict__ ql,
                              const float* __restrict__ ksum, float* __restrict__ dinv) {
    int gw = (blockIdx.x * 256 + threadIdx.x) >> 5;
    int lane = threadIdx.x & 31;
    int h = gw >> 12, n = gw & 4095;
    const float* row = qf + (size_t)gw * MFEAT;
    float v[8];
    float mx = -3e38f;
    #pragma unroll
    for (int i = 0; i < 8; i++) { v[i] = row[lane + 32 * i]; mx = fmaxf(mx, v[i]); }
    #pragma unroll
    for (int off = 16; off; off >>= 1) mx = fmaxf(mx, __shfl_xor_sync(0xffffffffu, mx, off));
    const float* qr = q + (size_t)n * DIM + h * DH;
    float a = qr[lane], b = qr[lane + 32];
    float ss = a * a + b * b;
    #pragma unroll
    for (int off = 16; off; off >>= 1) ss += __shfl_xor_sync(0xffffffffu, ss, off);
    float diag = ss * 0.0625f;
    const float* ks = ksum + h * MFEAT;
    float s = 0.0f;
    #pragma unroll
    for (int i = 0; i < 8; i++) {
        float r = 0.0625f * (expf(v[i] - diag - mx) + 1e-4f);
        split_store(r, qh, ql, (size_t)gw * MFEAT + lane + 32 * i);
        s += r * ks[lane + 32 * i];
    }
    #pragma unroll
    for (int off = 16; off; off >>= 1) s += __shfl_xor_sync(0xffffffffu, s, off);
    if (lane == 0) dinv[gw] = 1.0f / s;
}

__global__ void ctx_kernel(const float* __restrict__ kf, const float* __restrict__ v,
                           float* __restrict__ ctx) {
    int h = blockIdx.y;
    int n0 = blockIdx.x * 128;
    int t = threadIdx.x;
    __shared__ float sv[4][64];
    float4 acc4[16];
    #pragma unroll
    for (int i = 0; i < 16; i++) acc4[i] = make_float4(0.f, 0.f, 0.f, 0.f);
    int rr = t >> 6, cc = t & 63;
    for (int n = n0; n < n0 + 128; n += 4) {
        sv[rr][cc] = v[(size_t)(n + rr) * DIM + h * DH + cc];
        __syncthreads();
        #pragma unroll
        for (int r = 0; r < 4; r++) {
            float kv = kf[((size_t)((h << 12) + n + r)) * MFEAT + t];
            const float4* vp = (const float4*)sv[r];
            #pragma unroll
            for (int d4 = 0; d4 < 16; d4++) {
                float4 vv = vp[d4];
                acc4[d4].x += kv * vv.x; acc4[d4].y += kv * vv.y;
                acc4[d4].z += kv * vv.z; acc4[d4].w += kv * vv.w;
            }
        }
        __syncthreads();
    }
    float* cp = ctx + ((size_t)h * MFEAT + t) * DH;
    #pragma unroll
    for (int d4 = 0; d4 < 16; d4++) {
        atomicAdd(&cp[d4 * 4 + 0], acc4[d4].x);
        atomicAdd(&cp[d4 * 4 + 1], acc4[d4].y);
        atomicAdd(&cp[d4 * 4 + 2], acc4[d4].z);
        atomicAdd(&cp[d4 * 4 + 3], acc4[d4].w);
    }
}

__global__ void ctxT_kernel(const float* __restrict__ ctx,
                            __nv_bfloat16* __restrict__ oh, __nv_bfloat16* __restrict__ ol) {
    int h = blockIdx.x;
    for (int i = threadIdx.x; i < MFEAT * DH; i += 256) {
        int m = i >> 6, d = i & 63;
        float v = ctx[(size_t)h * MFEAT * DH + i];
        split_store(v, oh, ol, ((size_t)h * DH + d) * MFEAT + m);
    }
}

__global__ void tconv_kernel(const float* __restrict__ in, int ldi, size_t inz,
                             __nv_bfloat16* __restrict__ oh, __nv_bfloat16* __restrict__ ol,
                             int ldo, size_t outz) {
    __shared__ float ts[32][33];
    const float* ip = in + (size_t)blockIdx.z * inz;
    int r0 = blockIdx.y * 32, c0 = blockIdx.x * 32;
    int tx = threadIdx.x, ty = threadIdx.y;
    #pragma unroll
    for (int j = 0; j < 4; j++)
        ts[ty + j * 8][tx] = ip[(size_t)(r0 + ty + j * 8) * ldi + c0 + tx];
    __syncthreads();
    size_t ob = (size_t)blockIdx.z * outz;
    #pragma unroll
    for (int j = 0; j < 4; j++)
        split_store(ts[tx][ty + j * 8], oh, ol, ob + (size_t)(c0 + ty + j * 8) * ldo + r0 + tx);
}

__global__ void projc_kernel(const float* __restrict__ in,
                             __nv_bfloat16* __restrict__ oh, __nv_bfloat16* __restrict__ ol) {
    size_t i = (size_t)blockIdx.x * 256 + threadIdx.x;
    split_store(0.35355339059327373f * in[i], oh, ol, i);
}

// ---------------- HMMA GEMM core (mma.sync bf16, 3-term split) ---------------
template<int EPI>
__device__ __forceinline__ void epi2(int r, int c, float v0, float v1,
                                     const float* __restrict__ bias, const float* __restrict__ res,
                                     float* __restrict__ C, __nv_bfloat16* __restrict__ Ch,
                                     __nv_bfloat16* __restrict__ Cl, int ldc,
                                     const float* __restrict__ scale) {
    if (EPI == 2 || EPI == 3) { v0 += bias[c]; v1 += bias[c + 1]; }
    if (EPI == 2) { v0 = gelu_tanh(v0); v1 = gelu_tanh(v1); }
    if (EPI == 3) {
        float2 rr = *(const float2*)(res + (size_t)r * ldc + c);
        v0 += rr.x; v1 += rr.y;
    }
    if (EPI == 6) { float s = scale[r]; v0 *= s; v1 *= s; }
    if (EPI == 0 || EPI == 3 || EPI == 4)
        *(float2*)(C + (size_t)r * ldc + c) = make_float2(v0, v1);
    if (EPI == 2 || EPI == 4 || EPI == 6) {
        __nv_bfloat16 h0 = __float2bfloat16(v0), h1 = __float2bfloat16(v1);
        __nv_bfloat16 l0 = __float2bfloat16(v0 - __bfloat162float(h0));
        __nv_bfloat16 l1 = __float2bfloat16(v1 - __bfloat162float(h1));
        __nv_bfloat162 hh = __halves2bfloat162(h0, h1);
        __nv_bfloat162 ll = __halves2bfloat162(l0, l1);
        *(__nv_bfloat162*)(Ch + (size_t)r * ldc + c) = hh;
        *(__nv_bfloat162*)(Cl + (size_t)r * ldc + c) = ll;
    }
}

template<int EPI, int TN, bool KM>
__device__ void hmma_core(const __nv_bfloat16* __restrict__ Ah, const __nv_bfloat16* __restrict__ Al,
                          int lda,
                          const __nv_bfloat16* __restrict__ Bh, const __nv_bfloat16* __restrict__ Bl,
                          int ldb,
                          const float* __restrict__ bias, const float* __restrict__ res,
                          float* __restrict__ C, __nv_bfloat16* __restrict__ Ch,
                          __nv_bfloat16* __restrict__ Cl, int ldc,
                          const float* __restrict__ scale, unsigned* __restrict__ hmaxp,
                          int K, int row0, int col0)
{
    extern __shared__ __nv_bfloat16 smem[];
    const int AS = 128 * 40;
    const int BS = TN * 40;
    const int STG = 2 * AS + 2 * BS;

    const int MT = (TN == 128) ? 4 : 2;
    int tid = threadIdx.x, w = tid >> 5, lane = tid & 31;
    int wm0, wn0;
    if (TN == 128) { wm0 = (w >> 2) * 64; wn0 = (w & 3) * 32; }
    else           { wm0 = (w >> 1) * 32; wn0 = (w & 1) * 32; }

    float acc[4][4][4];
    #pragma unroll
    for (int i = 0; i < 4; i++)
        #pragma unroll
        for (int j = 0; j < 4; j++)
            #pragma unroll
            for (int e = 0; e < 4; e++) acc[i][j][e] = 0.0f;

    int nch = K >> 5;

    auto prefetch = [&](int c, int s) {
        int k0 = c << 5;
        __nv_bfloat16* sAh = smem + s * STG;
        __nv_bfloat16* sAl = sAh + AS;
        __nv_bfloat16* sBh = sAh + 2 * AS;
        __nv_bfloat16* sBl = sBh + BS;
        for (int i = tid; i < 128 * 4; i += 256) {
            int r = i >> 2, kp = (i & 3) << 3;
            size_t gi = (size_t)(row0 + r) * lda + k0 + kp;
            cp16(sAh + r * 40 + kp, Ah + gi);
            cp16(sAl + r * 40 + kp, Al + gi);
        }
        for (int i = tid; i < TN * 4; i += 256) {
            int r = i >> 2, kp = (i & 3) << 3;
            size_t gi = (size_t)(col0 + r) * ldb + k0 + kp;
            cp16(sBh + r * 40 + kp, Bh + gi);
            cp16(sBl + r * 40 + kp, Bl + gi);
        }
        cp_commit();
    };

    prefetch(0, 0);
    for (int c = 0; c < nch; c++) {
        if (c + 1 < nch) {
            prefetch(c + 1, (c + 1) & 1);
            asm volatile("cp.async.wait_group 1;" ::: "memory");
        } else {
            asm volatile("cp.async.wait_group 0;" ::: "memory");
        }
        __syncthreads();

        __nv_bfloat16* cAh = smem + (c & 1) * STG;
        __nv_bfloat16* cAl = cAh + AS;
        __nv_bfloat16* cBh = cAh + 2 * AS;
        __nv_bfloat16* cBl = cBh + BS;

        #pragma unroll
        for (int kk = 0; kk < 32; kk += 16) {
            uint32_t bh[4][2], bl[4][2];
            ldmB(bh[0], bh[1], cBh + wn0 * 40 + kk, lane);
            ldmB(bh[2], bh[3], cBh + (wn0 + 16) * 40 + kk, lane);
            ldmB(bl[0], bl[1], cBl + wn0 * 40 + kk, lane);
            ldmB(bl[2], bl[3], cBl + (wn0 + 16) * 40 + kk, lane);
            #pragma unroll
            for (int mt = 0; mt < MT; mt++) {
                uint32_t ah[4], al[4];
                ldmA(ah, cAh + (wm0 + mt * 16) * 40 + kk, lane);
                ldmA(al, cAl + (wm0 + mt * 16) * 40 + kk, lane);
                #pragma unroll
                for (int nt = 0; nt < 4; nt++) {
                    mma16816(acc[mt][nt], ah, bh[nt]);
                    mma16816(acc[mt][nt], ah, bl[nt]);
                    mma16816(acc[mt][nt], al, bh[nt]);
                }
            }
        }
        __syncthreads();
    }

    #pragma unroll
    for (int mt = 0; mt < MT; mt++) {
        #pragma unroll
        for (int nt = 0; nt < 4; nt++) {
            int r = row0 + wm0 + mt * 16 + (lane >> 2);
            int cc = col0 + wn0 + nt * 8 + ((lane & 3) << 1);
            epi2<EPI>(r,     cc, acc[mt][nt][0], acc[mt][nt][1], bias, res, C, Ch, Cl, ldc, scale);
            epi2<EPI>(r + 8, cc, acc[mt][nt][2], acc[mt][nt][3], bias, res, C, Ch, Cl, ldc, scale);
        }
    }

    if (KM) {
        // per-tile max of raw outputs -> ordered-uint atomicMax into hmaxp
        float m = -3e38f;
        #pragma unroll
        for (int mt = 0; mt < MT; mt++)
            #pragma unroll
            for (int nt = 0; nt < 4; nt++)
                #pragma unroll
                for (int e = 0; e < 4; e++) m = fmaxf(m, acc[mt][nt][e]);
        #pragma unroll
        for (int off = 16; off; off >>= 1) m = fmaxf(m, __shfl_xor_sync(0xffffffffu, m, off));
        __shared__ float smax[8];
        if (lane == 0) smax[w] = m;
        __syncthreads();
        if (tid == 0) {
            float bm = smax[0];
            #pragma unroll
            for (int i = 1; i < 8; i++) bm = fmaxf(bm, smax[i]);
            atomicMax(hmaxp, f2o(bm));
        }
    }
}

#define SMEM_128 (2 * (2 * 128 * 40 + 2 * 128 * 40) * 2)   // 81920 B
#define SMEM_64  (2 * (2 * 128 * 40 + 2 * 64 * 40) * 2)    // 61440 B

// ---------------- HMMA wrappers ----------------------------------------------
template<int EPI>
__global__ __launch_bounds__(256, 2) void hm_plain_k(
    const __nv_bfloat16* Ah, const __nv_bfloat16* Al, int lda,
    const __nv_bfloat16* Bh, const __nv_bfloat16* Bl, int ldb,
    const float* bias, const float* res,
    float* C, __nv_bfloat16* Ch, __nv_bfloat16* Cl, int ldc, int K)
{
    hmma_core<EPI, 128, false>(Ah, Al, lda, Bh, Bl, ldb, bias, res, C, Ch, Cl, ldc,
                               nullptr, nullptr, K, blockIdx.y * 128, blockIdx.x * 128);
}

__global__ __launch_bounds__(256, 2) void hm_qkv_k(
    const __nv_bfloat16* Ah, const __nv_bfloat16* Al,
    const __nv_bfloat16* Wqh, const __nv_bfloat16* Wql,
    const __nv_bfloat16* Wkh, const __nv_bfloat16* Wkl,
    const __nv_bfloat16* Wvh, const __nv_bfloat16* Wvl,
    float* q, float* k, float* v,
    __nv_bfloat16* qh, __nv_bfloat16* ql, __nv_bfloat16* kh, __nv_bfloat16* kl,
    __nv_bfloat16* vh, __nv_bfloat16* vl)
{
    int z = blockIdx.z;
    const __nv_bfloat16* Bh = (z == 0) ? Wqh : (z == 1) ? Wkh : Wvh;
    const __nv_bfloat16* Bl = (z == 0) ? Wql : (z == 1) ? Wkl : Wvl;
    float* C = (z == 0) ? q : (z == 1) ? k : v;
    __nv_bfloat16* Ch = (z == 0) ? qh : (z == 1) ? kh : vh;
    __nv_bfloat16* Cl = (z == 0) ? ql : (z == 1) ? kl : vl;
    hmma_core<4, 128, false>(Ah, Al, DIM, Bh, Bl, DIM, nullptr, nullptr, C, Ch, Cl, DIM,
                             nullptr, nullptr, DIM, blockIdx.y * 128, blockIdx.x * 128);
}

__global__ __launch_bounds__(256, 2) void hm_xd_k(
    const __nv_bfloat16* qh, const __nv_bfloat16* ql,
    const __nv_bfloat16* kh, const __nv_bfloat16* kl,
    const __nv_bfloat16* prh, const __nv_bfloat16* prl,
    float* xq, float* xk, unsigned* hmax)
{
    int z = blockIdx.z;
    if (z < 12) {
        const __nv_bfloat16* Ah = qh + z * DH;
        const __nv_bfloat16* Al = ql + z * DH;
        float* C = xq + (size_t)z * NTOK * MFEAT;
        hmma_core<0, 128, false>(Ah, Al, DIM, prh, prl, DH, nullptr, nullptr, C,
                                 nullptr, nullptr, MFEAT, nullptr, nullptr, DH,
                                 blockIdx.y * 128, blockIdx.x * 128);
    } else {
        int h = z - 12;
        const __nv_bfloat16* Ah = kh + h * DH;
        const __nv_bfloat16* Al = kl + h * DH;
        float* C = xk + (size_t)h * NTOK * MFEAT;
        hmma_core<0, 128, true>(Ah, Al, DIM, prh, prl, DH, nullptr, nullptr, C,
                                nullptr, nullptr, MFEAT, nullptr, hmax + h, DH,
                                blockIdx.y * 128, blockIdx.x * 128);
    }
}

__global__ __launch_bounds__(256, 2) void hm_o_k(
    const __nv_bfloat16* qfh, const __nv_bfloat16* qfl,
    const __nv_bfloat16* cth, const __nv_bfloat16* ctl,
    const float* dinv, __nv_bfloat16* oh, __nv_bfloat16* ol)
{
    int h = blockIdx.z;
    hmma_core<6, 64, false>(qfh + (size_t)h * NTOK * MFEAT, qfl + (size_t)h * NTOK * MFEAT, MFEAT,
                            cth + (size_t)h * DH * MFEAT, ctl + (size_t)h * DH * MFEAT, MFEAT,
                            nullptr, nullptr, nullptr, oh + h * DH, ol + h * DH, DIM,
                            dinv + (size_t)h * NTOK, nullptr, MFEAT, blockIdx.y * 128, 0);
}

// ---------------- SIMT guard GEMM for tiny Wout -------------------------------
__global__ __launch_bounds__(256)
void sgemm_guard_k(const float* __restrict__ A, int lda, const float* __restrict__ B, int ldb,
                   const float* __restrict__ bias, float* __restrict__ C, int ldc,
                   int N, int K) {
    __shared__ float As[8][128];
    __shared__ float Bs[8][128];
    int tid = threadIdx.x;
    int row0 = blockIdx.y * 128, col0 = blockIdx.x * 128;
    int tx = tid & 15, ty = tid >> 4;
    int arow = tid >> 1, acol = (tid & 1) * 4;
    int brow = tid >> 5, bcol = (tid & 31) * 4;
    float acc[8][8];
    #pragma unroll
    for (int i = 0; i < 8; i++)
        #pragma unroll
        for (int j = 0; j < 8; j++) acc[i][j] = 0.0f;
    for (int k0 = 0; k0 < K; k0 += 8) {
        float4 av = *(const float4*)(A + (size_t)(row0 + arow) * lda + k0 + acol);
        As[acol + 0][arow] = av.x; As[acol + 1][arow] = av.y;
        As[acol + 2][arow] = av.z; As[acol + 3][arow] = av.w;
        #pragma unroll
        for (int j = 0; j < 4; j++) {
            int c = col0 + bcol + j;
            Bs[brow][bcol + j] = (c < N) ? B[(size_t)(k0 + brow) * ldb + c] : 0.0f;
        }
        __syncthreads();
        #pragma unroll
        for (int kk = 0; kk < 8; kk++) {
            float a[8], bb[8];
            #pragma unroll
            for (int i = 0; i < 8; i++) a[i] = As[kk][ty + 16 * i];
            #pragma unroll
            for (int j = 0; j < 8; j++) bb[j] = Bs[kk][tx + 16 * j];
            #pragma unroll
            for (int i = 0; i < 8; i++)
                #pragma unroll
                for (int j = 0; j < 8; j++) acc[i][j] += a[i] * bb[j];
        }
        __syncthreads();
    }
    #pragma unroll
    for (int i = 0; i < 8; i++) {
        int r = row0 + ty + 16 * i;
        #pragma unroll
        for (int j = 0; j < 8; j++) {
            int c = col0 + tx + 16 * j;
            if (c < N) C[(size_t)r * ldc + c] = acc[i][j] + bias[c];
        }
    }
}

// ---------------- host --------------------------------------------------------
extern "C" void kernel_launch(void* const* d_in, const int* in_sizes, int n_in,
                              void* d_out, int out_size) {
    const float* methy  = (const float*)d_in[0];
    const int*   chromo = (const int*)  d_in[1];
    const int*   pos    = (const int*)  d_in[2];
    const float* mtab   = (const float*)d_in[3];
    const float* ctab   = (const float*)d_in[4];
    const float* ptab   = (const float*)d_in[5];
    const float* ln1g   = (const float*)d_in[6];
    const float* ln1b   = (const float*)d_in[7];
    const float* ln2g   = (const float*)d_in[8];
    const float* ln2b   = (const float*)d_in[9];
    const float* Wq     = (const float*)d_in[10];
    const float* Wk     = (const float*)d_in[11];
    const float* Wv     = (const float*)d_in[12];
    const float* Wo     = (const float*)d_in[13];
    const float* bo     = (const float*)d_in[14];
    const float* W1     = (const float*)d_in[15];
    const float* b1     = (const float*)d_in[16];
    const float* W2     = (const float*)d_in[17];
    const float* b2     = (const float*)d_in[18];
    const float* proj   = (const float*)d_in[19];
    const float* nfg    = (const float*)d_in[20];
    const float* nfb    = (const float*)d_in[21];
    const float* Wout   = (const float*)d_in[22];
    const float* bout   = (const float*)d_in[23];
    float* out = (float*)d_out;

    static int smem_set = 0;
    if (!smem_set) {
        cudaFuncSetAttribute(hm_qkv_k,      cudaFuncAttributeMaxDynamicSharedMemorySize, SMEM_128);
        cudaFuncSetAttribute(hm_xd_k,       cudaFuncAttributeMaxDynamicSharedMemorySize, SMEM_128);
        cudaFuncSetAttribute(hm_o_k,        cudaFuncAttributeMaxDynamicSharedMemorySize, SMEM_64);
        cudaFuncSetAttribute(hm_plain_k<2>, cudaFuncAttributeMaxDynamicSharedMemorySize, SMEM_128);
        cudaFuncSetAttribute(hm_plain_k<3>, cudaFuncAttributeMaxDynamicSharedMemorySize, SMEM_128);
        smem_set = 1;
    }

    float *px, *ph, *pq, *pk, *pv, *pqf, *pkf, *pksum, *pctx, *pdinv;
    unsigned* phmax;
    cudaGetSymbolAddress((void**)&px,    g_x);
    cudaGetSymbolAddress((void**)&ph,    g_h);
    cudaGetSymbolAddress((void**)&pq,    g_q);
    cudaGetSymbolAddress((void**)&pk,    g_k);
    cudaGetSymbolAddress((void**)&pv,    g_v);
    cudaGetSymbolAddress((void**)&pqf,   g_qf);
    cudaGetSymbolAddress((void**)&pkf,   g_kf);
    cudaGetSymbolAddress((void**)&pksum, g_ksum);
    cudaGetSymbolAddress((void**)&pctx,  g_ctx);
    cudaGetSymbolAddress((void**)&pdinv, g_dinv);
    cudaGetSymbolAddress((void**)&phmax, g_hmax);

    __nv_bfloat16 *hh, *hl, *qh, *ql, *kh, *kl, *vh, *vl, *oh, *ol, *ffh, *ffl;
    __nv_bfloat16 *qfh, *qfl, *ctTh, *ctTl, *pch, *pcl;
    __nv_bfloat16 *wqh, *wql, *wkh, *wkl, *wvh, *wvl, *woh, *wol, *w1h, *w1l, *w2h, *w2l;
    cudaGetSymbolAddress((void**)&hh,  g_hh);  cudaGetSymbolAddress((void**)&hl,  g_hl);
    cudaGetSymbolAddress((void**)&qh,  g_qh);  cudaGetSymbolAddress((void**)&ql,  g_ql);
    cudaGetSymbolAddress((void**)&kh,  g_kh);  cudaGetSymbolAddress((void**)&kl,  g_kl);
    cudaGetSymbolAddress((void**)&vh,  g_vh);  cudaGetSymbolAddress((void**)&vl,  g_vl);
    cudaGetSymbolAddress((void**)&oh,  g_oh);  cudaGetSymbolAddress((void**)&ol,  g_ol);
    cudaGetSymbolAddress((void**)&ffh, g_ffh); cudaGetSymbolAddress((void**)&ffl, g_ffl);
    cudaGetSymbolAddress((void**)&qfh, g_qfh); cudaGetSymbolAddress((void**)&qfl, g_qfl);
    cudaGetSymbolAddress((void**)&ctTh, g_ctTh); cudaGetSymbolAddress((void**)&ctTl, g_ctTl);
    cudaGetSymbolAddress((void**)&pch, g_pch); cudaGetSymbolAddress((void**)&pcl, g_pcl);
    cudaGetSymbolAddress((void**)&wqh, g_wqh); cudaGetSymbolAddress((void**)&wql, g_wql);
    cudaGetSymbolAddress((void**)&wkh, g_wkh); cudaGetSymbolAddress((void**)&wkl, g_wkl);
    cudaGetSymbolAddress((void**)&wvh, g_wvh); cudaGetSymbolAddress((void**)&wvl, g_wvl);
    cudaGetSymbolAddress((void**)&woh, g_woh); cudaGetSymbolAddress((void**)&wol, g_wol);
    cudaGetSymbolAddress((void**)&w1h, g_w1h); cudaGetSymbolAddress((void**)&w1l, g_w1l);
    cudaGetSymbolAddress((void**)&w2h, g_w2h); cudaGetSymbolAddress((void**)&w2l, g_w2l);

    dim3 tb(32, 8);
    tconv_kernel<<<dim3(24, 24, 6), tb>>>(Wq, DIM, (size_t)DIM * DIM, wqh, wql, DIM, (size_t)DIM * DIM);
    tconv_kernel<<<dim3(24, 24, 6), tb>>>(Wk, DIM, (size_t)DIM * DIM, wkh, wkl, DIM, (size_t)DIM * DIM);
    tconv_kernel<<<dim3(24, 24, 6), tb>>>(Wv, DIM, (size_t)DIM * DIM, wvh, wvl, DIM, (size_t)DIM * DIM);
    tconv_kernel<<<dim3(24, 24, 6), tb>>>(Wo, DIM, (size_t)DIM * DIM, woh, wol, DIM, (size_t)DIM * DIM);
    tconv_kernel<<<dim3(96, 24, 6), tb>>>(W1, FFD, (size_t)DIM * FFD, w1h, w1l, DIM, (size_t)DIM * FFD);
    tconv_kernel<<<dim3(24, 96, 6), tb>>>(W2, DIM, (size_t)DIM * FFD, w2h, w2l, FFD, (size_t)DIM * FFD);
    projc_kernel<<<DEPTH * MFEAT * DH / 256, 256>>>(proj, pch, pcl);

    embed_kernel<<<NTOK, 256>>>(methy, pos, chromo, mtab, ptab, ctab, px);

    for (int l = 0; l < DEPTH; l++) {
        size_t wo = (size_t)l * DIM * DIM;
        size_t w12 = (size_t)l * DIM * FFD;

        ln_kernel<<<NTOK / 8, 256>>>(px, ln1g + l * DIM, ln1b + l * DIM, ph, hh, hl);
        hm_qkv_k<<<dim3(6, 32, 3), 256, SMEM_128>>>(hh, hl,
            wqh + wo, wql + wo, wkh + wo, wkl + wo, wvh + wo, wvl + wo,
            pq, pk, pv, qh, ql, kh, kl, vh, vl);

        zero_kernel<<<(HEADS * MFEAT * DH + 255) / 256, 256>>>(phmax, pksum, pctx);

        hm_xd_k<<<dim3(2, 32, 24), 256, SMEM_128>>>(qh, ql, kh, kl,
            pch + (size_t)l * MFEAT * DH, pcl + (size_t)l * MFEAT * DH, pqf, pkf, phmax);
        k_post_kernel<<<dim3(32, HEADS), 256>>>(pk, pkf, phmax, methy, pksum);
        q_post_kernel<<<HEADS * NTOK / 8, 256>>>(pq, pqf, qfh, qfl, pksum, pdinv);
        ctx_kernel<<<dim3(32, HEADS), 256>>>(pkf, pv, pctx);
        ctxT_kernel<<<HEADS, 256>>>(pctx, ctTh, ctTl);
        hm_o_k<<<dim3(1, 32, HEADS), 256, SMEM_64>>>(qfh, qfl, ctTh, ctTl, pdinv, oh, ol);

        hm_plain_k<3><<<dim3(6, 32), 256, SMEM_128>>>(oh, ol, DIM, woh + wo, wol + wo, DIM,
            bo + l * DIM, px, px, nullptr, nullptr, DIM, DIM);
        ln_kernel<<<NTOK / 8, 256>>>(px, ln2g + l * DIM, ln2b + l * DIM, ph, hh, hl);
        hm_plain_k<2><<<dim3(24, 32), 256, SMEM_128>>>(hh, hl, DIM, w1h + w12, w1l + w12, DIM,
            b1 + l * FFD, nullptr, nullptr, ffh, ffl, FFD, DIM);
        hm_plain_k<3><<<dim3(6, 32), 256, SMEM_128>>>(ffh, ffl, FFD, w2h + w12, w2l + w12, FFD,
            b2 + l * DIM, px, px, nullptr, nullptr, DIM, FFD);
    }

    ln_kernel<<<NTOK / 8, 256>>>(px, nfg, nfb, ph, hh, hl);
    sgemm_guard_k<<<dim3(1, 32), 256>>>(ph, DIM, Wout, NOUT, bout, out, NOUT, NOUT, DIM);
}

// round 14
// speedup vs baseline: 1.9234x; 1.0445x over previous
#include <cuda_runtime.h>
#include <cuda_bf16.h>
#include <math.h>
#include <stdint.h>

#define NTOK  4096
#define DIM   768
#define DEPTH 6
#define HEADS 12
#define DH    64
#define FFD   3072
#define MFEAT 256
#define NOUT  102

// ---------------- fp32 scratch ----------------------------------------------
__device__ float g_x  [NTOK*DIM];
__device__ float g_h  [NTOK*DIM];
__device__ float g_q  [NTOK*DIM];
__device__ float g_k  [NTOK*DIM];
__device__ float g_qf [HEADS*NTOK*MFEAT];
__device__ float g_kf [HEADS*NTOK*MFEAT];
__device__ unsigned g_hmax[HEADS];
__device__ float g_ksum[HEADS*MFEAT];
__device__ float g_ctx [HEADS*MFEAT*DH];
__device__ float g_dinv[HEADS*NTOK];
__device__ float g_v  [NTOK*DIM];

// ---------------- bf16 hi/lo scratch -----------------------------------------
__device__ __nv_bfloat16 g_hh [NTOK*DIM],  g_hl [NTOK*DIM];
__device__ __nv_bfloat16 g_qh [NTOK*DIM],  g_ql [NTOK*DIM];
__device__ __nv_bfloat16 g_kh [NTOK*DIM],  g_kl [NTOK*DIM];
__device__ __nv_bfloat16 g_vh [NTOK*DIM],  g_vl [NTOK*DIM];
__device__ __nv_bfloat16 g_oh [NTOK*DIM],  g_ol [NTOK*DIM];
__device__ __nv_bfloat16 g_ffh[NTOK*FFD],  g_ffl[NTOK*FFD];
__device__ __nv_bfloat16 g_qfh[HEADS*NTOK*MFEAT], g_qfl[HEADS*NTOK*MFEAT];
__device__ __nv_bfloat16 g_ctTh[HEADS*DH*MFEAT],  g_ctTl[HEADS*DH*MFEAT];
__device__ __nv_bfloat16 g_pch[DEPTH*MFEAT*DH],   g_pcl[DEPTH*MFEAT*DH];
__device__ __nv_bfloat16 g_wqh[DEPTH*DIM*DIM], g_wql[DEPTH*DIM*DIM];
__device__ __nv_bfloat16 g_wkh[DEPTH*DIM*DIM], g_wkl[DEPTH*DIM*DIM];
__device__ __nv_bfloat16 g_wvh[DEPTH*DIM*DIM], g_wvl[DEPTH*DIM*DIM];
__device__ __nv_bfloat16 g_woh[DEPTH*DIM*DIM], g_wol[DEPTH*DIM*DIM];
__device__ __nv_bfloat16 g_w1h[DEPTH*FFD*DIM], g_w1l[DEPTH*FFD*DIM];
__device__ __nv_bfloat16 g_w2h[DEPTH*DIM*FFD], g_w2l[DEPTH*DIM*FFD];

// ---------------- helpers ----------------------------------------------------
__device__ __forceinline__ unsigned f2o(float f) {
    unsigned u = __float_as_uint(f);
    return (u & 0x80000000u) ? ~u : (u | 0x80000000u);
}
__device__ __forceinline__ float o2f(unsigned u) {
    return __uint_as_float((u & 0x80000000u) ? (u & 0x7fffffffu) : ~u);
}

// FFMA-only exp (no MUFU): exp2 range reduction + degree-7 poly + bit exponent
__device__ __forceinline__ float fexp(float x) {
    float t = x * 1.4426950408889634f;
    t = fmaxf(t, -120.0f);
    float fi = floorf(t);
    float f = t - fi;
    float p = 1.52527338e-5f;
    p = p * f + 1.54035304e-4f;
    p = p * f + 1.33335581e-3f;
    p = p * f + 9.61812911e-3f;
    p = p * f + 5.55041087e-2f;
    p = p * f + 2.40226507e-1f;
    p = p * f + 6.93147181e-1f;
    p = p * f + 1.0f;
    int ei = (int)fi;
    return __int_as_float((ei + 127) << 23) * p;
}
// FFMA-only reciprocal (positive y), bit-hack seed + 3 Newton iters
__device__ __forceinline__ float frcp(float y) {
    float r = __int_as_float(0x7EF311C3 - __float_as_int(y));
    r = r * (2.0f - y * r);
    r = r * (2.0f - y * r);
    r = r * (2.0f - y * r);
    return r;
}
__device__ __forceinline__ float gelu_tanh(float x) {
    float u = 0.7978845608028654f * (x + 0.044715f * x * x * x);
    float uc = fminf(fmaxf(u, -9.0f), 9.0f);
    float e = fexp(2.0f * uc);
    float th = 1.0f - 2.0f * frcp(e + 1.0f);
    return 0.5f * x * (1.0f + th);
}
__device__ __forceinline__ uint32_t smem_u32(const void* p) {
    uint32_t a;
    asm("{ .reg .u64 t; cvta.to.shared.u64 t, %1; cvt.u32.u64 %0, t; }" : "=r"(a) : "l"(p));
    return a;
}
__device__ __forceinline__ void split_store(float v, __nv_bfloat16* oh,
                                            __nv_bfloat16* ol, size_t i) {
    __nv_bfloat16 h = __float2bfloat16(v);
    oh[i] = h;
    ol[i] = __float2bfloat16(v - __bfloat162float(h));
}
__device__ __forceinline__ void cp16(void* dst_smem, const void* src) {
    uint32_t d = smem_u32(dst_smem);
    asm volatile("cp.async.cg.shared.global [%0], [%1], 16;" :: "r"(d), "l"(src));
}
__device__ __forceinline__ void cp_commit() {
    asm volatile("cp.async.commit_group;" ::: "memory");
}

__device__ __forceinline__ void ldmA(uint32_t f[4], const __nv_bfloat16* base, int lane) {
    const __nv_bfloat16* p = base + (lane & 15) * 40 + ((lane >> 4) << 3);
    uint32_t a = smem_u32(p);
    asm volatile("ldmatrix.sync.aligned.m8n8.x4.shared.b16 {%0,%1,%2,%3}, [%4];"
                 : "=r"(f[0]), "=r"(f[1]), "=r"(f[2]), "=r"(f[3]) : "r"(a));
}
__device__ __forceinline__ void ldmB(uint32_t f0[2], uint32_t f1[2],
                                     const __nv_bfloat16* base, int lane) {
    int r = (lane & 7) + ((lane >> 4) << 3);
    int c = ((lane >> 3) & 1) << 3;
    const __nv_bfloat16* p = base + r * 40 + c;
    uint32_t a = smem_u32(p);
    asm volatile("ldmatrix.sync.aligned.m8n8.x4.shared.b16 {%0,%1,%2,%3}, [%4];"
                 : "=r"(f0[0]), "=r"(f0[1]), "=r"(f1[0]), "=r"(f1[1]) : "r"(a));
}
__device__ __forceinline__ void mma16816(float c[4], const uint32_t a[4], const uint32_t b[2]) {
    asm volatile(
        "mma.sync.aligned.m16n8k16.row.col.f32.bf16.bf16.f32 "
        "{%0,%1,%2,%3}, {%4,%5,%6,%7}, {%8,%9}, {%0,%1,%2,%3};"
        : "+f"(c[0]), "+f"(c[1]), "+f"(c[2]), "+f"(c[3])
        : "r"(a[0]), "r"(a[1]), "r"(a[2]), "r"(a[3]), "r"(b[0]), "r"(b[1]));
}

// ---------------- small SIMT kernels -----------------------------------------
__global__ void embed_kernel(const float* __restrict__ methy, const int* __restrict__ pos,
                             const int* __restrict__ chromo,
                             const float* __restrict__ mtab, const float* __restrict__ ptab,
                             const float* __restrict__ ctab, float* __restrict__ x) {
    int n = blockIdx.x, t = threadIdx.x;
    float mv = methy[n];
    int mi = 0;
    mi += (mv > -2.0f);
    mi += (mv > -1.0f);
    #pragma unroll
    for (int k = 0; k < 100; k++) mi += (mv > (float)k * 0.01f);
    int pi = pos[n], ci = chromo[n];
    #pragma unroll
    for (int i = 0; i < 3; i++) {
        int d = t + i * 256;
        x[(size_t)n * DIM + d] = mtab[(size_t)mi * DIM + d]
                               + ptab[(size_t)pi * DIM + d]
                               + ctab[(size_t)ci * DIM + d];
    }
}

__global__ void ln_kernel(const float* __restrict__ x, const float* __restrict__ g,
                          const float* __restrict__ b, float* __restrict__ out,
                          __nv_bfloat16* __restrict__ oh, __nv_bfloat16* __restrict__ ol) {
    int w = threadIdx.x >> 5, lane = threadIdx.x & 31;
    int n = blockIdx.x * 8 + w;
    const float* xr = x + (size_t)n * DIM;
    float v[24];
    float s = 0.0f;
    #pragma unroll
    for (int j = 0; j < 24; j++) { v[j] = xr[lane + 32 * j]; s += v[j]; }
    #pragma unroll
    for (int off = 16; off; off >>= 1) s += __shfl_xor_sync(0xffffffffu, s, off);
    float mu = s * (1.0f / 768.0f);
    float sq = 0.0f;
    #pragma unroll
    for (int j = 0; j < 24; j++) { float d = v[j] - mu; sq += d * d; }
    #pragma unroll
    for (int off = 16; off; off >>= 1) sq += __shfl_xor_sync(0xffffffffu, sq, off);
    float rstd = rsqrtf(sq * (1.0f / 768.0f) + 1e-5f);
    size_t base = (size_t)n * DIM;
    #pragma unroll
    for (int j = 0; j < 24; j++) {
        int d = lane + 32 * j;
        float r = (v[j] - mu) * rstd * g[d] + b[d];
        out[base + d] = r;
        split_store(r, oh, ol, base + d);
    }
}

__global__ void zero_kernel(unsigned* __restrict__ hmax, float* __restrict__ ksum,
                            float* __restrict__ ctx) {
    int i = blockIdx.x * 256 + threadIdx.x;
    if (i < HEADS) hmax[i] = 0u;
    if (i < HEADS * MFEAT) ksum[i] = 0.0f;
    if (i < HEADS * MFEAT * DH) ctx[i] = 0.0f;
}

// FUSED k-feature + ctx + ksum: computes kf in-register from raw xd, never stores it.
// grid (32, HEADS), 256 threads; block covers rows [n0, n0+128) of head h; t = m index.
__global__ void kctx_kernel(const float* __restrict__ xdk, const float* __restrict__ k,
                            const float* __restrict__ v,
                            const unsigned* __restrict__ hmax,
                            const float* __restrict__ methy,
                            float* __restrict__ ksum, float* __restrict__ ctx) {
    int h = blockIdx.y;
    int n0 = blockIdx.x * 128;
    int t = threadIdx.x;
    __shared__ float sdiag[128];
    __shared__ float smask[128];
    __shared__ float sv[4][64];

    // diag + mask for the block's 128 rows: t -> row t>>1, half t&1 (32 elems each)
    {
        int r = t >> 1, halfsel = t & 1;
        const float* kr = k + (size_t)(n0 + r) * DIM + h * DH + halfsel * 32;
        float s = 0.0f;
        #pragma unroll
        for (int j = 0; j < 32; j++) s += kr[j] * kr[j];
        s += __shfl_xor_sync(0xffffffffu, s, 1);
        if (halfsel == 0) sdiag[r] = s * 0.0625f;
        if (t < 128) smask[t] = (methy[n0 + t] != 0.0f) ? 1.0f : 0.0f;
    }
    __syncthreads();

    float mx = o2f(hmax[h]);
    float4 acc4[16];
    #pragma unroll
    for (int i = 0; i < 16; i++) acc4[i] = make_float4(0.f, 0.f, 0.f, 0.f);
    float kssum = 0.0f;
    int rr = t >> 6, cc = t & 63;

    for (int n = n0; n < n0 + 128; n += 4) {
        sv[rr][cc] = v[(size_t)(n + rr) * DIM + h * DH + cc];
        __syncthreads();
        #pragma unroll
        for (int r = 0; r < 4; r++) {
            int nn = n + r;
            int li = nn - n0;
            float xd = xdk[((size_t)((h << 12) + nn)) * MFEAT + t];
            float kv = smask[li] * 0.0625f * (fexp(xd - sdiag[li] - mx) + 1e-4f);
            kssum += kv;
            const float4* vp = (const float4*)sv[r];
            #pragma unroll
            for (int d4 = 0; d4 < 16; d4++) {
                float4 vv = vp[d4];
                acc4[d4].x += kv * vv.x; acc4[d4].y += kv * vv.y;
                acc4[d4].z += kv * vv.z; acc4[d4].w += kv * vv.w;
            }
        }
        __syncthreads();
    }
    atomicAdd(&ksum[h * MFEAT + t], kssum);
    float* cp = ctx + ((size_t)h * MFEAT + t) * DH;
    #pragma unroll
    for (int d4 = 0; d4 < 16; d4++) {
        atomicAdd(&cp[d4 * 4 + 0], acc4[d4].x);
        atomicAdd(&cp[d4 * 4 + 1], acc4[d4].y);
        atomicAdd(&cp[d4 * 4 + 2], acc4[d4].z);
        atomicAdd(&cp[d4 * 4 + 3], acc4[d4].w);
    }
}

// q post: rowmax+diag+exp -> splits, fused dinv (needs ksum ready). warp per row.
__global__ void q_post_kernel(const float* __restrict__ q, const float* __restrict__ qf,
                              __nv_bfloat16* __restrict__ qh, __nv_bfloat16* __restrict__ ql,
                              const float* __restrict__ ksum, float* __restrict__ dinv) {
    int gw = (blockIdx.x * 256 + threadIdx.x) >> 5;
    int lane = threadIdx.x & 31;
    int h = gw >> 12, n = gw & 4095;
    const float* row = qf + (size_t)gw * MFEAT;
    float v[8];
    float mx = -3e38f;
    #pragma unroll
    for (int i = 0; i < 8; i++) { v[i] = row[lane + 32 * i]; mx = fmaxf(mx, v[i]); }
    #pragma unroll
    for (int off = 16; off; off >>= 1) mx = fmaxf(mx, __shfl_xor_sync(0xffffffffu, mx, off));
    const float* qr = q + (size_t)n * DIM + h * DH;
    float a = qr[lane], b = qr[lane + 32];
    float ss = a * a + b * b;
    #pragma unroll
    for (int off = 16; off; off >>= 1) ss += __shfl_xor_sync(0xffffffffu, ss, off);
    float diag = ss * 0.0625f;
    const float* ks = ksum + h * MFEAT;
    float s = 0.0f;
    #pragma unroll
    for (int i = 0; i < 8; i++) {
        float r = 0.0625f * (fexp(v[i] - diag - mx) + 1e-4f);
        split_store(r, qh, ql, (size_t)gw * MFEAT + lane + 32 * i);
        s += r * ks[lane + 32 * i];
    }
    #pragma unroll
    for (int off = 16; off; off >>= 1) s += __shfl_xor_sync(0xffffffffu, s, off);
    if (lane == 0) dinv[gw] = 1.0f / s;
}

__global__ void ctxT_kernel(const float* __restrict__ ctx,
                            __nv_bfloat16* __restrict__ oh, __nv_bfloat16* __restrict__ ol) {
    int h = blockIdx.x;
    for (int i = threadIdx.x; i < MFEAT * DH; i += 256) {
        int m = i >> 6, d = i & 63;
        float v = ctx[(size_t)h * MFEAT * DH + i];
        split_store(v, oh, ol, ((size_t)h * DH + d) * MFEAT + m);
    }
}

__global__ void tconv_kernel(const float* __restrict__ in, int ldi, size_t inz,
                             __nv_bfloat16* __restrict__ oh, __nv_bfloat16* __restrict__ ol,
                             int ldo, size_t outz) {
    __shared__ float ts[32][33];
    const float* ip = in + (size_t)blockIdx.z * inz;
    int r0 = blockIdx.y * 32, c0 = blockIdx.x * 32;
    int tx = threadIdx.x, ty = threadIdx.y;
    #pragma unroll
    for (int j = 0; j < 4; j++)
        ts[ty + j * 8][tx] = ip[(size_t)(r0 + ty + j * 8) * ldi + c0 + tx];
    __syncthreads();
    size_t ob = (size_t)blockIdx.z * outz;
    #pragma unroll
    for (int j = 0; j < 4; j++)
        split_store(ts[tx][ty + j * 8], oh, ol, ob + (size_t)(c0 + ty + j * 8) * ldo + r0 + tx);
}

__global__ void projc_kernel(const float* __restrict__ in,
                             __nv_bfloat16* __restrict__ oh, __nv_bfloat16* __restrict__ ol) {
    size_t i = (size_t)blockIdx.x * 256 + threadIdx.x;
    split_store(0.35355339059327373f * in[i], oh, ol, i);
}

// ---------------- HMMA GEMM core (mma.sync bf16, 3-term split) ---------------
template<int EPI>
__device__ __forceinline__ void epi2(int r, int c, float v0, float v1,
                                     const float* __restrict__ bias, const float* __restrict__ res,
                                     float* __restrict__ C, __nv_bfloat16* __restrict__ Ch,
                                     __nv_bfloat16* __restrict__ Cl, int ldc,
                                     const float* __restrict__ scale) {
    if (EPI == 2 || EPI == 3) { v0 += bias[c]; v1 += bias[c + 1]; }
    if (EPI == 2) { v0 = gelu_tanh(v0); v1 = gelu_tanh(v1); }
    if (EPI == 3) {
        float2 rr = *(const float2*)(res + (size_t)r * ldc + c);
        v0 += rr.x; v1 += rr.y;
    }
    if (EPI == 6) { float s = scale[r]; v0 *= s; v1 *= s; }
    if (EPI == 0 || EPI == 3 || EPI == 4)
        *(float2*)(C + (size_t)r * ldc + c) = make_float2(v0, v1);
    if (EPI == 2 || EPI == 4 || EPI == 6) {
        __nv_bfloat16 h0 = __float2bfloat16(v0), h1 = __float2bfloat16(v1);
        __nv_bfloat16 l0 = __float2bfloat16(v0 - __bfloat162float(h0));
        __nv_bfloat16 l1 = __float2bfloat16(v1 - __bfloat162float(h1));
        __nv_bfloat162 hh = __halves2bfloat162(h0, h1);
        __nv_bfloat162 ll = __halves2bfloat162(l0, l1);
        *(__nv_bfloat162*)(Ch + (size_t)r * ldc + c) = hh;
        *(__nv_bfloat162*)(Cl + (size_t)r * ldc + c) = ll;
    }
}

template<int EPI, int TN, bool KM>
__device__ void hmma_core(const __nv_bfloat16* __restrict__ Ah, const __nv_bfloat16* __restrict__ Al,
                          int lda,
                          const __nv_bfloat16* __restrict__ Bh, const __nv_bfloat16* __restrict__ Bl,
                          int ldb,
                          const float* __restrict__ bias, const float* __restrict__ res,
                          float* __restrict__ C, __nv_bfloat16* __restrict__ Ch,
                          __nv_bfloat16* __restrict__ Cl, int ldc,
                          const float* __restrict__ scale, unsigned* __restrict__ hmaxp,
                          int K, int row0, int col0)
{
    extern __shared__ __nv_bfloat16 smem[];
    const int AS = 128 * 40;
    const int BS = TN * 40;
    const int STG = 2 * AS + 2 * BS;

    const int MT = (TN == 128) ? 4 : 2;
    int tid = threadIdx.x, w = tid >> 5, lane = tid & 31;
    int wm0, wn0;
    if (TN == 128) { wm0 = (w >> 2) * 64; wn0 = (w & 3) * 32; }
    else           { wm0 = (w >> 1) * 32; wn0 = (w & 1) * 32; }

    float acc[4][4][4];
    #pragma unroll
    for (int i = 0; i < 4; i++)
        #pragma unroll
        for (int j = 0; j < 4; j++)
            #pragma unroll
            for (int e = 0; e < 4; e++) acc[i][j][e] = 0.0f;

    int nch = K >> 5;

    auto prefetch = [&](int c, int s) {
        int k0 = c << 5;
        __nv_bfloat16* sAh = smem + s * STG;
        __nv_bfloat16* sAl = sAh + AS;
        __nv_bfloat16* sBh = sAh + 2 * AS;
        __nv_bfloat16* sBl = sBh + BS;
        for (int i = tid; i < 128 * 4; i += 256) {
            int r = i >> 2, kp = (i & 3) << 3;
            size_t gi = (size_t)(row0 + r) * lda + k0 + kp;
            cp16(sAh + r * 40 + kp, Ah + gi);
            cp16(sAl + r * 40 + kp, Al + gi);
        }
        for (int i = tid; i < TN * 4; i += 256) {
            int r = i >> 2, kp = (i & 3) << 3;
            size_t gi = (size_t)(col0 + r) * ldb + k0 + kp;
            cp16(sBh + r * 40 + kp, Bh + gi);
            cp16(sBl + r * 40 + kp, Bl + gi);
        }
        cp_commit();
    };

    prefetch(0, 0);
    for (int c = 0; c < nch; c++) {
        if (c + 1 < nch) {
            prefetch(c + 1, (c + 1) & 1);
            asm volatile("cp.async.wait_group 1;" ::: "memory");
        } else {
            asm volatile("cp.async.wait_group 0;" ::: "memory");
        }
        __syncthreads();

        __nv_bfloat16* cAh = smem + (c & 1) * STG;
        __nv_bfloat16* cAl = cAh + AS;
        __nv_bfloat16* cBh = cAh + 2 * AS;
        __nv_bfloat16* cBl = cBh + BS;

        #pragma unroll
        for (int kk = 0; kk < 32; kk += 16) {
            uint32_t bh[4][2], bl[4][2];
            ldmB(bh[0], bh[1], cBh + wn0 * 40 + kk, lane);
            ldmB(bh[2], bh[3], cBh + (wn0 + 16) * 40 + kk, lane);
            ldmB(bl[0], bl[1], cBl + wn0 * 40 + kk, lane);
            ldmB(bl[2], bl[3], cBl + (wn0 + 16) * 40 + kk, lane);
            #pragma unroll
            for (int mt = 0; mt < MT; mt++) {
                uint32_t ah[4], al[4];
                ldmA(ah, cAh + (wm0 + mt * 16) * 40 + kk, lane);
                ldmA(al, cAl + (wm0 + mt * 16) * 40 + kk, lane);
                #pragma unroll
                for (int nt = 0; nt < 4; nt++) {
                    mma16816(acc[mt][nt], ah, bh[nt]);
                    mma16816(acc[mt][nt], ah, bl[nt]);
                    mma16816(acc[mt][nt], al, bh[nt]);
                }
            }
        }
        __syncthreads();
    }

    #pragma unroll
    for (int mt = 0; mt < MT; mt++) {
        #pragma unroll
        for (int nt = 0; nt < 4; nt++) {
            int r = row0 + wm0 + mt * 16 + (lane >> 2);
            int cc = col0 + wn0 + nt * 8 + ((lane & 3) << 1);
            epi2<EPI>(r,     cc, acc[mt][nt][0], acc[mt][nt][1], bias, res, C, Ch, Cl, ldc, scale);
            epi2<EPI>(r + 8, cc, acc[mt][nt][2], acc[mt][nt][3], bias, res, C, Ch, Cl, ldc, scale);
        }
    }

    if (KM) {
        float m = -3e38f;
        #pragma unroll
        for (int mt = 0; mt < MT; mt++)
            #pragma unroll
            for (int nt = 0; nt < 4; nt++)
                #pragma unroll
                for (int e = 0; e < 4; e++) m = fmaxf(m, acc[mt][nt][e]);
        #pragma unroll
        for (int off = 16; off; off >>= 1) m = fmaxf(m, __shfl_xor_sync(0xffffffffu, m, off));
        __shared__ float smax[8];
        if (lane == 0) smax[w] = m;
        __syncthreads();
        if (tid == 0) {
            float bm = smax[0];
            #pragma unroll
            for (int i = 1; i < 8; i++) bm = fmaxf(bm, smax[i]);
            atomicMax(hmaxp, f2o(bm));
        }
    }
}

#define SMEM_128 (2 * (2 * 128 * 40 + 2 * 128 * 40) * 2)   // 81920 B
#define SMEM_64  (2 * (2 * 128 * 40 + 2 * 64 * 40) * 2)    // 61440 B

// ---------------- HMMA wrappers ----------------------------------------------
template<int EPI>
__global__ __launch_bounds__(256, 2) void hm_plain_k(
    const __nv_bfloat16* Ah, const __nv_bfloat16* Al, int lda,
    const __nv_bfloat16* Bh, const __nv_bfloat16* Bl, int ldb,
    const float* bias, const float* res,
    float* C, __nv_bfloat16* Ch, __nv_bfloat16* Cl, int ldc, int K)
{
    hmma_core<EPI, 128, false>(Ah, Al, lda, Bh, Bl, ldb, bias, res, C, Ch, Cl, ldc,
                               nullptr, nullptr, K, blockIdx.y * 128, blockIdx.x * 128);
}

__global__ __launch_bounds__(256, 2) void hm_qkv_k(
    const __nv_bfloat16* Ah, const __nv_bfloat16* Al,
    const __nv_bfloat16* Wqh, const __nv_bfloat16* Wql,
    const __nv_bfloat16* Wkh, const __nv_bfloat16* Wkl,
    const __nv_bfloat16* Wvh, const __nv_bfloat16* Wvl,
    float* q, float* k, float* v,
    __nv_bfloat16* qh, __nv_bfloat16* ql, __nv_bfloat16* kh, __nv_bfloat16* kl,
    __nv_bfloat16* vh, __nv_bfloat16* vl)
{
    int z = blockIdx.z;
    const __nv_bfloat16* Bh = (z == 0) ? Wqh : (z == 1) ? Wkh : Wvh;
    const __nv_bfloat16* Bl = (z == 0) ? Wql : (z == 1) ? Wkl : Wvl;
    float* C = (z == 0) ? q : (z == 1) ? k : v;
    __nv_bfloat16* Ch = (z == 0) ? qh : (z == 1) ? kh : vh;
    __nv_bfloat16* Cl = (z == 0) ? ql : (z == 1) ? kl : vl;
    hmma_core<4, 128, false>(Ah, Al, DIM, Bh, Bl, DIM, nullptr, nullptr, C, Ch, Cl, DIM,
                             nullptr, nullptr, DIM, blockIdx.y * 128, blockIdx.x * 128);
}

__global__ __launch_bounds__(256, 2) void hm_xd_k(
    const __nv_bfloat16* qh, const __nv_bfloat16* ql,
    const __nv_bfloat16* kh, const __nv_bfloat16* kl,
    const __nv_bfloat16* prh, const __nv_bfloat16* prl,
    float* xq, float* xk, unsigned* hmax)
{
    int z = blockIdx.z;
    if (z < 12) {
        const __nv_bfloat16* Ah = qh + z * DH;
        const __nv_bfloat16* Al = ql + z * DH;
        float* C = xq + (size_t)z * NTOK * MFEAT;
        hmma_core<0, 128, false>(Ah, Al, DIM, prh, prl, DH, nullptr, nullptr, C,
                                 nullptr, nullptr, MFEAT, nullptr, nullptr, DH,
                                 blockIdx.y * 128, blockIdx.x * 128);
    } else {
        int h = z - 12;
        const __nv_bfloat16* Ah = kh + h * DH;
        const __nv_bfloat16* Al = kl + h * DH;
        float* C = xk + (size_t)h * NTOK * MFEAT;
        hmma_core<0, 128, true>(Ah, Al, DIM, prh, prl, DH, nullptr, nullptr, C,
                                nullptr, nullptr, MFEAT, nullptr, hmax + h, DH,
                                blockIdx.y * 128, blockIdx.x * 128);
    }
}

__global__ __launch_bounds__(256, 2) void hm_o_k(
    const __nv_bfloat16* qfh, const __nv_bfloat16* qfl,
    const __nv_bfloat16* cth, const __nv_bfloat16* ctl,
    const float* dinv, __nv_bfloat16* oh, __nv_bfloat16* ol)
{
    int h = blockIdx.z;
    hmma_core<6, 64, false>(qfh + (size_t)h * NTOK * MFEAT, qfl + (size_t)h * NTOK * MFEAT, MFEAT,
                            cth + (size_t)h * DH * MFEAT, ctl + (size_t)h * DH * MFEAT, MFEAT,
                            nullptr, nullptr, nullptr, oh + h * DH, ol + h * DH, DIM,
                            dinv + (size_t)h * NTOK, nullptr, MFEAT, blockIdx.y * 128, 0);
}

// ---------------- SIMT guard GEMM for tiny Wout -------------------------------
__global__ __launch_bounds__(256)
void sgemm_guard_k(const float* __restrict__ A, int lda, const float* __restrict__ B, int ldb,
                   const float* __restrict__ bias, float* __restrict__ C, int ldc,
                   int N, int K) {
    __shared__ float As[8][128];
    __shared__ float Bs[8][128];
    int tid = threadIdx.x;
    int row0 = blockIdx.y * 128, col0 = blockIdx.x * 128;
    int tx = tid & 15, ty = tid >> 4;
    int arow = tid >> 1, acol = (tid & 1) * 4;
    int brow = tid >> 5, bcol = (tid & 31) * 4;
    float acc[8][8];
    #pragma unroll
    for (int i = 0; i < 8; i++)
        #pragma unroll
        for (int j = 0; j < 8; j++) acc[i][j] = 0.0f;
    for (int k0 = 0; k0 < K; k0 += 8) {
        float4 av = *(const float4*)(A + (size_t)(row0 + arow) * lda + k0 + acol);
        As[acol + 0][arow] = av.x; As[acol + 1][arow] = av.y;
        As[acol + 2][arow] = av.z; As[acol + 3][arow] = av.w;
        #pragma unroll
        for (int j = 0; j < 4; j++) {
            int c = col0 + bcol + j;
            Bs[brow][bcol + j] = (c < N) ? B[(size_t)(k0 + brow) * ldb + c] : 0.0f;
        }
        __syncthreads();
        #pragma unroll
        for (int kk = 0; kk < 8; kk++) {
            float a[8], bb[8];
            #pragma unroll
            for (int i = 0; i < 8; i++) a[i] = As[kk][ty + 16 * i];
            #pragma unroll
            for (int j = 0; j < 8; j++) bb[j] = Bs[kk][tx + 16 * j];
            #pragma unroll
            for (int i = 0; i < 8; i++)
                #pragma unroll
                for (int j = 0; j < 8; j++) acc[i][j] += a[i] * bb[j];
        }
        __syncthreads();
    }
    #pragma unroll
    for (int i = 0; i < 8; i++) {
        int r = row0 + ty + 16 * i;
        #pragma unroll
        for (int j = 0; j < 8; j++) {
            int c = col0 + tx + 16 * j;
            if (c < N) C[(size_t)r * ldc + c] = acc[i][j] + bias[c];
        }
    }
}

// ---------------- host --------------------------------------------------------
extern "C" void kernel_launch(void* const* d_in, const int* in_sizes, int n_in,
                              void* d_out, int out_size) {
    const float* methy  = (const float*)d_in[0];
    const int*   chromo = (const int*)  d_in[1];
    const int*   pos    = (const int*)  d_in[2];
    const float* mtab   = (const float*)d_in[3];
    const float* ctab   = (const float*)d_in[4];
    const float* ptab   = (const float*)d_in[5];
    const float* ln1g   = (const float*)d_in[6];
    const float* ln1b   = (const float*)d_in[7];
    const float* ln2g   = (const float*)d_in[8];
    const float* ln2b   = (const float*)d_in[9];
    const float* Wq     = (const float*)d_in[10];
    const float* Wk     = (const float*)d_in[11];
    const float* Wv     = (const float*)d_in[12];
    const float* Wo     = (const float*)d_in[13];
    const float* bo     = (const float*)d_in[14];
    const float* W1     = (const float*)d_in[15];
    const float* b1     = (const float*)d_in[16];
    const float* W2     = (const float*)d_in[17];
    const float* b2     = (const float*)d_in[18];
    const float* proj   = (const float*)d_in[19];
    const float* nfg    = (const float*)d_in[20];
    const float* nfb    = (const float*)d_in[21];
    const float* Wout   = (const float*)d_in[22];
    const float* bout   = (const float*)d_in[23];
    float* out = (float*)d_out;

    static int smem_set = 0;
    if (!smem_set) {
        cudaFuncSetAttribute(hm_qkv_k,      cudaFuncAttributeMaxDynamicSharedMemorySize, SMEM_128);
        cudaFuncSetAttribute(hm_xd_k,       cudaFuncAttributeMaxDynamicSharedMemorySize, SMEM_128);
        cudaFuncSetAttribute(hm_o_k,        cudaFuncAttributeMaxDynamicSharedMemorySize, SMEM_64);
        cudaFuncSetAttribute(hm_plain_k<2>, cudaFuncAttributeMaxDynamicSharedMemorySize, SMEM_128);
        cudaFuncSetAttribute(hm_plain_k<3>, cudaFuncAttributeMaxDynamicSharedMemorySize, SMEM_128);
        smem_set = 1;
    }

    float *px, *ph, *pq, *pk, *pv, *pqf, *pkf, *pksum, *pctx, *pdinv;
    unsigned* phmax;
    cudaGetSymbolAddress((void**)&px,    g_x);
    cudaGetSymbolAddress((void**)&ph,    g_h);
    cudaGetSymbolAddress((void**)&pq,    g_q);
    cudaGetSymbolAddress((void**)&pk,    g_k);
    cudaGetSymbolAddress((void**)&pv,    g_v);
    cudaGetSymbolAddress((void**)&pqf,   g_qf);
    cudaGetSymbolAddress((void**)&pkf,   g_kf);
    cudaGetSymbolAddress((void**)&pksum, g_ksum);
    cudaGetSymbolAddress((void**)&pctx,  g_ctx);
    cudaGetSymbolAddress((void**)&pdinv, g_dinv);
    cudaGetSymbolAddress((void**)&phmax, g_hmax);

    __nv_bfloat16 *hh, *hl, *qh, *ql, *kh, *kl, *vh, *vl, *oh, *ol, *ffh, *ffl;
    __nv_bfloat16 *qfh, *qfl, *ctTh, *ctTl, *pch, *pcl;
    __nv_bfloat16 *wqh, *wql, *wkh, *wkl, *wvh, *wvl, *woh, *wol, *w1h, *w1l, *w2h, *w2l;
    cudaGetSymbolAddress((void**)&hh,  g_hh);  cudaGetSymbolAddress((void**)&hl,  g_hl);
    cudaGetSymbolAddress((void**)&qh,  g_qh);  cudaGetSymbolAddress((void**)&ql,  g_ql);
    cudaGetSymbolAddress((void**)&kh,  g_kh);  cudaGetSymbolAddress((void**)&kl,  g_kl);
    cudaGetSymbolAddress((void**)&vh,  g_vh);  cudaGetSymbolAddress((void**)&vl,  g_vl);
    cudaGetSymbolAddress((void**)&oh,  g_oh);  cudaGetSymbolAddress((void**)&ol,  g_ol);
    cudaGetSymbolAddress((void**)&ffh, g_ffh); cudaGetSymbolAddress((void**)&ffl, g_ffl);
    cudaGetSymbolAddress((void**)&qfh, g_qfh); cudaGetSymbolAddress((void**)&qfl, g_qfl);
    cudaGetSymbolAddress((void**)&ctTh, g_ctTh); cudaGetSymbolAddress((void**)&ctTl, g_ctTl);
    cudaGetSymbolAddress((void**)&pch, g_pch); cudaGetSymbolAddress((void**)&pcl, g_pcl);
    cudaGetSymbolAddress((void**)&wqh, g_wqh); cudaGetSymbolAddress((void**)&wql, g_wql);
    cudaGetSymbolAddress((void**)&wkh, g_wkh); cudaGetSymbolAddress((void**)&wkl, g_wkl);
    cudaGetSymbolAddress((void**)&wvh, g_wvh); cudaGetSymbolAddress((void**)&wvl, g_wvl);
    cudaGetSymbolAddress((void**)&woh, g_woh); cudaGetSymbolAddress((void**)&wol, g_wol);
    cudaGetSymbolAddress((void**)&w1h, g_w1h); cudaGetSymbolAddress((void**)&w1l, g_w1l);
    cudaGetSymbolAddress((void**)&w2h, g_w2h); cudaGetSymbolAddress((void**)&w2l, g_w2l);

    dim3 tb(32, 8);
    tconv_kernel<<<dim3(24, 24, 6), tb>>>(Wq, DIM, (size_t)DIM * DIM, wqh, wql, DIM, (size_t)DIM * DIM);
    tconv_kernel<<<dim3(24, 24, 6), tb>>>(Wk, DIM, (size_t)DIM * DIM, wkh, wkl, DIM, (size_t)DIM * DIM);
    tconv_kernel<<<dim3(24, 24, 6), tb>>>(Wv, DIM, (size_t)DIM * DIM, wvh, wvl, DIM, (size_t)DIM * DIM);
    tconv_kernel<<<dim3(24, 24, 6), tb>>>(Wo, DIM, (size_t)DIM * DIM, woh, wol, DIM, (size_t)DIM * DIM);
    tconv_kernel<<<dim3(96, 24, 6), tb>>>(W1, FFD, (size_t)DIM * FFD, w1h, w1l, DIM, (size_t)DIM * FFD);
    tconv_kernel<<<dim3(24, 96, 6), tb>>>(W2, DIM, (size_t)DIM * FFD, w2h, w2l, FFD, (size_t)DIM * FFD);
    projc_kernel<<<DEPTH * MFEAT * DH / 256, 256>>>(proj, pch, pcl);

    embed_kernel<<<NTOK, 256>>>(methy, pos, chromo, mtab, ptab, ctab, px);

    for (int l = 0; l < DEPTH; l++) {
        size_t wo = (size_t)l * DIM * DIM;
        size_t w12 = (size_t)l * DIM * FFD;

        ln_kernel<<<NTOK / 8, 256>>>(px, ln1g + l * DIM, ln1b + l * DIM, ph, hh, hl);
        hm_qkv_k<<<dim3(6, 32, 3), 256, SMEM_128>>>(hh, hl,
            wqh + wo, wql + wo, wkh + wo, wkl + wo, wvh + wo, wvl + wo,
            pq, pk, pv, qh, ql, kh, kl, vh, vl);

        zero_kernel<<<(HEADS * MFEAT * DH + 255) / 256, 256>>>(phmax, pksum, pctx);

        hm_xd_k<<<dim3(2, 32, 24), 256, SMEM_128>>>(qh, ql, kh, kl,
            pch + (size_t)l * MFEAT * DH, pcl + (size_t)l * MFEAT * DH, pqf, pkf, phmax);
        kctx_kernel<<<dim3(32, HEADS), 256>>>(pkf, pk, pv, phmax, methy, pksum, pctx);
        q_post_kernel<<<HEADS * NTOK / 8, 256>>>(pq, pqf, qfh, qfl, pksum, pdinv);
        ctxT_kernel<<<HEADS, 256>>>(pctx, ctTh, ctTl);
        hm_o_k<<<dim3(1, 32, HEADS), 256, SMEM_64>>>(qfh, qfl, ctTh, ctTl, pdinv, oh, ol);

        hm_plain_k<3><<<dim3(6, 32), 256, SMEM_128>>>(oh, ol, DIM, woh + wo, wol + wo, DIM,
            bo + l * DIM, px, px, nullptr, nullptr, DIM, DIM);
        ln_kernel<<<NTOK / 8, 256>>>(px, ln2g + l * DIM, ln2b + l * DIM, ph, hh, hl);
        hm_plain_k<2><<<dim3(24, 32), 256, SMEM_128>>>(hh, hl, DIM, w1h + w12, w1l + w12, DIM,
            b1 + l * FFD, nullptr, nullptr, ffh, ffl, FFD, DIM);
        hm_plain_k<3><<<dim3(6, 32), 256, SMEM_128>>>(ffh, ffl, FFD, w2h + w12, w2l + w12, FFD,
            b2 + l * DIM, px, px, nullptr, nullptr, DIM, FFD);
    }

    ln_kernel<<<NTOK / 8, 256>>>(px, nfg, nfb, ph, hh, hl);
    sgemm_guard_k<<<dim3(1, 32), 256>>>(ph, DIM, Wout, NOUT, bout, out, NOUT, NOUT, DIM);
}

// round 16
// speedup vs baseline: 1.9429x; 1.0102x over previous
#include <cuda_runtime.h>
#include <cuda_bf16.h>
#include <math.h>
#include <stdint.h>

#define NTOK  4096
#define DIM   768
#define DEPTH 6
#define HEADS 12
#define DH    64
#define FFD   3072
#define MFEAT 256
#define NOUT  102

// ---------------- fp32 scratch ----------------------------------------------
__device__ float g_x  [NTOK*DIM];
__device__ float g_h  [NTOK*DIM];
__device__ float g_q  [NTOK*DIM];
__device__ float g_k  [NTOK*DIM];
__device__ float g_qf [HEADS*NTOK*MFEAT];
__device__ float g_kf [HEADS*NTOK*MFEAT];
__device__ unsigned g_hmax[HEADS];
__device__ float g_ksum[HEADS*MFEAT];
__device__ float g_ctx [HEADS*MFEAT*DH];
__device__ float g_dinv[HEADS*NTOK];
__device__ float g_v  [NTOK*DIM];

// ---------------- bf16 hi/lo scratch -----------------------------------------
__device__ __nv_bfloat16 g_hh [NTOK*DIM],  g_hl [NTOK*DIM];
__device__ __nv_bfloat16 g_qh [NTOK*DIM],  g_ql [NTOK*DIM];
__device__ __nv_bfloat16 g_kh [NTOK*DIM],  g_kl [NTOK*DIM];
__device__ __nv_bfloat16 g_vh [NTOK*DIM],  g_vl [NTOK*DIM];
__device__ __nv_bfloat16 g_oh [NTOK*DIM],  g_ol [NTOK*DIM];
__device__ __nv_bfloat16 g_ffh[NTOK*FFD],  g_ffl[NTOK*FFD];
__device__ __nv_bfloat16 g_qfh[HEADS*NTOK*MFEAT], g_qfl[HEADS*NTOK*MFEAT];
__device__ __nv_bfloat16 g_ctTh[HEADS*DH*MFEAT],  g_ctTl[HEADS*DH*MFEAT];
__device__ __nv_bfloat16 g_pch[DEPTH*MFEAT*DH],   g_pcl[DEPTH*MFEAT*DH];
__device__ __nv_bfloat16 g_wqh[DEPTH*DIM*DIM], g_wql[DEPTH*DIM*DIM];
__device__ __nv_bfloat16 g_wkh[DEPTH*DIM*DIM], g_wkl[DEPTH*DIM*DIM];
__device__ __nv_bfloat16 g_wvh[DEPTH*DIM*DIM], g_wvl[DEPTH*DIM*DIM];
__device__ __nv_bfloat16 g_woh[DEPTH*DIM*DIM], g_wol[DEPTH*DIM*DIM];
__device__ __nv_bfloat16 g_w1h[DEPTH*FFD*DIM], g_w1l[DEPTH*FFD*DIM];
__device__ __nv_bfloat16 g_w2h[DEPTH*DIM*FFD], g_w2l[DEPTH*DIM*FFD];

// ---------------- helpers ----------------------------------------------------
__device__ __forceinline__ unsigned f2o(float f) {
    unsigned u = __float_as_uint(f);
    return (u & 0x80000000u) ? ~u : (u | 0x80000000u);
}
__device__ __forceinline__ float o2f(unsigned u) {
    return __uint_as_float((u & 0x80000000u) ? (u & 0x7fffffffu) : ~u);
}
__device__ __forceinline__ float fexp(float x) {
    float t = x * 1.4426950408889634f;
    t = fmaxf(t, -120.0f);
    float fi = floorf(t);
    float f = t - fi;
    float p = 1.52527338e-5f;
    p = p * f + 1.54035304e-4f;
    p = p * f + 1.33335581e-3f;
    p = p * f + 9.61812911e-3f;
    p = p * f + 5.55041087e-2f;
    p = p * f + 2.40226507e-1f;
    p = p * f + 6.93147181e-1f;
    p = p * f + 1.0f;
    int ei = (int)fi;
    return __int_as_float((ei + 127) << 23) * p;
}
__device__ __forceinline__ float frcp(float y) {
    float r = __int_as_float(0x7EF311C3 - __float_as_int(y));
    r = r * (2.0f - y * r);
    r = r * (2.0f - y * r);
    r = r * (2.0f - y * r);
    return r;
}
__device__ __forceinline__ float gelu_tanh(float x) {
    float u = 0.7978845608028654f * (x + 0.044715f * x * x * x);
    float uc = fminf(fmaxf(u, -9.0f), 9.0f);
    float e = fexp(2.0f * uc);
    float th = 1.0f - 2.0f * frcp(e + 1.0f);
    return 0.5f * x * (1.0f + th);
}
__device__ __forceinline__ uint32_t smem_u32(const void* p) {
    uint32_t a;
    asm("{ .reg .u64 t; cvta.to.shared.u64 t, %1; cvt.u32.u64 %0, t; }" : "=r"(a) : "l"(p));
    return a;
}
__device__ __forceinline__ void split_store(float v, __nv_bfloat16* oh,
                                            __nv_bfloat16* ol, size_t i) {
    __nv_bfloat16 h = __float2bfloat16(v);
    oh[i] = h;
    ol[i] = __float2bfloat16(v - __bfloat162float(h));
}
__device__ __forceinline__ void cp16(void* dst_smem, const void* src) {
    uint32_t d = smem_u32(dst_smem);
    asm volatile("cp.async.cg.shared.global [%0], [%1], 16;" :: "r"(d), "l"(src));
}
__device__ __forceinline__ void cp_commit() {
    asm volatile("cp.async.commit_group;" ::: "memory");
}

__device__ __forceinline__ void ldmA(uint32_t f[4], const __nv_bfloat16* base, int lane) {
    const __nv_bfloat16* p = base + (lane & 15) * 40 + ((lane >> 4) << 3);
    uint32_t a = smem_u32(p);
    asm volatile("ldmatrix.sync.aligned.m8n8.x4.shared.b16 {%0,%1,%2,%3}, [%4];"
                 : "=r"(f[0]), "=r"(f[1]), "=r"(f[2]), "=r"(f[3]) : "r"(a));
}
__device__ __forceinline__ void ldmB(uint32_t f0[2], uint32_t f1[2],
                                     const __nv_bfloat16* base, int lane) {
    int r = (lane & 7) + ((lane >> 4) << 3);
    int c = ((lane >> 3) & 1) << 3;
    const __nv_bfloat16* p = base + r * 40 + c;
    uint32_t a = smem_u32(p);
    asm volatile("ldmatrix.sync.aligned.m8n8.x4.shared.b16 {%0,%1,%2,%3}, [%4];"
                 : "=r"(f0[0]), "=r"(f0[1]), "=r"(f1[0]), "=r"(f1[1]) : "r"(a));
}
__device__ __forceinline__ void mma16816(float c[4], const uint32_t a[4], const uint32_t b[2]) {
    asm volatile(
        "mma.sync.aligned.m16n8k16.row.col.f32.bf16.bf16.f32 "
        "{%0,%1,%2,%3}, {%4,%5,%6,%7}, {%8,%9}, {%0,%1,%2,%3};"
        : "+f"(c[0]), "+f"(c[1]), "+f"(c[2]), "+f"(c[3])
        : "r"(a[0]), "r"(a[1]), "r"(a[2]), "r"(a[3]), "r"(b[0]), "r"(b[1]));
}

// ---------------- small SIMT kernels -----------------------------------------
__global__ void embed_kernel(const float* __restrict__ methy, const int* __restrict__ pos,
                             const int* __restrict__ chromo,
                             const float* __restrict__ mtab, const float* __restrict__ ptab,
                             const float* __restrict__ ctab, float* __restrict__ x) {
    int n = blockIdx.x, t = threadIdx.x;
    float mv = methy[n];
    int mi = 0;
    mi += (mv > -2.0f);
    mi += (mv > -1.0f);
    #pragma unroll
    for (int k = 0; k < 100; k++) mi += (mv > (float)k * 0.01f);
    int pi = pos[n], ci = chromo[n];
    #pragma unroll
    for (int i = 0; i < 3; i++) {
        int d = t + i * 256;
        x[(size_t)n * DIM + d] = mtab[(size_t)mi * DIM + d]
                               + ptab[(size_t)pi * DIM + d]
                               + ctab[(size_t)ci * DIM + d];
    }
}

template<bool SF32>
__global__ void ln_kernel(const float* __restrict__ x, const float* __restrict__ g,
                          const float* __restrict__ b, float* __restrict__ out,
                          __nv_bfloat16* __restrict__ oh, __nv_bfloat16* __restrict__ ol) {
    int w = threadIdx.x >> 5, lane = threadIdx.x & 31;
    int n = blockIdx.x * 8 + w;
    const float* xr = x + (size_t)n * DIM;
    float v[24];
    float s = 0.0f;
    #pragma unroll
    for (int j = 0; j < 24; j++) { v[j] = xr[lane + 32 * j]; s += v[j]; }
    #pragma unroll
    for (int off = 16; off; off >>= 1) s += __shfl_xor_sync(0xffffffffu, s, off);
    float mu = s * (1.0f / 768.0f);
    float sq = 0.0f;
    #pragma unroll
    for (int j = 0; j < 24; j++) { float d = v[j] - mu; sq += d * d; }
    #pragma unroll
    for (int off = 16; off; off >>= 1) sq += __shfl_xor_sync(0xffffffffu, sq, off);
    float rstd = rsqrtf(sq * (1.0f / 768.0f) + 1e-5f);
    size_t base = (size_t)n * DIM;
    #pragma unroll
    for (int j = 0; j < 24; j++) {
        int d = lane + 32 * j;
        float r = (v[j] - mu) * rstd * g[d] + b[d];
        if (SF32) out[base + d] = r;
        split_store(r, oh, ol, base + d);
    }
}

__global__ void zero_kernel(unsigned* __restrict__ hmax, float* __restrict__ ksum,
                            float* __restrict__ ctx) {
    int i = blockIdx.x * 256 + threadIdx.x;
    if (i < HEADS) hmax[i] = 0u;
    if (i < HEADS * MFEAT) ksum[i] = 0.0f;
    if (i < HEADS * MFEAT * DH) ctx[i] = 0.0f;
}

// FUSED k-feature + ctx + ksum
__global__ void kctx_kernel(const float* __restrict__ xdk, const float* __restrict__ k,
                            const float* __restrict__ v,
                            const unsigned* __restrict__ hmax,
                            const float* __restrict__ methy,
                            float* __restrict__ ksum, float* __restrict__ ctx) {
    int h = blockIdx.y;
    int n0 = blockIdx.x * 128;
    int t = threadIdx.x;
    __shared__ float sdiag[128];
    __shared__ float smask[128];
    __shared__ float sv[4][64];
    {
        int r = t >> 1, halfsel = t & 1;
        const float* kr = k + (size_t)(n0 + r) * DIM + h * DH + halfsel * 32;
        float s = 0.0f;
        #pragma unroll
        for (int j = 0; j < 32; j++) s += kr[j] * kr[j];
        s += __shfl_xor_sync(0xffffffffu, s, 1);
        if (halfsel == 0) sdiag[r] = s * 0.0625f;
        if (t < 128) smask[t] = (methy[n0 + t] != 0.0f) ? 1.0f : 0.0f;
    }
    __syncthreads();

    float mx = o2f(hmax[h]);
    float4 acc4[16];
    #pragma unroll
    for (int i = 0; i < 16; i++) acc4[i] = make_float4(0.f, 0.f, 0.f, 0.f);
    float kssum = 0.0f;
    int rr = t >> 6, cc = t & 63;

    for (int n = n0; n < n0 + 128; n += 4) {
        sv[rr][cc] = v[(size_t)(n + rr) * DIM + h * DH + cc];
        __syncthreads();
        #pragma unroll
        for (int r = 0; r < 4; r++) {
            int nn = n + r;
            int li = nn - n0;
            float xd = xdk[((size_t)((h << 12) + nn)) * MFEAT + t];
            float kv = smask[li] * 0.0625f * (fexp(xd - sdiag[li] - mx) + 1e-4f);
            kssum += kv;
            const float4* vp = (const float4*)sv[r];
            #pragma unroll
            for (int d4 = 0; d4 < 16; d4++) {
                float4 vv = vp[d4];
                acc4[d4].x += kv * vv.x; acc4[d4].y += kv * vv.y;
                acc4[d4].z += kv * vv.z; acc4[d4].w += kv * vv.w;
            }
        }
        __syncthreads();
    }
    atomicAdd(&ksum[h * MFEAT + t], kssum);
    float* cp = ctx + ((size_t)h * MFEAT + t) * DH;
    #pragma unroll
    for (int d4 = 0; d4 < 16; d4++) {
        atomicAdd(&cp[d4 * 4 + 0], acc4[d4].x);
        atomicAdd(&cp[d4 * 4 + 1], acc4[d4].y);
        atomicAdd(&cp[d4 * 4 + 2], acc4[d4].z);
        atomicAdd(&cp[d4 * 4 + 3], acc4[d4].w);
    }
}

__global__ void q_post_kernel(const float* __restrict__ q, const float* __restrict__ qf,
                              __nv_bfloat16* __restrict__ qh, __nv_bfloat16* __restrict__ ql,
                              const float* __restrict__ ksum, float* __restrict__ dinv) {
    int gw = (blockIdx.x * 256 + threadIdx.x) >> 5;
    int lane = threadIdx.x & 31;
    int h = gw >> 12, n = gw & 4095;
    const float* row = qf + (size_t)gw * MFEAT;
    float v[8];
    float mx = -3e38f;
    #pragma unroll
    for (int i = 0; i < 8; i++) { v[i] = row[lane + 32 * i]; mx = fmaxf(mx, v[i]); }
    #pragma unroll
    for (int off = 16; off; off >>= 1) mx = fmaxf(mx, __shfl_xor_sync(0xffffffffu, mx, off));
    const float* qr = q + (size_t)n * DIM + h * DH;
    float a = qr[lane], b = qr[lane + 32];
    float ss = a * a + b * b;
    #pragma unroll
    for (int off = 16; off; off >>= 1) ss += __shfl_xor_sync(0xffffffffu, ss, off);
    float diag = ss * 0.0625f;
    const float* ks = ksum + h * MFEAT;
    float s = 0.0f;
    #pragma unroll
    for (int i = 0; i < 8; i++) {
        float r = 0.0625f * (fexp(v[i] - diag - mx) + 1e-4f);
        split_store(r, qh, ql, (size_t)gw * MFEAT + lane + 32 * i);
        s += r * ks[lane + 32 * i];
    }
    #pragma unroll
    for (int off = 16; off; off >>= 1) s += __shfl_xor_sync(0xffffffffu, s, off);
    if (lane == 0) dinv[gw] = 1.0f / s;
}

__global__ void ctxT_kernel(const float* __restrict__ ctx,
                            __nv_bfloat16* __restrict__ oh, __nv_bfloat16* __restrict__ ol) {
    int h = blockIdx.x;
    for (int i = threadIdx.x; i < MFEAT * DH; i += 256) {
        int m = i >> 6, d = i & 63;
        float v = ctx[(size_t)h * MFEAT * DH + i];
        split_store(v, oh, ol, ((size_t)h * DH + d) * MFEAT + m);
    }
}

__global__ void tconv_kernel(const float* __restrict__ in, int ldi, size_t inz,
                             __nv_bfloat16* __restrict__ oh, __nv_bfloat16* __restrict__ ol,
                             int ldo, size_t outz) {
    __shared__ float ts[32][33];
    const float* ip = in + (size_t)blockIdx.z * inz;
    int r0 = blockIdx.y * 32, c0 = blockIdx.x * 32;
    int tx = threadIdx.x, ty = threadIdx.y;
    #pragma unroll
    for (int j = 0; j < 4; j++)
        ts[ty + j * 8][tx] = ip[(size_t)(r0 + ty + j * 8) * ldi + c0 + tx];
    __syncthreads();
    size_t ob = (size_t)blockIdx.z * outz;
    #pragma unroll
    for (int j = 0; j < 4; j++)
        split_store(ts[tx][ty + j * 8], oh, ol, ob + (size_t)(c0 + ty + j * 8) * ldo + r0 + tx);
}

__global__ void projc_kernel(const float* __restrict__ in,
                             __nv_bfloat16* __restrict__ oh, __nv_bfloat16* __restrict__ ol) {
    size_t i = (size_t)blockIdx.x * 256 + threadIdx.x;
    split_store(0.35355339059327373f * in[i], oh, ol, i);
}

// ---------------- HMMA GEMM core (mma.sync bf16, 3-term split) ---------------
template<int EPI>
__device__ __forceinline__ void epi2(int r, int c, float v0, float v1,
                                     const float* __restrict__ bias, const float* __restrict__ res,
                                     float* __restrict__ C, __nv_bfloat16* __restrict__ Ch,
                                     __nv_bfloat16* __restrict__ Cl, int ldc,
                                     const float* __restrict__ scale) {
    if (EPI == 2 || EPI == 3) { v0 += bias[c]; v1 += bias[c + 1]; }
    if (EPI == 2) { v0 = gelu_tanh(v0); v1 = gelu_tanh(v1); }
    if (EPI == 3) {
        float2 rr = *(const float2*)(res + (size_t)r * ldc + c);
        v0 += rr.x; v1 += rr.y;
    }
    if (EPI == 6) { float s = scale[r]; v0 *= s; v1 *= s; }
    if (EPI == 0 || EPI == 3 || EPI == 4)
        *(float2*)(C + (size_t)r * ldc + c) = make_float2(v0, v1);
    if (EPI == 2 || EPI == 4 || EPI == 6) {
        __nv_bfloat16 h0 = __float2bfloat16(v0), h1 = __float2bfloat16(v1);
        __nv_bfloat16 l0 = __float2bfloat16(v0 - __bfloat162float(h0));
        __nv_bfloat16 l1 = __float2bfloat16(v1 - __bfloat162float(h1));
        __nv_bfloat162 hh = __halves2bfloat162(h0, h1);
        __nv_bfloat162 ll = __halves2bfloat162(l0, l1);
        *(__nv_bfloat162*)(Ch + (size_t)r * ldc + c) = hh;
        *(__nv_bfloat162*)(Cl + (size_t)r * ldc + c) = ll;
    }
}

template<int EPI, int TN, bool KM>
__device__ void hmma_core(const __nv_bfloat16* __restrict__ Ah, const __nv_bfloat16* __restrict__ Al,
                          int lda,
                          const __nv_bfloat16* __restrict__ Bh, const __nv_bfloat16* __restrict__ Bl,
                          int ldb,
                          const float* __restrict__ bias, const float* __restrict__ res,
                          float* __restrict__ C, __nv_bfloat16* __restrict__ Ch,
                          __nv_bfloat16* __restrict__ Cl, int ldc,
                          const float* __restrict__ scale, unsigned* __restrict__ hmaxp,
                          int K, int row0, int col0)
{
    extern __shared__ __nv_bfloat16 smem[];
    const int AS = 128 * 40;
    const int BS = TN * 40;
    const int STG = 2 * AS + 2 * BS;

    const int MT = (TN == 128) ? 4 : 2;
    int tid = threadIdx.x, w = tid >> 5, lane = tid & 31;
    int wm0, wn0;
    if (TN == 128) { wm0 = (w >> 2) * 64; wn0 = (w & 3) * 32; }
    else           { wm0 = (w >> 1) * 32; wn0 = (w & 1) * 32; }

    float acc[4][4][4];
    #pragma unroll
    for (int i = 0; i < 4; i++)
        #pragma unroll
        for (int j = 0; j < 4; j++)
            #pragma unroll
            for (int e = 0; e < 4; e++) acc[i][j][e] = 0.0f;

    int nch = K >> 5;

    auto prefetch = [&](int c, int s) {
        int k0 = c << 5;
        __nv_bfloat16* sAh = smem + s * STG;
        __nv_bfloat16* sAl = sAh + AS;
        __nv_bfloat16* sBh = sAh + 2 * AS;
        __nv_bfloat16* sBl = sBh + BS;
        for (int i = tid; i < 128 * 4; i += 256) {
            int r = i >> 2, kp = (i & 3) << 3;
            size_t gi = (size_t)(row0 + r) * lda + k0 + kp;
            cp16(sAh + r * 40 + kp, Ah + gi);
            cp16(sAl + r * 40 + kp, Al + gi);
        }
        for (int i = tid; i < TN * 4; i += 256) {
            int r = i >> 2, kp = (i & 3) << 3;
            size_t gi = (size_t)(col0 + r) * ldb + k0 + kp;
            cp16(sBh + r * 40 + kp, Bh + gi);
            cp16(sBl + r * 40 + kp, Bl + gi);
        }
        cp_commit();
    };

    prefetch(0, 0);
    for (int c = 0; c < nch; c++) {
        if (c + 1 < nch) {
            prefetch(c + 1, (c + 1) & 1);
            asm volatile("cp.async.wait_group 1;" ::: "memory");
        } else {
            asm volatile("cp.async.wait_group 0;" ::: "memory");
        }
        __syncthreads();

        __nv_bfloat16* cAh = smem + (c & 1) * STG;
        __nv_bfloat16* cAl = cAh + AS;
        __nv_bfloat16* cBh = cAh + 2 * AS;
        __nv_bfloat16* cBl = cBh + BS;

        #pragma unroll
        for (int kk = 0; kk < 32; kk += 16) {
            uint32_t bh[4][2], bl[4][2];
            ldmB(bh[0], bh[1], cBh + wn0 * 40 + kk, lane);
            ldmB(bh[2], bh[3], cBh + (wn0 + 16) * 40 + kk, lane);
            ldmB(bl[0], bl[1], cBl + wn0 * 40 + kk, lane);
            ldmB(bl[2], bl[3], cBl + (wn0 + 16) * 40 + kk, lane);
            #pragma unroll
            for (int mt = 0; mt < MT; mt++) {
                uint32_t ah[4], al[4];
                ldmA(ah, cAh + (wm0 + mt * 16) * 40 + kk, lane);
                ldmA(al, cAl + (wm0 + mt * 16) * 40 + kk, lane);
                #pragma unroll
                for (int nt = 0; nt < 4; nt++) {
                    mma16816(acc[mt][nt], ah, bh[nt]);
                    mma16816(acc[mt][nt], ah, bl[nt]);
                    mma16816(acc[mt][nt], al, bh[nt]);
                }
            }
        }
        __syncthreads();
    }

    #pragma unroll
    for (int mt = 0; mt < MT; mt++) {
        #pragma unroll
        for (int nt = 0; nt < 4; nt++) {
            int r = row0 + wm0 + mt * 16 + (lane >> 2);
            int cc = col0 + wn0 + nt * 8 + ((lane & 3) << 1);
            epi2<EPI>(r,     cc, acc[mt][nt][0], acc[mt][nt][1], bias, res, C, Ch, Cl, ldc, scale);
            epi2<EPI>(r + 8, cc, acc[mt][nt][2], acc[mt][nt][3], bias, res, C, Ch, Cl, ldc, scale);
        }
    }

    if (KM) {
        float m = -3e38f;
        #pragma unroll
        for (int mt = 0; mt < MT; mt++)
            #pragma unroll
            for (int nt = 0; nt < 4; nt++)
                #pragma unroll
                for (int e = 0; e < 4; e++) m = fmaxf(m, acc[mt][nt][e]);
        #pragma unroll
        for (int off = 16; off; off >>= 1) m = fmaxf(m, __shfl_xor_sync(0xffffffffu, m, off));
        __shared__ float smax[8];
        if (lane == 0) smax[w] = m;
        __syncthreads();
        if (tid == 0) {
            float bm = smax[0];
            #pragma unroll
            for (int i = 1; i < 8; i++) bm = fmaxf(bm, smax[i]);
            atomicMax(hmaxp, f2o(bm));
        }
    }
}

#define SMEM_128 (2 * (2 * 128 * 40 + 2 * 128 * 40) * 2)   // 81920 B
#define SMEM_64  (2 * (2 * 128 * 40 + 2 * 64 * 40) * 2)    // 61440 B

// ---------------- HMMA wrappers ----------------------------------------------
template<int EPI>
__global__ __launch_bounds__(256, 2) void hm_plain_k(
    const __nv_bfloat16* Ah, const __nv_bfloat16* Al, int lda,
    const __nv_bfloat16* Bh, const __nv_bfloat16* Bl, int ldb,
    const float* bias, const float* res,
    float* C, __nv_bfloat16* Ch, __nv_bfloat16* Cl, int ldc, int K)
{
    hmma_core<EPI, 128, false>(Ah, Al, lda, Bh, Bl, ldb, bias, res, C, Ch, Cl, ldc,
                               nullptr, nullptr, K, blockIdx.y * 128, blockIdx.x * 128);
}

__global__ __launch_bounds__(256, 2) void hm_qkv_k(
    const __nv_bfloat16* Ah, const __nv_bfloat16* Al,
    const __nv_bfloat16* Wqh, const __nv_bfloat16* Wql,
    const __nv_bfloat16* Wkh, const __nv_bfloat16* Wkl,
    const __nv_bfloat16* Wvh, const __nv_bfloat16* Wvl,
    float* q, float* k, float* v,
    __nv_bfloat16* qh, __nv_bfloat16* ql, __nv_bfloat16* kh, __nv_bfloat16* kl,
    __nv_bfloat16* vh, __nv_bfloat16* vl)
{
    int z = blockIdx.z;
    const __nv_bfloat16* Bh = (z == 0) ? Wqh : (z == 1) ? Wkh : Wvh;
    const __nv_bfloat16* Bl = (z == 0) ? Wql : (z == 1) ? Wkl : Wvl;
    float* C = (z == 0) ? q : (z == 1) ? k : v;
    __nv_bfloat16* Ch = (z == 0) ? qh : (z == 1) ? kh : vh;
    __nv_bfloat16* Cl = (z == 0) ? ql : (z == 1) ? kl : vl;
    hmma_core<4, 128, false>(Ah, Al, DIM, Bh, Bl, DIM, nullptr, nullptr, C, Ch, Cl, DIM,
                             nullptr, nullptr, DIM, blockIdx.y * 128, blockIdx.x * 128);
}

__global__ __launch_bounds__(256, 2) void hm_xdq_k(
    const __nv_bfloat16* qh, const __nv_bfloat16* ql,
    const __nv_bfloat16* prh, const __nv_bfloat16* prl, float* xq)
{
    int h = blockIdx.z;
    hmma_core<0, 128, false>(qh + h * DH, ql + h * DH, DIM, prh, prl, DH,
                             nullptr, nullptr, xq + (size_t)h * NTOK * MFEAT,
                             nullptr, nullptr, MFEAT, nullptr, nullptr, DH,
                             blockIdx.y * 128, blockIdx.x * 128);
}

__global__ __launch_bounds__(256, 2) void hm_xdk_k(
    const __nv_bfloat16* kh, const __nv_bfloat16* kl,
    const __nv_bfloat16* prh, const __nv_bfloat16* prl, float* xk, unsigned* hmax)
{
    int h = blockIdx.z;
    hmma_core<0, 128, true>(kh + h * DH, kl + h * DH, DIM, prh, prl, DH,
                            nullptr, nullptr, xk + (size_t)h * NTOK * MFEAT,
                            nullptr, nullptr, MFEAT, nullptr, hmax + h, DH,
                            blockIdx.y * 128, blockIdx.x * 128);
}

__global__ __launch_bounds__(256, 2) void hm_o_k(
    const __nv_bfloat16* qfh, const __nv_bfloat16* qfl,
    const __nv_bfloat16* cth, const __nv_bfloat16* ctl,
    const float* dinv, __nv_bfloat16* oh, __nv_bfloat16* ol)
{
    int h = blockIdx.z;
    hmma_core<6, 64, false>(qfh + (size_t)h * NTOK * MFEAT, qfl + (size_t)h * NTOK * MFEAT, MFEAT,
                            cth + (size_t)h * DH * MFEAT, ctl + (size_t)h * DH * MFEAT, MFEAT,
                            nullptr, nullptr, nullptr, oh + h * DH, ol + h * DH, DIM,
                            dinv + (size_t)h * NTOK, nullptr, MFEAT, blockIdx.y * 128, 0);
}

// ---------------- SIMT guard GEMM for tiny Wout -------------------------------
__global__ __launch_bounds__(256)
void sgemm_guard_k(const float* __restrict__ A, int lda, const float* __restrict__ B, int ldb,
                   const float* __restrict__ bias, float* __restrict__ C, int ldc,
                   int N, int K) {
    __shared__ float As[8][128];
    __shared__ float Bs[8][128];
    int tid = threadIdx.x;
    int row0 = blockIdx.y * 128, col0 = blockIdx.x * 128;
    int tx = tid & 15, ty = tid >> 4;
    int arow = tid >> 1, acol = (tid & 1) * 4;
    int brow = tid >> 5, bcol = (tid & 31) * 4;
    float acc[8][8];
    #pragma unroll
    for (int i = 0; i < 8; i++)
        #pragma unroll
        for (int j = 0; j < 8; j++) acc[i][j] = 0.0f;
    for (int k0 = 0; k0 < K; k0 += 8) {
        float4 av = *(const float4*)(A + (size_t)(row0 + arow) * lda + k0 + acol);
        As[acol + 0][arow] = av.x; As[acol + 1][arow] = av.y;
        As[acol + 2][arow] = av.z; As[acol + 3][arow] = av.w;
        #pragma unroll
        for (int j = 0; j < 4; j++) {
            int c = col0 + bcol + j;
            Bs[brow][bcol + j] = (c < N) ? B[(size_t)(k0 + brow) * ldb + c] : 0.0f;
        }
        __syncthreads();
        #pragma unroll
        for (int kk = 0; kk < 8; kk++) {
            float a[8], bb[8];
            #pragma unroll
            for (int i = 0; i < 8; i++) a[i] = As[kk][ty + 16 * i];
            #pragma unroll
            for (int j = 0; j < 8; j++) bb[j] = Bs[kk][tx + 16 * j];
            #pragma unroll
            for (int i = 0; i < 8; i++)
                #pragma unroll
                for (int j = 0; j < 8; j++) acc[i][j] += a[i] * bb[j];
        }
        __syncthreads();
    }
    #pragma unroll
    for (int i = 0; i < 8; i++) {
        int r = row0 + ty + 16 * i;
        #pragma unroll
        for (int j = 0; j < 8; j++) {
            int c = col0 + tx + 16 * j;
            if (c < N) C[(size_t)r * ldc + c] = acc[i][j] + bias[c];
        }
    }
}

// ---------------- host --------------------------------------------------------
extern "C" void kernel_launch(void* const* d_in, const int* in_sizes, int n_in,
                              void* d_out, int out_size) {
    const float* methy  = (const float*)d_in[0];
    const int*   chromo = (const int*)  d_in[1];
    const int*   pos    = (const int*)  d_in[2];
    const float* mtab   = (const float*)d_in[3];
    const float* ctab   = (const float*)d_in[4];
    const float* ptab   = (const float*)d_in[5];
    const float* ln1g   = (const float*)d_in[6];
    const float* ln1b   = (const float*)d_in[7];
    const float* ln2g   = (const float*)d_in[8];
    const float* ln2b   = (const float*)d_in[9];
    const float* Wq     = (const float*)d_in[10];
    const float* Wk     = (const float*)d_in[11];
    const float* Wv     = (const float*)d_in[12];
    const float* Wo     = (const float*)d_in[13];
    const float* bo     = (const float*)d_in[14];
    const float* W1     = (const float*)d_in[15];
    const float* b1     = (const float*)d_in[16];
    const float* W2     = (const float*)d_in[17];
    const float* b2     = (const float*)d_in[18];
    const float* proj   = (const float*)d_in[19];
    const float* nfg    = (const float*)d_in[20];
    const float* nfb    = (const float*)d_in[21];
    const float* Wout   = (const float*)d_in[22];
    const float* bout   = (const float*)d_in[23];
    float* out = (float*)d_out;

    static int inited = 0;
    static cudaStream_t s1;
    static cudaEvent_t e_fork, e_prep, e_ln, e_qkv, e_ksum, e_ctxT;
    if (!inited) {
        cudaFuncSetAttribute(hm_qkv_k,      cudaFuncAttributeMaxDynamicSharedMemorySize, SMEM_128);
        cudaFuncSetAttribute(hm_xdq_k,      cudaFuncAttributeMaxDynamicSharedMemorySize, SMEM_128);
        cudaFuncSetAttribute(hm_xdk_k,      cudaFuncAttributeMaxDynamicSharedMemorySize, SMEM_128);
        cudaFuncSetAttribute(hm_o_k,        cudaFuncAttributeMaxDynamicSharedMemorySize, SMEM_64);
        cudaFuncSetAttribute(hm_plain_k<2>, cudaFuncAttributeMaxDynamicSharedMemorySize, SMEM_128);
        cudaFuncSetAttribute(hm_plain_k<3>, cudaFuncAttributeMaxDynamicSharedMemorySize, SMEM_128);
        cudaStreamCreateWithFlags(&s1, cudaStreamNonBlocking);
        cudaEventCreateWithFlags(&e_fork, cudaEventDisableTiming);
        cudaEventCreateWithFlags(&e_prep, cudaEventDisableTiming);
        cudaEventCreateWithFlags(&e_ln,   cudaEventDisableTiming);
        cudaEventCreateWithFlags(&e_qkv,  cudaEventDisableTiming);
        cudaEventCreateWithFlags(&e_ksum, cudaEventDisableTiming);
        cudaEventCreateWithFlags(&e_ctxT, cudaEventDisableTiming);
        inited = 1;
    }

    float *px, *ph, *pq, *pk, *pv, *pqf, *pkf, *pksum, *pctx, *pdinv;
    unsigned* phmax;
    cudaGetSymbolAddress((void**)&px,    g_x);
    cudaGetSymbolAddress((void**)&ph,    g_h);
    cudaGetSymbolAddress((void**)&pq,    g_q);
    cudaGetSymbolAddress((void**)&pk,    g_k);
    cudaGetSymbolAddress((void**)&pv,    g_v);
    cudaGetSymbolAddress((void**)&pqf,   g_qf);
    cudaGetSymbolAddress((void**)&pkf,   g_kf);
    cudaGetSymbolAddress((void**)&pksum, g_ksum);
    cudaGetSymbolAddress((void**)&pctx,  g_ctx);
    cudaGetSymbolAddress((void**)&pdinv, g_dinv);
    cudaGetSymbolAddress((void**)&phmax, g_hmax);

    __nv_bfloat16 *hh, *hl, *qh, *ql, *kh, *kl, *vh, *vl, *oh, *ol, *ffh, *ffl;
    __nv_bfloat16 *qfh, *qfl, *ctTh, *ctTl, *pch, *pcl;
    __nv_bfloat16 *wqh, *wql, *wkh, *wkl, *wvh, *wvl, *woh, *wol, *w1h, *w1l, *w2h, *w2l;
    cudaGetSymbolAddress((void**)&hh,  g_hh);  cudaGetSymbolAddress((void**)&hl,  g_hl);
    cudaGetSymbolAddress((void**)&qh,  g_qh);  cudaGetSymbolAddress((void**)&ql,  g_ql);
    cudaGetSymbolAddress((void**)&kh,  g_kh);  cudaGetSymbolAddress((void**)&kl,  g_kl);
    cudaGetSymbolAddress((void**)&vh,  g_vh);  cudaGetSymbolAddress((void**)&vl,  g_vl);
    cudaGetSymbolAddress((void**)&oh,  g_oh);  cudaGetSymbolAddress((void**)&ol,  g_ol);
    cudaGetSymbolAddress((void**)&ffh, g_ffh); cudaGetSymbolAddress((void**)&ffl, g_ffl);
    cudaGetSymbolAddress((void**)&qfh, g_qfh); cudaGetSymbolAddress((void**)&qfl, g_qfl);
    cudaGetSymbolAddress((void**)&ctTh, g_ctTh); cudaGetSymbolAddress((void**)&ctTl, g_ctTl);
    cudaGetSymbolAddress((void**)&pch, g_pch); cudaGetSymbolAddress((void**)&pcl, g_pcl);
    cudaGetSymbolAddress((void**)&wqh, g_wqh); cudaGetSymbolAddress((void**)&wql, g_wql);
    cudaGetSymbolAddress((void**)&wkh, g_wkh); cudaGetSymbolAddress((void**)&wkl, g_wkl);
    cudaGetSymbolAddress((void**)&wvh, g_wvh); cudaGetSymbolAddress((void**)&wvl, g_wvl);
    cudaGetSymbolAddress((void**)&woh, g_woh); cudaGetSymbolAddress((void**)&wol, g_wol);
    cudaGetSymbolAddress((void**)&w1h, g_w1h); cudaGetSymbolAddress((void**)&w1l, g_w1l);
    cudaGetSymbolAddress((void**)&w2h, g_w2h); cudaGetSymbolAddress((void**)&w2l, g_w2l);

    // fork s1 from capture-origin stream; do weight prep there while embed runs on s0
    cudaEventRecord(e_fork, 0);
    cudaStreamWaitEvent(s1, e_fork, 0);
    dim3 tb(32, 8);
    tconv_kernel<<<dim3(24, 24, 6), tb, 0, s1>>>(Wq, DIM, (size_t)DIM * DIM, wqh, wql, DIM, (size_t)DIM * DIM);
    tconv_kernel<<<dim3(24, 24, 6), tb, 0, s1>>>(Wk, DIM, (size_t)DIM * DIM, wkh, wkl, DIM, (size_t)DIM * DIM);
    tconv_kernel<<<dim3(24, 24, 6), tb, 0, s1>>>(Wv, DIM, (size_t)DIM * DIM, wvh, wvl, DIM, (size_t)DIM * DIM);
    tconv_kernel<<<dim3(24, 24, 6), tb, 0, s1>>>(Wo, DIM, (size_t)DIM * DIM, woh, wol, DIM, (size_t)DIM * DIM);
    tconv_kernel<<<dim3(96, 24, 6), tb, 0, s1>>>(W1, FFD, (size_t)DIM * FFD, w1h, w1l, DIM, (size_t)DIM * FFD);
    tconv_kernel<<<dim3(24, 96, 6), tb, 0, s1>>>(W2, DIM, (size_t)DIM * FFD, w2h, w2l, FFD, (size_t)DIM * FFD);
    projc_kernel<<<DEPTH * MFEAT * DH / 256, 256, 0, s1>>>(proj, pch, pcl);
    cudaEventRecord(e_prep, s1);

    embed_kernel<<<NTOK, 256>>>(methy, pos, chromo, mtab, ptab, ctab, px);
    cudaStreamWaitEvent(0, e_prep, 0);   // weights ready before first qkv

    for (int l = 0; l < DEPTH; l++) {
        size_t wo = (size_t)l * DIM * DIM;
        size_t w12 = (size_t)l * DIM * FFD;

        ln_kernel<false><<<NTOK / 8, 256>>>(px, ln1g + l * DIM, ln1b + l * DIM, nullptr, hh, hl);
        cudaEventRecord(e_ln, 0);
        cudaStreamWaitEvent(s1, e_ln, 0);          // prev-layer s0 consumers of ksum/ctx done
        zero_kernel<<<(HEADS * MFEAT * DH + 255) / 256, 256, 0, s1>>>(phmax, pksum, pctx);

        hm_qkv_k<<<dim3(6, 32, 3), 256, SMEM_128>>>(hh, hl,
            wqh + wo, wql + wo, wkh + wo, wkl + wo, wvh + wo, wvl + wo,
            pq, pk, pv, qh, ql, kh, kl, vh, vl);
        cudaEventRecord(e_qkv, 0);

        // k-chain on s1
        cudaStreamWaitEvent(s1, e_qkv, 0);
        hm_xdk_k<<<dim3(2, 32, HEADS), 256, SMEM_128, s1>>>(kh, kl,
            pch + (size_t)l * MFEAT * DH, pcl + (size_t)l * MFEAT * DH, pkf, phmax);
        kctx_kernel<<<dim3(32, HEADS), 256, 0, s1>>>(pkf, pk, pv, phmax, methy, pksum, pctx);
        cudaEventRecord(e_ksum, s1);
        ctxT_kernel<<<HEADS, 256, 0, s1>>>(pctx, ctTh, ctTl);
        cudaEventRecord(e_ctxT, s1);

        // q-chain on s0 (overlapped)
        hm_xdq_k<<<dim3(2, 32, HEADS), 256, SMEM_128>>>(qh, ql,
            pch + (size_t)l * MFEAT * DH, pcl + (size_t)l * MFEAT * DH, pqf);
        cudaStreamWaitEvent(0, e_ksum, 0);
        q_post_kernel<<<HEADS * NTOK / 8, 256>>>(pq, pqf, qfh, qfl, pksum, pdinv);
        cudaStreamWaitEvent(0, e_ctxT, 0);
        hm_o_k<<<dim3(1, 32, HEADS), 256, SMEM_64>>>(qfh, qfl, ctTh, ctTl, pdinv, oh, ol);

        hm_plain_k<3><<<dim3(6, 32), 256, SMEM_128>>>(oh, ol, DIM, woh + wo, wol + wo, DIM,
            bo + l * DIM, px, px, nullptr, nullptr, DIM, DIM);
        ln_kernel<false><<<NTOK / 8, 256>>>(px, ln2g + l * DIM, ln2b + l * DIM, nullptr, hh, hl);
        hm_plain_k<2><<<dim3(24, 32), 256, SMEM_128>>>(hh, hl, DIM, w1h + w12, w1l + w12, DIM,
            b1 + l * FFD, nullptr, nullptr, ffh, ffl, FFD, DIM);
        hm_plain_k<3><<<dim3(6, 32), 256, SMEM_128>>>(ffh, ffl, FFD, w2h + w12, w2l + w12, FFD,
            b2 + l * DIM, px, px, nullptr, nullptr, DIM, FFD);
    }

    ln_kernel<true><<<NTOK / 8, 256>>>(px, nfg, nfb, ph, hh, hl);
    sgemm_guard_k<<<dim3(1, 32), 256>>>(ph, DIM, Wout, NOUT, bout, out, NOUT, NOUT, DIM);
}